// round 9
// baseline (speedup 1.0000x reference)
#include <cuda_runtime.h>
#include <math.h>
#include <stdint.h>

// ---------------- static problem config ----------------
#define BB 32
#define TT 12
#define NNODE 500
#define NSKIPC 256
#define NENDC 512
#define NPREDC 12
#define LL 8
#define RFh 13
#define BN_EPS 1e-5f

typedef unsigned long long ull;
typedef unsigned int u32;

__device__ __forceinline__ ull pack2(float lo, float hi) {
    ull r; asm("mov.b64 %0,{%1,%2};" : "=l"(r) : "f"(lo), "f"(hi)); return r;
}
__device__ __forceinline__ ull fma2(ull a, ull b, ull c) {
    ull d; asm("fma.rn.f32x2 %0,%1,%2,%3;" : "=l"(d) : "l"(a), "l"(b), "l"(c)); return d;
}
__device__ __forceinline__ void unpack2(ull v, float& lo, float& hi) {
    asm("mov.b64 {%0,%1},%2;" : "=f"(lo), "=f"(hi) : "l"(v));
}
__device__ __forceinline__ float to_tf32(float x) {
    u32 r; asm("cvt.rna.tf32.f32 %0, %1;" : "=r"(r) : "f"(x));
    return __uint_as_float(r);
}
__device__ __forceinline__ void mma_tf32(float* c, const u32* a, const u32* b) {
    asm("mma.sync.aligned.m16n8k8.row.col.f32.tf32.tf32.f32 "
        "{%0,%1,%2,%3},{%4,%5,%6,%7},{%8,%9},{%0,%1,%2,%3};"
        : "+f"(c[0]), "+f"(c[1]), "+f"(c[2]), "+f"(c[3])
        : "r"(a[0]), "r"(a[1]), "r"(a[2]), "r"(a[3]), "r"(b[0]), "r"(b[1]));
}

// ---------------- device scratch ----------------
__device__ float g_P[NNODE * 64];
__device__ float g_Q[NNODE * 64];
__device__ float g_eraw[2 * NNODE * NNODE];
__device__ float g_Scat[NNODE * 2000];            // [v][ A0 | A0^2 | A1 | A1^2 ]
__device__ float g_tmp[BB * TT * 32 * 2];
__device__ float g_X0[BB * 32 * RFh * NNODE];
__device__ float g_X1[BB * 32 * RFh * NNODE];
__device__ float g_XG[BB * 32 * 12 * NNODE];
__device__ float g_Y[12288 * 2000];               // diffusion outputs; reused as head hidden H
__device__ float g_XGcat[BB * 256 * NNODE];       // last-t gated slices, rows (l*32+c)
__device__ float g_Wcat[256 * 256];               // skip weights re-laid [o][l*32+c]
__device__ float g_skip[BB * NSKIPC * NNODE];
__device__ float g_Srelu[BB * NNODE * NSKIPC];
__device__ float g_o1wT[NSKIPC * NENDC];
__device__ float g_part[1536 * 64];               // per-block BN partial sums
__device__ float g_bnab[(LL + 1) * 64];           // per-layer fused BN scale/shift; slot LL = identity

// ---------------- fused one-time prep ----------------
__global__ void k_prep(const float* __restrict__ skp_w, const float* __restrict__ o1w) {
    int idx = blockIdx.x * 256 + threadIdx.x;
    if (idx < 64) g_bnab[LL * 64 + idx] = (idx < 32) ? 1.f : 0.f;
    if (idx < 65536) {
        int o = idx >> 8, r = idx & 255, l = r >> 5, c = r & 31;
        g_Wcat[idx] = skp_w[l * 8192 + o * 32 + c];
    }
    if (idx < 131072) {
        int h = idx / NSKIPC, c = idx % NSKIPC;
        g_o1wT[c * NENDC + h] = o1w[idx];
    }
}

// ---------------- adjacency ----------------
__global__ void k_pq(const float* __restrict__ factor, const float* __restrict__ map_w,
                     const float* __restrict__ map_b,
                     const float* __restrict__ a1w, const float* __restrict__ a1b) {
    __shared__ float vv[32];
    int j = blockIdx.x, h = threadIdx.x;   // 64 threads
    if (h < 32) {
        float acc = map_b[h];
#pragma unroll
        for (int u = 0; u < 32; u++) acc += factor[j * 32 + u] * map_w[u * 32 + h];
        vv[h] = fmaxf(acc, 0.f);
    }
    __syncthreads();
    float p = 0.f, q = a1b[h];
#pragma unroll
    for (int d = 0; d < 32; d++) {
        p += vv[d] * a1w[d * 64 + h];
        q += vv[d] * a1w[(32 + d) * 64 + h];
    }
    g_P[j * 64 + h] = p;
    g_Q[j * 64 + h] = q;
}

__global__ void k_adjmlp(const float* __restrict__ a2w, const float* __restrict__ a2b,
                         const float* __restrict__ a3w, const float* __restrict__ a3b) {
    __shared__ float Pt[128][65];
    __shared__ __align__(16) float sA2[64][32];
    __shared__ float sQ[64];
    __shared__ float sA3[64];
    __shared__ float sA2b[32];
    __shared__ float sA3b[2];
    int i = blockIdx.x, tid = threadIdx.x;
    for (int k = tid; k < 64 * 32; k += 128) sA2[k / 32][k % 32] = a2w[k];
    if (tid < 64) { sQ[tid] = g_Q[i * 64 + tid]; sA3[tid] = a3w[tid]; }
    if (tid < 32) sA2b[tid] = a2b[tid];
    if (tid < 2) sA3b[tid] = a3b[tid];
    for (int j0 = 0; j0 < NNODE; j0 += 128) {
        __syncthreads();
        int cnt = min(128, NNODE - j0);
        for (int k = tid; k < cnt * 64; k += 128)
            Pt[k / 64][k % 64] = g_P[(j0 + (k / 64)) * 64 + (k % 64)];
        __syncthreads();
        if (tid < cnt) {
            int j = j0 + tid;
            float h1[64];
#pragma unroll
            for (int h = 0; h < 64; h++) h1[h] = fmaxf(Pt[tid][h] + sQ[h], 0.f);
            float e0 = sA3b[0], e1 = sA3b[1];
#pragma unroll
            for (int c = 0; c < 32; c++) {
                float acc = sA2b[c];
#pragma unroll
                for (int h = 0; h < 64; h++) acc += h1[h] * sA2[h][c];
                acc = fmaxf(acc, 0.f);
                e0 += acc * sA3[c * 2];
                e1 += acc * sA3[c * 2 + 1];
            }
            g_eraw[i * NNODE + j] = e0;
            g_eraw[NNODE * NNODE + i * NNODE + j] = e1;
        }
    }
}

__global__ void k_softmax(float* __restrict__ outSup, int writeSup) {
    int bid = blockIdx.x;
    int e = bid / NNODE, i = bid % NNODE;
    const float* row = g_eraw + e * NNODE * NNODE + i * NNODE;
    __shared__ float red[256];
    int tid = threadIdx.x;
    float m = -1e30f;
    for (int j = tid; j < NNODE; j += 256) m = fmaxf(m, row[j]);
    red[tid] = m; __syncthreads();
    for (int s = 128; s > 0; s >>= 1) { if (tid < s) red[tid] = fmaxf(red[tid], red[tid + s]); __syncthreads(); }
    m = red[0]; __syncthreads();
    float sum = 0.f;
    for (int j = tid; j < NNODE; j += 256) sum += expf(row[j] - m);
    red[tid] = sum; __syncthreads();
    for (int s = 128; s > 0; s >>= 1) { if (tid < s) red[tid] += red[tid + s]; __syncthreads(); }
    float inv = 1.f / red[0];
    for (int j = tid; j < NNODE; j += 256) {
        float p = expf(row[j] - m) * inv;
        if (j == i) p = fmaxf(p, 1.f);
        g_Scat[i * 2000 + e * 1000 + j] = p;
        if (writeSup) outSup[(e * NNODE + i) * NNODE + j] = p;
    }
}

// ---------------- tf32 tensor GEMM v2: paired SMEM layouts (LDS.64 frags), 1 sync/kt ----------------
__global__ __launch_bounds__(256)
void tgemm(const float* __restrict__ A, const float* __restrict__ B, float* __restrict__ C,
           int M, int N, int K, int lda, int ldb, int ldc,
           int sA, int sB, int sC) {
    __shared__ __align__(16) float As[2][16][136];   // [buf][k][pcol(m)]
    __shared__ __align__(16) float Bs[2][128][18];   // [buf][n][pk(k)]
    A += (size_t)blockIdx.z * sA;
    B += (size_t)blockIdx.z * sB;
    C += (size_t)blockIdx.z * sC;
    int tid = threadIdx.x;
    int m0 = blockIdx.y * 128, n0 = blockIdx.x * 128;
    int lane = tid & 31, wid = tid >> 5;
    int wm = wid & 1, wn = wid >> 1;
    int gid = lane >> 2, tig = lane & 3;
    // loader indices
    int lm = tid >> 1, lrh = tid & 1;
    int pcolA = (lm & ~15) + ((lm & 7) << 1) + ((lm >> 3) & 1);
    int lkl = tid >> 4, lnq = (tid & 15) << 3;
    int pkB = (lkl & 8) + ((lkl & 3) << 1) + ((lkl >> 2) & 1);

    float acc[4][4][4];
#pragma unroll
    for (int mi = 0; mi < 4; mi++)
#pragma unroll
        for (int ni = 0; ni < 4; ni++)
#pragma unroll
            for (int r = 0; r < 4; r++) acc[mi][ni][r] = 0.f;

    int nkt = (K + 15) / 16;

    // ---- prologue: stage chunk 0 into buf 0 ----
    {
        float av[8], bv[8];
        int row = m0 + lm, c0 = lrh * 8;
        if (row < M && c0 + 7 < K) {
            float4 p = *(const float4*)(A + (size_t)row * lda + c0);
            float4 q = *(const float4*)(A + (size_t)row * lda + c0 + 4);
            av[0]=p.x; av[1]=p.y; av[2]=p.z; av[3]=p.w; av[4]=q.x; av[5]=q.y; av[6]=q.z; av[7]=q.w;
        } else {
#pragma unroll
            for (int l = 0; l < 8; l++)
                av[l] = (row < M && c0 + l < K) ? A[(size_t)row * lda + c0 + l] : 0.f;
        }
        int br = lkl, bc = n0 + lnq;
        if (br < K && bc + 7 < N) {
            float4 p = *(const float4*)(B + (size_t)br * ldb + bc);
            float4 q = *(const float4*)(B + (size_t)br * ldb + bc + 4);
            bv[0]=p.x; bv[1]=p.y; bv[2]=p.z; bv[3]=p.w; bv[4]=q.x; bv[5]=q.y; bv[6]=q.z; bv[7]=q.w;
        } else {
#pragma unroll
            for (int l = 0; l < 8; l++)
                bv[l] = (br < K && bc + l < N) ? B[(size_t)br * ldb + bc + l] : 0.f;
        }
#pragma unroll
        for (int l = 0; l < 8; l++) As[0][lrh * 8 + l][pcolA] = to_tf32(av[l]);
#pragma unroll
        for (int l = 0; l < 8; l++) Bs[0][lnq + l][pkB] = to_tf32(bv[l]);
    }
    __syncthreads();

    for (int kt = 0; kt < nkt; kt++) {
        int cur = kt & 1;
        bool hn = (kt + 1 < nkt);
        float av[8], bv[8];
        if (hn) {
            int kc0 = (kt + 1) * 16;
            int row = m0 + lm, c0 = kc0 + lrh * 8;
            if (row < M && c0 + 7 < K) {
                float4 p = *(const float4*)(A + (size_t)row * lda + c0);
                float4 q = *(const float4*)(A + (size_t)row * lda + c0 + 4);
                av[0]=p.x; av[1]=p.y; av[2]=p.z; av[3]=p.w; av[4]=q.x; av[5]=q.y; av[6]=q.z; av[7]=q.w;
            } else {
#pragma unroll
                for (int l = 0; l < 8; l++)
                    av[l] = (row < M && c0 + l < K) ? A[(size_t)row * lda + c0 + l] : 0.f;
            }
            int br = kc0 + lkl, bc = n0 + lnq;
            if (br < K && bc + 7 < N) {
                float4 p = *(const float4*)(B + (size_t)br * ldb + bc);
                float4 q = *(const float4*)(B + (size_t)br * ldb + bc + 4);
                bv[0]=p.x; bv[1]=p.y; bv[2]=p.z; bv[3]=p.w; bv[4]=q.x; bv[5]=q.y; bv[6]=q.z; bv[7]=q.w;
            } else {
#pragma unroll
                for (int l = 0; l < 8; l++)
                    bv[l] = (br < K && bc + l < N) ? B[(size_t)br * ldb + bc + l] : 0.f;
            }
        }
        // compute on cur: per ks-half, 12 LDS.64 + 16 mma
#pragma unroll
        for (int ks = 0; ks < 16; ks += 8) {
            ull a01[4], a23[4], b01[4];
            const float* Ak0 = &As[cur][ks + tig][wm * 64 + (gid << 1)];
            const float* Ak1 = &As[cur][ks + tig + 4][wm * 64 + (gid << 1)];
#pragma unroll
            for (int mi = 0; mi < 4; mi++) {
                a01[mi] = *(const ull*)(Ak0 + mi * 16);
                a23[mi] = *(const ull*)(Ak1 + mi * 16);
            }
#pragma unroll
            for (int ni = 0; ni < 4; ni++)
                b01[ni] = *(const ull*)&Bs[cur][wn * 32 + ni * 8 + gid][ks + (tig << 1)];
#pragma unroll
            for (int mi = 0; mi < 4; mi++) {
                u32 af[4] = {(u32)a01[mi], (u32)(a01[mi] >> 32),
                             (u32)a23[mi], (u32)(a23[mi] >> 32)};
#pragma unroll
                for (int ni = 0; ni < 4; ni++) {
                    u32 bf[2] = {(u32)b01[ni], (u32)(b01[ni] >> 32)};
                    mma_tf32(acc[mi][ni], af, bf);
                }
            }
        }
        if (hn) {
            int nxt = cur ^ 1;
#pragma unroll
            for (int l = 0; l < 8; l++) As[nxt][lrh * 8 + l][pcolA] = to_tf32(av[l]);
#pragma unroll
            for (int l = 0; l < 8; l++) Bs[nxt][lnq + l][pkB] = to_tf32(bv[l]);
            __syncthreads();
        }
    }
#pragma unroll
    for (int mi = 0; mi < 4; mi++) {
        int r0 = m0 + wm * 64 + mi * 16 + gid;
        int r1 = r0 + 8;
#pragma unroll
        for (int ni = 0; ni < 4; ni++) {
            int cc = n0 + wn * 32 + ni * 8 + tig * 2;
            if (r0 < M) {
                if (cc + 1 < N) *(float2*)(C + (size_t)r0 * ldc + cc) = make_float2(acc[mi][ni][0], acc[mi][ni][1]);
                else if (cc < N) C[(size_t)r0 * ldc + cc] = acc[mi][ni][0];
            }
            if (r1 < M) {
                if (cc + 1 < N) *(float2*)(C + (size_t)r1 * ldc + cc) = make_float2(acc[mi][ni][2], acc[mi][ni][3]);
                else if (cc < N) C[(size_t)r1 * ldc + cc] = acc[mi][ni][2];
            }
        }
    }
}

// ---------------- input split + enter ----------------
__global__ void k_tmp(const float* __restrict__ inputs, const float* __restrict__ factor) {
    int t = blockIdx.x, b = blockIdx.y, tid = threadIdx.x;
    int o = tid >> 2, r = tid & 3;
    int u = o >> 1, f = o & 1;
    const float* inp = inputs + ((size_t)(b * TT + t) * NNODE) * 2 + f;
    float acc = 0.f;
    for (int n = r; n < NNODE; n += 4) acc += inp[n * 2] * factor[n * 32 + u];
    acc += __shfl_down_sync(0xffffffffu, acc, 2);
    acc += __shfl_down_sync(0xffffffffu, acc, 1);
    if (r == 0) g_tmp[(b * TT + t) * 64 + o] = acc;
}

__global__ void k_enter(const float* __restrict__ inputs, const float* __restrict__ factor,
                        const float* __restrict__ ew, const float* __restrict__ eb,
                        float* __restrict__ X0) {
    __shared__ float sw[128], sb[32], stmp[64];
    int b = blockIdx.z, tp = blockIdx.y;
    int tid = threadIdx.x;
    if (tid < 128) sw[tid] = ew[tid];
    if (tid < 32) sb[tid] = eb[tid];
    if (tp > 0 && tid < 64) stmp[tid] = g_tmp[(b * TT + (tp - 1)) * 64 + tid];
    __syncthreads();
    int n = blockIdx.x * 128 + tid;
    if (n >= NNODE) return;
    if (tp == 0) {
#pragma unroll
        for (int o = 0; o < 32; o++)
            X0[((size_t)(b * 32 + o) * RFh + 0) * NNODE + n] = sb[o];
    } else {
        int t = tp - 1;
        float s0 = 0.f, s1 = 0.f;
#pragma unroll
        for (int u = 0; u < 32; u++) {
            float fv = factor[n * 32 + u];
            s0 += fv * stmp[u * 2];
            s1 += fv * stmp[u * 2 + 1];
        }
        float i0 = inputs[((size_t)(b * TT + t) * NNODE + n) * 2 + 0];
        float i1 = inputs[((size_t)(b * TT + t) * NNODE + n) * 2 + 1];
        float r0 = i0 - s0, r1 = i1 - s1;
#pragma unroll
        for (int o = 0; o < 32; o++) {
            float v = sb[o] + sw[o * 4] * s0 + sw[o * 4 + 1] * s1 + sw[o * 4 + 2] * r0 + sw[o * 4 + 3] * r1;
            X0[((size_t)(b * 32 + o) * RFh + tp) * NNODE + n] = v;
        }
    }
}

// ---------------- gated dilated temporal conv; BN affine fused on input ----------------
__global__ void k_gatefilter(const float* __restrict__ X, float* __restrict__ XG,
                             float* __restrict__ XGcat,
                             const float* __restrict__ fw, const float* __restrict__ fb,
                             const float* __restrict__ gw, const float* __restrict__ gb,
                             const float* __restrict__ abPrev,
                             int Tin, int Tout, int dd, int layer) {
    __shared__ __align__(16) float swf[2048];
    __shared__ __align__(16) float swg[2048];
    __shared__ float sfb[32], sgb[32], sA[32], sB[32];
    int tid = threadIdx.x;
    for (int idx = tid; idx < 2048; idx += 128) {
        int c = idx >> 6, r = idx & 63, kk = r >> 5, o = r & 31;
        swf[idx] = fw[(o << 6) + (c << 1) + kk];
        swg[idx] = gw[(o << 6) + (c << 1) + kk];
    }
    if (tid < 32) {
        sfb[tid] = fb[tid]; sgb[tid] = gb[tid];
        sA[tid] = abPrev[tid]; sB[tid] = abPrev[32 + tid];
    }
    __syncthreads();
    int n = blockIdx.x * 128 + tid;
    if (n >= NNODE) return;
    int t = blockIdx.y, b = blockIdx.z;
    ull fa2[16], ga2[16];
#pragma unroll
    for (int p = 0; p < 16; p++) {
        fa2[p] = pack2(sfb[p * 2], sfb[p * 2 + 1]);
        ga2[p] = pack2(sgb[p * 2], sgb[p * 2 + 1]);
    }
    const float* Xb = X + (size_t)(b * 32) * Tin * NNODE + n;
    for (int c = 0; c < 32; c++) {
        float xa = Xb[(size_t)(c * Tin + t) * NNODE] * sA[c] + sB[c];
        float xb = Xb[(size_t)(c * Tin + t + dd) * NNODE] * sA[c] + sB[c];
        ull xad = pack2(xa, xa), xbd = pack2(xb, xb);
        const ulonglong2* wf0 = (const ulonglong2*)&swf[c * 64];
        const ulonglong2* wf1 = (const ulonglong2*)&swf[c * 64 + 32];
        const ulonglong2* wg0 = (const ulonglong2*)&swg[c * 64];
        const ulonglong2* wg1 = (const ulonglong2*)&swg[c * 64 + 32];
#pragma unroll
        for (int p = 0; p < 8; p++) {
            ulonglong2 wa = wf0[p];
            fa2[p * 2 + 0] = fma2(xad, wa.x, fa2[p * 2 + 0]);
            fa2[p * 2 + 1] = fma2(xad, wa.y, fa2[p * 2 + 1]);
            ulonglong2 wb = wf1[p];
            fa2[p * 2 + 0] = fma2(xbd, wb.x, fa2[p * 2 + 0]);
            fa2[p * 2 + 1] = fma2(xbd, wb.y, fa2[p * 2 + 1]);
            ulonglong2 wc = wg0[p];
            ga2[p * 2 + 0] = fma2(xad, wc.x, ga2[p * 2 + 0]);
            ga2[p * 2 + 1] = fma2(xad, wc.y, ga2[p * 2 + 1]);
            ulonglong2 wd = wg1[p];
            ga2[p * 2 + 0] = fma2(xbd, wd.x, ga2[p * 2 + 0]);
            ga2[p * 2 + 1] = fma2(xbd, wd.y, ga2[p * 2 + 1]);
        }
    }
    bool last = (t == Tout - 1);
#pragma unroll
    for (int p = 0; p < 16; p++) {
        float f0, f1, g0, g1;
        unpack2(fa2[p], f0, f1);
        unpack2(ga2[p], g0, g1);
        float s0 = 1.f / (1.f + expf(-g0));
        float s1 = 1.f / (1.f + expf(-g1));
        float v0 = tanhf(f0) * s0, v1 = tanhf(f1) * s1;
        XG[((size_t)(b * 32 + p * 2 + 0) * Tout + t) * NNODE + n] = v0;
        XG[((size_t)(b * 32 + p * 2 + 1) * Tout + t) * NNODE + n] = v1;
        if (last) {
            XGcat[((size_t)b * 256 + layer * 32 + p * 2 + 0) * NNODE + n] = v0;
            XGcat[((size_t)b * 256 + layer * 32 + p * 2 + 1) * NNODE + n] = v1;
        }
    }
}

// ---------------- gc 1x1 + residual(BN-fused) + BN partial stats; adjacent node pairs ----------------
__global__ void k_gcres(const float* __restrict__ XG, const float* __restrict__ Y,
                        const float* __restrict__ Xc, float* __restrict__ Xn,
                        const float* __restrict__ gcw, const float* __restrict__ gcb,
                        const float* __restrict__ abPrev,
                        float* __restrict__ part, int Tin, int Tout, int dd) {
    __shared__ __align__(16) float swg[160 * 32];
    __shared__ float sgb[32], sA[32], sB[32];
    __shared__ float sredS[4][32];
    __shared__ float sredQ[4][32];
    int tid = threadIdx.x;
    for (int idx = tid; idx < 160 * 32; idx += 128) {
        int c = idx / 32, o = idx % 32;
        swg[idx] = gcw[o * 160 + c];
    }
    if (tid < 32) { sgb[tid] = gcb[tid]; sA[tid] = abPrev[tid]; sB[tid] = abPrev[32 + tid]; }
    __syncthreads();
    int n0 = blockIdx.x * 256 + tid * 2;      // adjacent pair (n0, n0+1); NNODE even
    int t = blockIdx.y, b = blockIdx.z;
    bool active = (n0 < NNODE);
    ull acc0[16], acc1[16];
#pragma unroll
    for (int q = 0; q < 16; q++) {
        ull bias = active ? pack2(sgb[q * 2], sgb[q * 2 + 1]) : pack2(0.f, 0.f);
        acc0[q] = bias;
        acc1[q] = bias;
    }
    for (int c = 0; c < 32; c++) {
        size_t base = ((size_t)(b * 32 + c) * Tout + t) * NNODE;
        float2 v = active ? *(const float2*)&XG[base + n0] : make_float2(0.f, 0.f);
        ull vd0 = pack2(v.x, v.x), vd1 = pack2(v.y, v.y);
        const ulonglong2* w2 = (const ulonglong2*)&swg[c * 32];
#pragma unroll
        for (int q = 0; q < 8; q++) {
            ulonglong2 w = w2[q];
            acc0[q * 2 + 0] = fma2(vd0, w.x, acc0[q * 2 + 0]);
            acc0[q * 2 + 1] = fma2(vd0, w.y, acc0[q * 2 + 1]);
            acc1[q * 2 + 0] = fma2(vd1, w.x, acc1[q * 2 + 0]);
            acc1[q * 2 + 1] = fma2(vd1, w.y, acc1[q * 2 + 1]);
        }
    }
    for (int e = 0; e < 4; e++) {
        for (int c = 0; c < 32; c++) {
            size_t m = ((size_t)(b * 32 + c) * Tout + t) * 2000 + e * 500;
            float2 v = active ? *(const float2*)&Y[m + n0] : make_float2(0.f, 0.f);
            ull vd0 = pack2(v.x, v.x), vd1 = pack2(v.y, v.y);
            const ulonglong2* w2 = (const ulonglong2*)&swg[(32 + e * 32 + c) * 32];
#pragma unroll
            for (int q = 0; q < 8; q++) {
                ulonglong2 w = w2[q];
                acc0[q * 2 + 0] = fma2(vd0, w.x, acc0[q * 2 + 0]);
                acc0[q * 2 + 1] = fma2(vd0, w.y, acc0[q * 2 + 1]);
                acc1[q * 2 + 0] = fma2(vd1, w.x, acc1[q * 2 + 0]);
                acc1[q * 2 + 1] = fma2(vd1, w.y, acc1[q * 2 + 1]);
            }
        }
    }
    float f0[32], f1[32];
#pragma unroll
    for (int q = 0; q < 16; q++) {
        unpack2(acc0[q], f0[q * 2], f0[q * 2 + 1]);
        unpack2(acc1[q], f1[q * 2], f1[q * 2 + 1]);
    }
    if (active) {
#pragma unroll
        for (int o = 0; o < 32; o++) {
            size_t rbase = ((size_t)(b * 32 + o) * Tin + t + dd) * NNODE;
            size_t wbase = ((size_t)(b * 32 + o) * Tout + t) * NNODE;
            float2 rv = *(const float2*)&Xc[rbase + n0];
            f0[o] += rv.x * sA[o] + sB[o];
            f1[o] += rv.y * sA[o] + sB[o];
            *(float2*)&Xn[wbase + n0] = make_float2(f0[o], f1[o]);
        }
    }
    int lane = tid & 31, warp = tid >> 5;
#pragma unroll
    for (int o = 0; o < 32; o++) {
        float s = active ? (f0[o] + f1[o]) : 0.f;
        float q = active ? (f0[o] * f0[o] + f1[o] * f1[o]) : 0.f;
#pragma unroll
        for (int off = 16; off; off >>= 1) {
            s += __shfl_down_sync(0xffffffffu, s, off);
            q += __shfl_down_sync(0xffffffffu, q, off);
        }
        if (lane == 0) { sredS[warp][o] = s; sredQ[warp][o] = q; }
    }
    __syncthreads();
    if (tid < 64) {
        int o = tid & 31;
        bool isq = (tid >= 32);
        float v = 0.f;
#pragma unroll
        for (int w = 0; w < 4; w++) v += (isq ? sredQ[w][o] : sredS[w][o]);
        size_t bidx = (size_t)(blockIdx.z * gridDim.y + blockIdx.y) * gridDim.x + blockIdx.x;
        part[bidx * 64 + tid] = v;
    }
}

// reduce partials -> fused BN scale/shift into per-layer slot
__global__ void k_redstats(const float* __restrict__ part, int nblk, float cnt,
                           const float* __restrict__ g, const float* __restrict__ bta,
                           float* __restrict__ ab) {
    int c = blockIdx.x;
    int tid = threadIdx.x;
    double s = 0.0, q = 0.0;
    for (int i = tid; i < nblk; i += 256) {
        s += (double)part[(size_t)i * 64 + c];
        q += (double)part[(size_t)i * 64 + 32 + c];
    }
    __shared__ double rs[256], rq[256];
    rs[tid] = s; rq[tid] = q;
    __syncthreads();
    for (int st = 128; st > 0; st >>= 1) {
        if (tid < st) { rs[tid] += rs[tid + st]; rq[tid] += rq[tid + st]; }
        __syncthreads();
    }
    if (tid == 0) {
        float mean = (float)(rs[0] / cnt);
        float var = (float)(rq[0] / cnt) - mean * mean;
        float a = g[c] * rsqrtf(var + BN_EPS);
        ab[c] = a;
        ab[32 + c] = bta[c] - mean * a;
    }
}

// ---------------- output head ----------------
__global__ void k_transpose_skip(const float* __restrict__ skip, const float* __restrict__ skp_b,
                                 float* __restrict__ Srelu) {
    __shared__ float tile[32][33];
    int b = blockIdx.z;
    int n0 = blockIdx.x * 32, c0 = blockIdx.y * 32;
    int n = n0 + threadIdx.x, c = c0 + threadIdx.y;
    tile[threadIdx.y][threadIdx.x] = (n < NNODE) ? skip[(size_t)(b * NSKIPC + c) * NNODE + n] : 0.f;
    __syncthreads();
    int n2 = n0 + threadIdx.y, c2 = c0 + threadIdx.x;
    float bsum = 0.f;
#pragma unroll
    for (int l = 0; l < LL; l++) bsum += skp_b[l * 256 + c2];
    if (n2 < NNODE)
        Srelu[(size_t)(b * NNODE + n2) * NSKIPC + c2] = fmaxf(tile[threadIdx.x][threadIdx.y] + bsum, 0.f);
}

__global__ void k_headfinal(const float* __restrict__ H, const float* __restrict__ o1b,
                            const float* __restrict__ o2w, const float* __restrict__ o2b,
                            float* __restrict__ out) {
    int warp = threadIdx.x >> 5, lane = threadIdx.x & 31;
    int row = blockIdx.x * 4 + warp;
    if (row >= BB * NNODE) return;
    int b = row / NNODE, n = row % NNODE;
    const float* Hr = H + (size_t)row * NENDC;
    float h[16];
#pragma unroll
    for (int i = 0; i < 16; i++)
        h[i] = fmaxf(Hr[lane + i * 32] + o1b[lane + i * 32], 0.f);
#pragma unroll
    for (int p = 0; p < NPREDC; p++) {
        float acc = 0.f;
#pragma unroll
        for (int i = 0; i < 16; i++) acc += o2w[p * NENDC + lane + i * 32] * h[i];
#pragma unroll
        for (int off = 16; off; off >>= 1) acc += __shfl_down_sync(0xffffffffu, acc, off);
        if (lane == 0) out[(size_t)(b * NPREDC + p) * NNODE + n] = acc + o2b[p];
    }
}

// ---------------- host launcher ----------------
extern "C" void kernel_launch(void* const* d_in, const int* in_sizes, int n_in,
                              void* d_out, int out_size) {
    const float* inputs = (const float*)d_in[0];
    const float* factor = (const float*)d_in[1];
    const float* map_w  = (const float*)d_in[2];
    const float* map_b  = (const float*)d_in[3];
    const float* a1w    = (const float*)d_in[4];
    const float* a1b    = (const float*)d_in[5];
    const float* a2w    = (const float*)d_in[6];
    const float* a2b    = (const float*)d_in[7];
    const float* a3w    = (const float*)d_in[8];
    const float* a3b    = (const float*)d_in[9];
    const float* enter_w = (const float*)d_in[10];
    const float* enter_b = (const float*)d_in[11];
    const float* filt_w = (const float*)d_in[12];
    const float* filt_b = (const float*)d_in[13];
    const float* gate_w = (const float*)d_in[14];
    const float* gate_b = (const float*)d_in[15];
    const float* skp_w  = (const float*)d_in[16];
    const float* skp_b  = (const float*)d_in[17];
    const float* gc_w   = (const float*)d_in[18];
    const float* gc_b   = (const float*)d_in[19];
    const float* bn_g   = (const float*)d_in[20];
    const float* bn_b   = (const float*)d_in[21];
    const float* o1w    = (const float*)d_in[22];
    const float* o1b    = (const float*)d_in[23];
    const float* o2w    = (const float*)d_in[24];
    const float* o2b    = (const float*)d_in[25];

    float *pScat, *pY, *pX0, *pX1, *pXG, *pXGcat, *pWcat, *pSkip, *pSrelu, *pO1T, *pPart, *pAB;
    cudaGetSymbolAddress((void**)&pScat, g_Scat);
    cudaGetSymbolAddress((void**)&pY, g_Y);
    cudaGetSymbolAddress((void**)&pX0, g_X0);
    cudaGetSymbolAddress((void**)&pX1, g_X1);
    cudaGetSymbolAddress((void**)&pXG, g_XG);
    cudaGetSymbolAddress((void**)&pXGcat, g_XGcat);
    cudaGetSymbolAddress((void**)&pWcat, g_Wcat);
    cudaGetSymbolAddress((void**)&pSkip, g_skip);
    cudaGetSymbolAddress((void**)&pSrelu, g_Srelu);
    cudaGetSymbolAddress((void**)&pO1T, g_o1wT);
    cudaGetSymbolAddress((void**)&pPart, g_part);
    cudaGetSymbolAddress((void**)&pAB, g_bnab);

    float* out = (float*)d_out;
    const int ySize = BB * NPREDC * NNODE;
    const int supSize = 2 * NNODE * NNODE;
    int writeSup = (out_size >= ySize + supSize) ? 1 : 0;
    float* outSup = out + ySize;

    static const int Tin[LL] = {13, 12, 10, 9, 7, 6, 4, 3};
    static const int Dd[LL]  = {1, 2, 1, 2, 1, 2, 1, 2};
    static const int To[LL]  = {12, 10, 9, 7, 6, 4, 3, 1};

    // input split + enter + prep, then layer-0 gatefilter (4th launch -> ncu capture)
    k_tmp<<<dim3(TT, BB), 256>>>(inputs, factor);
    k_enter<<<dim3(4, RFh, BB), 128>>>(inputs, factor, enter_w, enter_b, pX0);
    k_prep<<<512, 256>>>(skp_w, o1w);
    k_gatefilter<<<dim3(4, To[0], BB), 128>>>(pX0, pXG, pXGcat,
        filt_w, filt_b, gate_w, gate_b, pAB + LL * 64, Tin[0], To[0], Dd[0], 0);
    // adaptive adjacency
    k_pq<<<NNODE, 64>>>(factor, map_w, map_b, a1w, a1b);
    k_adjmlp<<<NNODE, 128>>>(a2w, a2b, a3w, a3b);
    k_softmax<<<2 * NNODE, 256>>>(outSup, writeSup);
    tgemm<<<dim3(4, 4, 2), 256>>>(pScat, pScat, pScat + 500, 500, 500, 500, 2000, 2000, 2000,
                                  1000, 1000, 1000);

    float* Xc = pX0;
    float* Xn = pX1;
    for (int i = 0; i < LL - 1; i++) {
        int slotPrev = (i == 0) ? LL : (i - 1);
        int M = BB * 32 * To[i];
        tgemm<<<dim3(16, M / 128), 256>>>(pXG, pScat, pY, M, 2000, 500,
                                          500, 2000, 2000, 0, 0, 0);
        k_gcres<<<dim3(2, To[i], BB), 128>>>(pXG, pY, Xc, Xn,
            gc_w + i * 5120, gc_b + i * 32, pAB + slotPrev * 64, pPart,
            Tin[i], To[i], Dd[i]);
        int nblk = 2 * To[i] * BB;
        k_redstats<<<32, 256>>>(pPart, nblk, (float)(BB * To[i] * NNODE),
                                bn_g + i * 32, bn_b + i * 32, pAB + i * 64);
        int j = i + 1;
        k_gatefilter<<<dim3(4, To[j], BB), 128>>>(Xn, pXG, pXGcat,
            filt_w + j * 2048, filt_b + j * 32, gate_w + j * 2048, gate_b + j * 32,
            pAB + i * 64, Tin[j], To[j], Dd[j], j);
        float* t = Xc; Xc = Xn; Xn = t;
    }
    // skip = Wcat @ XGcat  (batched over b)
    tgemm<<<dim3(4, 2, BB), 256>>>(pWcat, pXGcat, pSkip, 256, NNODE, 256,
                                   256, NNODE, NNODE, 0, 256 * NNODE, 256 * NNODE);
    // output head
    k_transpose_skip<<<dim3(16, 8, BB), dim3(32, 32)>>>(pSkip, skp_b, pSrelu);
    tgemm<<<dim3(4, 125), 256>>>(pSrelu, pO1T, pY, BB * NNODE, NENDC, NSKIPC,
                                 NSKIPC, NENDC, NENDC, 0, 0, 0);
    k_headfinal<<<(BB * NNODE + 3) / 4, 128>>>(pY, o1b, o2w, o2b, out);
}

// round 10
// speedup vs baseline: 1.2060x; 1.2060x over previous
#include <cuda_runtime.h>
#include <math.h>
#include <stdint.h>

// ---------------- static problem config ----------------
#define BB 32
#define TT 12
#define NNODE 500
#define NSKIPC 256
#define NENDC 512
#define NPREDC 12
#define LL 8
#define RFh 13
#define BN_EPS 1e-5f

typedef unsigned long long ull;
typedef unsigned int u32;

__device__ __forceinline__ ull pack2(float lo, float hi) {
    ull r; asm("mov.b64 %0,{%1,%2};" : "=l"(r) : "f"(lo), "f"(hi)); return r;
}
__device__ __forceinline__ ull fma2(ull a, ull b, ull c) {
    ull d; asm("fma.rn.f32x2 %0,%1,%2,%3;" : "=l"(d) : "l"(a), "l"(b), "l"(c)); return d;
}
__device__ __forceinline__ void unpack2(ull v, float& lo, float& hi) {
    asm("mov.b64 {%0,%1},%2;" : "=f"(lo), "=f"(hi) : "l"(v));
}
__device__ __forceinline__ float to_tf32(float x) {
    u32 r; asm("cvt.rna.tf32.f32 %0, %1;" : "=r"(r) : "f"(x));
    return __uint_as_float(r);
}
__device__ __forceinline__ void mma_tf32(float* c, const u32* a, const u32* b) {
    asm("mma.sync.aligned.m16n8k8.row.col.f32.tf32.tf32.f32 "
        "{%0,%1,%2,%3},{%4,%5,%6,%7},{%8,%9},{%0,%1,%2,%3};"
        : "+f"(c[0]), "+f"(c[1]), "+f"(c[2]), "+f"(c[3])
        : "r"(a[0]), "r"(a[1]), "r"(a[2]), "r"(a[3]), "r"(b[0]), "r"(b[1]));
}

// ---------------- device scratch ----------------
__device__ float g_P[NNODE * 64];
__device__ float g_Q[NNODE * 64];
__device__ float g_eraw[2 * NNODE * NNODE];
__device__ float g_Scat[NNODE * 2000];            // [v][ A0 | A0^2 | A1 | A1^2 ]
__device__ float g_tmp[BB * TT * 32 * 2];
__device__ float g_X0[BB * 32 * RFh * NNODE];
__device__ float g_X1[BB * 32 * RFh * NNODE];
__device__ float g_XG[BB * 32 * 12 * NNODE];
__device__ float g_Y[12288 * 2000];               // diffusion outputs; reused as head hidden H
__device__ float g_XGcat[BB * 256 * NNODE];       // last-t gated slices, rows (l*32+c)
__device__ float g_Wcat[256 * 256];               // skip weights re-laid [o][l*32+c]
__device__ float g_skip[BB * NSKIPC * NNODE];
__device__ float g_Srelu[BB * NNODE * NSKIPC];
__device__ float g_o1wT[NSKIPC * NENDC];
__device__ float g_part[1536 * 64];               // per-block BN partial sums
__device__ float g_bnab[(LL + 1) * 64];           // per-layer fused BN scale/shift; slot LL = identity
__device__ float g_Wf[64 * 64];                   // fused gated-conv weights (tf32), rows o, cols r=kk*32+c
__device__ float g_bf[64];                        // fused gated-conv bias

// ---------------- fused one-time prep ----------------
__global__ void k_prep(const float* __restrict__ skp_w, const float* __restrict__ o1w) {
    int idx = blockIdx.x * 256 + threadIdx.x;
    if (idx < 64) g_bnab[LL * 64 + idx] = (idx < 32) ? 1.f : 0.f;
    if (idx < 65536) {
        int o = idx >> 8, r = idx & 255, l = r >> 5, c = r & 31;
        g_Wcat[idx] = skp_w[l * 8192 + o * 32 + c];
    }
    if (idx < 131072) {
        int h = idx / NSKIPC, c = idx % NSKIPC;
        g_o1wT[c * NENDC + h] = o1w[idx];
    }
}

// ---------------- per-layer fused gated-conv weights (BN fold) ----------------
__global__ void k_fusew(const float* __restrict__ fw, const float* __restrict__ fb,
                        const float* __restrict__ gw, const float* __restrict__ gb,
                        const float* __restrict__ ab, int identity) {
    int o = threadIdx.x;   // 64 threads: 0-31 filter, 32-63 gate
    const float* w = (o < 32) ? fw : gw;
    int oo = o & 31;
    float bias = (o < 32) ? fb[oo] : gb[oo];
    float bsum = 0.f;
#pragma unroll
    for (int c = 0; c < 32; c++) {
        float a = identity ? 1.f : ab[c];
        float bb = identity ? 0.f : ab[32 + c];
        float w0 = w[oo * 64 + c * 2 + 0];
        float w1 = w[oo * 64 + c * 2 + 1];
        g_Wf[o * 64 + c] = to_tf32(w0 * a);          // r = 0*32 + c (kk=0)
        g_Wf[o * 64 + 32 + c] = to_tf32(w1 * a);     // r = 1*32 + c (kk=1)
        bsum += (w0 + w1) * bb;
    }
    g_bf[o] = bias + bsum;
}

// ---------------- adjacency ----------------
__global__ void k_pq(const float* __restrict__ factor, const float* __restrict__ map_w,
                     const float* __restrict__ map_b,
                     const float* __restrict__ a1w, const float* __restrict__ a1b) {
    __shared__ float vv[32];
    int j = blockIdx.x, h = threadIdx.x;   // 64 threads
    if (h < 32) {
        float acc = map_b[h];
#pragma unroll
        for (int u = 0; u < 32; u++) acc += factor[j * 32 + u] * map_w[u * 32 + h];
        vv[h] = fmaxf(acc, 0.f);
    }
    __syncthreads();
    float p = 0.f, q = a1b[h];
#pragma unroll
    for (int d = 0; d < 32; d++) {
        p += vv[d] * a1w[d * 64 + h];
        q += vv[d] * a1w[(32 + d) * 64 + h];
    }
    g_P[j * 64 + h] = p;
    g_Q[j * 64 + h] = q;
}

__global__ void k_adjmlp(const float* __restrict__ a2w, const float* __restrict__ a2b,
                         const float* __restrict__ a3w, const float* __restrict__ a3b) {
    __shared__ float Pt[128][65];
    __shared__ __align__(16) float sA2[64][32];
    __shared__ float sQ[64];
    __shared__ float sA3[64];
    __shared__ float sA2b[32];
    __shared__ float sA3b[2];
    int i = blockIdx.x, tid = threadIdx.x;
    for (int k = tid; k < 64 * 32; k += 128) sA2[k / 32][k % 32] = a2w[k];
    if (tid < 64) { sQ[tid] = g_Q[i * 64 + tid]; sA3[tid] = a3w[tid]; }
    if (tid < 32) sA2b[tid] = a2b[tid];
    if (tid < 2) sA3b[tid] = a3b[tid];
    for (int j0 = 0; j0 < NNODE; j0 += 128) {
        __syncthreads();
        int cnt = min(128, NNODE - j0);
        for (int k = tid; k < cnt * 64; k += 128)
            Pt[k / 64][k % 64] = g_P[(j0 + (k / 64)) * 64 + (k % 64)];
        __syncthreads();
        if (tid < cnt) {
            int j = j0 + tid;
            float h1[64];
#pragma unroll
            for (int h = 0; h < 64; h++) h1[h] = fmaxf(Pt[tid][h] + sQ[h], 0.f);
            float e0 = sA3b[0], e1 = sA3b[1];
#pragma unroll
            for (int c = 0; c < 32; c++) {
                float acc = sA2b[c];
#pragma unroll
                for (int h = 0; h < 64; h++) acc += h1[h] * sA2[h][c];
                acc = fmaxf(acc, 0.f);
                e0 += acc * sA3[c * 2];
                e1 += acc * sA3[c * 2 + 1];
            }
            g_eraw[i * NNODE + j] = e0;
            g_eraw[NNODE * NNODE + i * NNODE + j] = e1;
        }
    }
}

__global__ void k_softmax(float* __restrict__ outSup, int writeSup) {
    int bid = blockIdx.x;
    int e = bid / NNODE, i = bid % NNODE;
    const float* row = g_eraw + e * NNODE * NNODE + i * NNODE;
    __shared__ float red[256];
    int tid = threadIdx.x;
    float m = -1e30f;
    for (int j = tid; j < NNODE; j += 256) m = fmaxf(m, row[j]);
    red[tid] = m; __syncthreads();
    for (int s = 128; s > 0; s >>= 1) { if (tid < s) red[tid] = fmaxf(red[tid], red[tid + s]); __syncthreads(); }
    m = red[0]; __syncthreads();
    float sum = 0.f;
    for (int j = tid; j < NNODE; j += 256) sum += expf(row[j] - m);
    red[tid] = sum; __syncthreads();
    for (int s = 128; s > 0; s >>= 1) { if (tid < s) red[tid] += red[tid + s]; __syncthreads(); }
    float inv = 1.f / red[0];
    for (int j = tid; j < NNODE; j += 256) {
        float p = expf(row[j] - m) * inv;
        if (j == i) p = fmaxf(p, 1.f);
        g_Scat[i * 2000 + e * 1000 + j] = p;
        if (writeSup) outSup[(e * NNODE + i) * NNODE + j] = p;
    }
}

// ---------------- tf32 tensor-core GEMM (R4 version: simple layouts) ----------------
__global__ __launch_bounds__(256)
void tgemm(const float* __restrict__ A, const float* __restrict__ B, float* __restrict__ C,
           int M, int N, int K, int lda, int ldb, int ldc,
           int sA, int sB, int sC) {
    __shared__ __align__(16) float As[2][16][136];   // [buf][k][m]
    __shared__ __align__(16) float Bs[2][16][136];   // [buf][k][n]
    A += (size_t)blockIdx.z * sA;
    B += (size_t)blockIdx.z * sB;
    C += (size_t)blockIdx.z * sC;
    int tid = threadIdx.x;
    int m0 = blockIdx.y * 128, n0 = blockIdx.x * 128;
    int lane = tid & 31, wid = tid >> 5;
    int wm = wid & 1, wn = wid >> 1;
    int gid = lane >> 2, tig = lane & 3;
    int lm = tid >> 1, lrh = tid & 1;
    int lkl = tid >> 4, lnq = (tid & 15) << 3;

    float acc[4][4][4];
#pragma unroll
    for (int mi = 0; mi < 4; mi++)
#pragma unroll
        for (int ni = 0; ni < 4; ni++)
#pragma unroll
            for (int r = 0; r < 4; r++) acc[mi][ni][r] = 0.f;

    int nkt = (K + 15) / 16;
    {
        float av[8];
        int row = m0 + lm, c0 = lrh * 8;
        if (row < M && c0 + 7 < K) {
            float4 p = *(const float4*)(A + (size_t)row * lda + c0);
            float4 q = *(const float4*)(A + (size_t)row * lda + c0 + 4);
            av[0]=p.x; av[1]=p.y; av[2]=p.z; av[3]=p.w; av[4]=q.x; av[5]=q.y; av[6]=q.z; av[7]=q.w;
        } else {
#pragma unroll
            for (int l = 0; l < 8; l++)
                av[l] = (row < M && c0 + l < K) ? A[(size_t)row * lda + c0 + l] : 0.f;
        }
#pragma unroll
        for (int l = 0; l < 8; l++) As[0][lrh * 8 + l][lm] = to_tf32(av[l]);
        float bv[8];
        int br = lkl, bc = n0 + lnq;
        if (br < K && bc + 7 < N) {
            float4 p = *(const float4*)(B + (size_t)br * ldb + bc);
            float4 q = *(const float4*)(B + (size_t)br * ldb + bc + 4);
            bv[0]=p.x; bv[1]=p.y; bv[2]=p.z; bv[3]=p.w; bv[4]=q.x; bv[5]=q.y; bv[6]=q.z; bv[7]=q.w;
        } else {
#pragma unroll
            for (int l = 0; l < 8; l++)
                bv[l] = (br < K && bc + l < N) ? B[(size_t)br * ldb + bc + l] : 0.f;
        }
        float4 f0 = make_float4(to_tf32(bv[0]), to_tf32(bv[1]), to_tf32(bv[2]), to_tf32(bv[3]));
        float4 f1 = make_float4(to_tf32(bv[4]), to_tf32(bv[5]), to_tf32(bv[6]), to_tf32(bv[7]));
        *(float4*)&Bs[0][lkl][lnq] = f0;
        *(float4*)&Bs[0][lkl][lnq + 4] = f1;
    }
    __syncthreads();

    for (int kt = 0; kt < nkt; kt++) {
        int cur = kt & 1;
        bool hn = (kt + 1 < nkt);
        float av[8], bv[8];
        if (hn) {
            int kc0 = (kt + 1) * 16;
            int row = m0 + lm, c0 = kc0 + lrh * 8;
            if (row < M && c0 + 7 < K) {
                float4 p = *(const float4*)(A + (size_t)row * lda + c0);
                float4 q = *(const float4*)(A + (size_t)row * lda + c0 + 4);
                av[0]=p.x; av[1]=p.y; av[2]=p.z; av[3]=p.w; av[4]=q.x; av[5]=q.y; av[6]=q.z; av[7]=q.w;
            } else {
#pragma unroll
                for (int l = 0; l < 8; l++)
                    av[l] = (row < M && c0 + l < K) ? A[(size_t)row * lda + c0 + l] : 0.f;
            }
            int br = kc0 + lkl, bc = n0 + lnq;
            if (br < K && bc + 7 < N) {
                float4 p = *(const float4*)(B + (size_t)br * ldb + bc);
                float4 q = *(const float4*)(B + (size_t)br * ldb + bc + 4);
                bv[0]=p.x; bv[1]=p.y; bv[2]=p.z; bv[3]=p.w; bv[4]=q.x; bv[5]=q.y; bv[6]=q.z; bv[7]=q.w;
            } else {
#pragma unroll
                for (int l = 0; l < 8; l++)
                    bv[l] = (br < K && bc + l < N) ? B[(size_t)br * ldb + bc + l] : 0.f;
            }
        }
#pragma unroll
        for (int ks = 0; ks < 16; ks += 8) {
            u32 af[4][4];
            u32 bf[4][2];
#pragma unroll
            for (int mi = 0; mi < 4; mi++) {
                int mb = wm * 64 + mi * 16 + gid;
                af[mi][0] = __float_as_uint(As[cur][ks + tig][mb]);
                af[mi][1] = __float_as_uint(As[cur][ks + tig][mb + 8]);
                af[mi][2] = __float_as_uint(As[cur][ks + tig + 4][mb]);
                af[mi][3] = __float_as_uint(As[cur][ks + tig + 4][mb + 8]);
            }
#pragma unroll
            for (int ni = 0; ni < 4; ni++) {
                int nb = wn * 32 + ni * 8 + gid;
                bf[ni][0] = __float_as_uint(Bs[cur][ks + tig][nb]);
                bf[ni][1] = __float_as_uint(Bs[cur][ks + tig + 4][nb]);
            }
#pragma unroll
            for (int mi = 0; mi < 4; mi++)
#pragma unroll
                for (int ni = 0; ni < 4; ni++)
                    mma_tf32(acc[mi][ni], af[mi], bf[ni]);
        }
        if (hn) {
            int nxt = cur ^ 1;
#pragma unroll
            for (int l = 0; l < 8; l++) As[nxt][lrh * 8 + l][lm] = to_tf32(av[l]);
            float4 f0 = make_float4(to_tf32(bv[0]), to_tf32(bv[1]), to_tf32(bv[2]), to_tf32(bv[3]));
            float4 f1 = make_float4(to_tf32(bv[4]), to_tf32(bv[5]), to_tf32(bv[6]), to_tf32(bv[7]));
            *(float4*)&Bs[nxt][lkl][lnq] = f0;
            *(float4*)&Bs[nxt][lkl][lnq + 4] = f1;
            __syncthreads();
        }
    }
#pragma unroll
    for (int mi = 0; mi < 4; mi++) {
        int r0 = m0 + wm * 64 + mi * 16 + gid;
        int r1 = r0 + 8;
#pragma unroll
        for (int ni = 0; ni < 4; ni++) {
            int cc = n0 + wn * 32 + ni * 8 + tig * 2;
            if (r0 < M) {
                if (cc + 1 < N) *(float2*)(C + (size_t)r0 * ldc + cc) = make_float2(acc[mi][ni][0], acc[mi][ni][1]);
                else if (cc < N) C[(size_t)r0 * ldc + cc] = acc[mi][ni][0];
            }
            if (r1 < M) {
                if (cc + 1 < N) *(float2*)(C + (size_t)r1 * ldc + cc) = make_float2(acc[mi][ni][2], acc[mi][ni][3]);
                else if (cc < N) C[(size_t)r1 * ldc + cc] = acc[mi][ni][2];
            }
        }
    }
}

// ---------------- gated conv as tensor GEMM: M=64(f||g), K=64(c,kk), N=Tout*NNODE ----------------
// B rows r: kk = r>>5, c = r&31 -> X offset c*Tin*N + kk*dd*N + col  (col = t*N + n, contiguous)
__global__ __launch_bounds__(256)
void gfgemm(const float* __restrict__ X, float* __restrict__ XG, float* __restrict__ XGcat,
            int Tin, int Tout, int dd, int layer) {
    __shared__ __align__(16) float Bs[64][136];   // B tile; reused as C-exchange after compute
    int tid = threadIdx.x;
    int b = blockIdx.y;
    int n0 = blockIdx.x * 128;
    int ToutN = Tout * NNODE;
    int TinN = Tin * NNODE;
    const float* Xb = X + (size_t)b * 32 * TinN;

    int lane = tid & 31, wid = tid >> 5;
    int wm = wid & 3, wn = wid >> 2;       // warp grid 4(m) x 2(n); warp tile 16 x 64
    int gid = lane >> 2, tig = lane & 3;

    // A fragments (fused weights) -> registers
    u32 af[8][4];
    {
        int r0 = wm * 16 + gid, r1 = r0 + 8;
#pragma unroll
        for (int ks = 0; ks < 8; ks++) {
            af[ks][0] = __float_as_uint(g_Wf[r0 * 64 + ks * 8 + tig]);
            af[ks][1] = __float_as_uint(g_Wf[r1 * 64 + ks * 8 + tig]);
            af[ks][2] = __float_as_uint(g_Wf[r0 * 64 + ks * 8 + tig + 4]);
            af[ks][3] = __float_as_uint(g_Wf[r1 * 64 + ks * 8 + tig + 4]);
        }
    }

    // stage B tile (64 rows x 128 cols) with tf32 conversion
    {
        int lr = tid >> 2, lq = tid & 3;
        size_t rbase = (size_t)(lr & 31) * TinN + (size_t)(lr >> 5) * (dd * NNODE);
        const float* src = Xb + rbase + n0;
#pragma unroll
        for (int i = 0; i < 8; i++) {
            int col = (lq + i * 4) * 4;
            int gcol = n0 + col;
            float4 v;
            if (gcol + 3 < ToutN) {
                v = *(const float4*)(src + col);
            } else {
                v.x = (gcol + 0 < ToutN) ? src[col + 0] : 0.f;
                v.y = (gcol + 1 < ToutN) ? src[col + 1] : 0.f;
                v.z = (gcol + 2 < ToutN) ? src[col + 2] : 0.f;
                v.w = (gcol + 3 < ToutN) ? src[col + 3] : 0.f;
            }
            float4 f = make_float4(to_tf32(v.x), to_tf32(v.y), to_tf32(v.z), to_tf32(v.w));
            *(float4*)&Bs[lr][col] = f;
        }
    }
    __syncthreads();

    float acc[8][4];
#pragma unroll
    for (int ni = 0; ni < 8; ni++)
#pragma unroll
        for (int r = 0; r < 4; r++) acc[ni][r] = 0.f;

#pragma unroll
    for (int ks = 0; ks < 8; ks++) {
#pragma unroll
        for (int ni = 0; ni < 8; ni++) {
            int nb = wn * 64 + ni * 8 + gid;
            u32 bfr[2] = { __float_as_uint(Bs[ks * 8 + tig][nb]),
                           __float_as_uint(Bs[ks * 8 + tig + 4][nb]) };
            mma_tf32(acc[ni], af[ks], bfr);
        }
    }
    __syncthreads();   // done reading B -> reuse as C exchange

#pragma unroll
    for (int ni = 0; ni < 8; ni++) {
        int cc = wn * 64 + ni * 8 + tig * 2;
        int r0 = wm * 16 + gid;
        Bs[r0][cc] = acc[ni][0]; Bs[r0][cc + 1] = acc[ni][1];
        Bs[r0 + 8][cc] = acc[ni][2]; Bs[r0 + 8][cc + 1] = acc[ni][3];
    }
    __syncthreads();

    // epilogue: gated activation + XG / XGcat stores
    {
        int o = tid >> 3;                 // 0..31
        float bff = g_bf[o], bfg = g_bf[o + 32];
        size_t xgbase = (size_t)(b * 32 + o) * ToutN;
        size_t catbase = ((size_t)b * 256 + layer * 32 + o) * NNODE;
        int lastBase = (Tout - 1) * NNODE;
#pragma unroll
        for (int j = 0; j < 4; j++) {
            int col = (tid & 7) * 4 + j * 32;
            int gcol = n0 + col;
            if (gcol >= ToutN) continue;
            float vv[4];
#pragma unroll
            for (int k = 0; k < 4; k++) {
                float f = Bs[o][col + k] + bff;
                float g = Bs[o + 32][col + k] + bfg;
                vv[k] = tanhf(f) * (1.f / (1.f + expf(-g)));
            }
            if (gcol + 3 < ToutN) {
                *(float4*)&XG[xgbase + gcol] = make_float4(vv[0], vv[1], vv[2], vv[3]);
            } else {
#pragma unroll
                for (int k = 0; k < 4; k++)
                    if (gcol + k < ToutN) XG[xgbase + gcol + k] = vv[k];
            }
#pragma unroll
            for (int k = 0; k < 4; k++) {
                int gc = gcol + k;
                if (gc >= lastBase && gc < ToutN)
                    XGcat[catbase + (gc - lastBase)] = vv[k];
            }
        }
    }
}

// ---------------- input split + enter ----------------
__global__ void k_tmp(const float* __restrict__ inputs, const float* __restrict__ factor) {
    int t = blockIdx.x, b = blockIdx.y, tid = threadIdx.x;
    int o = tid >> 2, r = tid & 3;
    int u = o >> 1, f = o & 1;
    const float* inp = inputs + ((size_t)(b * TT + t) * NNODE) * 2 + f;
    float acc = 0.f;
    for (int n = r; n < NNODE; n += 4) acc += inp[n * 2] * factor[n * 32 + u];
    acc += __shfl_down_sync(0xffffffffu, acc, 2);
    acc += __shfl_down_sync(0xffffffffu, acc, 1);
    if (r == 0) g_tmp[(b * TT + t) * 64 + o] = acc;
}

__global__ void k_enter(const float* __restrict__ inputs, const float* __restrict__ factor,
                        const float* __restrict__ ew, const float* __restrict__ eb,
                        float* __restrict__ X0) {
    __shared__ float sw[128], sb[32], stmp[64];
    int b = blockIdx.z, tp = blockIdx.y;
    int tid = threadIdx.x;
    if (tid < 128) sw[tid] = ew[tid];
    if (tid < 32) sb[tid] = eb[tid];
    if (tp > 0 && tid < 64) stmp[tid] = g_tmp[(b * TT + (tp - 1)) * 64 + tid];
    __syncthreads();
    int n = blockIdx.x * 128 + tid;
    if (n >= NNODE) return;
    if (tp == 0) {
#pragma unroll
        for (int o = 0; o < 32; o++)
            X0[((size_t)(b * 32 + o) * RFh + 0) * NNODE + n] = sb[o];
    } else {
        int t = tp - 1;
        float s0 = 0.f, s1 = 0.f;
#pragma unroll
        for (int u = 0; u < 32; u++) {
            float fv = factor[n * 32 + u];
            s0 += fv * stmp[u * 2];
            s1 += fv * stmp[u * 2 + 1];
        }
        float i0 = inputs[((size_t)(b * TT + t) * NNODE + n) * 2 + 0];
        float i1 = inputs[((size_t)(b * TT + t) * NNODE + n) * 2 + 1];
        float r0 = i0 - s0, r1 = i1 - s1;
#pragma unroll
        for (int o = 0; o < 32; o++) {
            float v = sb[o] + sw[o * 4] * s0 + sw[o * 4 + 1] * s1 + sw[o * 4 + 2] * r0 + sw[o * 4 + 3] * r1;
            X0[((size_t)(b * 32 + o) * RFh + tp) * NNODE + n] = v;
        }
    }
}

// ---------------- gc 1x1 + residual(BN-fused) + BN partial stats; adjacent node pairs ----------------
__global__ void k_gcres(const float* __restrict__ XG, const float* __restrict__ Y,
                        const float* __restrict__ Xc, float* __restrict__ Xn,
                        const float* __restrict__ gcw, const float* __restrict__ gcb,
                        const float* __restrict__ abPrev,
                        float* __restrict__ part, int Tin, int Tout, int dd) {
    __shared__ __align__(16) float swg[160 * 32];
    __shared__ float sgb[32], sA[32], sB[32];
    __shared__ float sredS[4][32];
    __shared__ float sredQ[4][32];
    int tid = threadIdx.x;
    for (int idx = tid; idx < 160 * 32; idx += 128) {
        int c = idx / 32, o = idx % 32;
        swg[idx] = gcw[o * 160 + c];
    }
    if (tid < 32) { sgb[tid] = gcb[tid]; sA[tid] = abPrev[tid]; sB[tid] = abPrev[32 + tid]; }
    __syncthreads();
    int n0 = blockIdx.x * 256 + tid * 2;
    int t = blockIdx.y, b = blockIdx.z;
    bool active = (n0 < NNODE);
    ull acc0[16], acc1[16];
#pragma unroll
    for (int q = 0; q < 16; q++) {
        ull bias = active ? pack2(sgb[q * 2], sgb[q * 2 + 1]) : pack2(0.f, 0.f);
        acc0[q] = bias;
        acc1[q] = bias;
    }
    for (int c = 0; c < 32; c++) {
        size_t base = ((size_t)(b * 32 + c) * Tout + t) * NNODE;
        float2 v = active ? *(const float2*)&XG[base + n0] : make_float2(0.f, 0.f);
        ull vd0 = pack2(v.x, v.x), vd1 = pack2(v.y, v.y);
        const ulonglong2* w2 = (const ulonglong2*)&swg[c * 32];
#pragma unroll
        for (int q = 0; q < 8; q++) {
            ulonglong2 w = w2[q];
            acc0[q * 2 + 0] = fma2(vd0, w.x, acc0[q * 2 + 0]);
            acc0[q * 2 + 1] = fma2(vd0, w.y, acc0[q * 2 + 1]);
            acc1[q * 2 + 0] = fma2(vd1, w.x, acc1[q * 2 + 0]);
            acc1[q * 2 + 1] = fma2(vd1, w.y, acc1[q * 2 + 1]);
        }
    }
    for (int e = 0; e < 4; e++) {
        for (int c = 0; c < 32; c++) {
            size_t m = ((size_t)(b * 32 + c) * Tout + t) * 2000 + e * 500;
            float2 v = active ? *(const float2*)&Y[m + n0] : make_float2(0.f, 0.f);
            ull vd0 = pack2(v.x, v.x), vd1 = pack2(v.y, v.y);
            const ulonglong2* w2 = (const ulonglong2*)&swg[(32 + e * 32 + c) * 32];
#pragma unroll
            for (int q = 0; q < 8; q++) {
                ulonglong2 w = w2[q];
                acc0[q * 2 + 0] = fma2(vd0, w.x, acc0[q * 2 + 0]);
                acc0[q * 2 + 1] = fma2(vd0, w.y, acc0[q * 2 + 1]);
                acc1[q * 2 + 0] = fma2(vd1, w.x, acc1[q * 2 + 0]);
                acc1[q * 2 + 1] = fma2(vd1, w.y, acc1[q * 2 + 1]);
            }
        }
    }
    float f0[32], f1[32];
#pragma unroll
    for (int q = 0; q < 16; q++) {
        unpack2(acc0[q], f0[q * 2], f0[q * 2 + 1]);
        unpack2(acc1[q], f1[q * 2], f1[q * 2 + 1]);
    }
    if (active) {
#pragma unroll
        for (int o = 0; o < 32; o++) {
            size_t rbase = ((size_t)(b * 32 + o) * Tin + t + dd) * NNODE;
            size_t wbase = ((size_t)(b * 32 + o) * Tout + t) * NNODE;
            float2 rv = *(const float2*)&Xc[rbase + n0];
            f0[o] += rv.x * sA[o] + sB[o];
            f1[o] += rv.y * sA[o] + sB[o];
            *(float2*)&Xn[wbase + n0] = make_float2(f0[o], f1[o]);
        }
    }
    int lane = tid & 31, warp = tid >> 5;
#pragma unroll
    for (int o = 0; o < 32; o++) {
        float s = active ? (f0[o] + f1[o]) : 0.f;
        float q = active ? (f0[o] * f0[o] + f1[o] * f1[o]) : 0.f;
#pragma unroll
        for (int off = 16; off; off >>= 1) {
            s += __shfl_down_sync(0xffffffffu, s, off);
            q += __shfl_down_sync(0xffffffffu, q, off);
        }
        if (lane == 0) { sredS[warp][o] = s; sredQ[warp][o] = q; }
    }
    __syncthreads();
    if (tid < 64) {
        int o = tid & 31;
        bool isq = (tid >= 32);
        float v = 0.f;
#pragma unroll
        for (int w = 0; w < 4; w++) v += (isq ? sredQ[w][o] : sredS[w][o]);
        size_t bidx = (size_t)(blockIdx.z * gridDim.y + blockIdx.y) * gridDim.x + blockIdx.x;
        part[bidx * 64 + tid] = v;
    }
}

// reduce partials -> fused BN scale/shift into per-layer slot
__global__ void k_redstats(const float* __restrict__ part, int nblk, float cnt,
                           const float* __restrict__ g, const float* __restrict__ bta,
                           float* __restrict__ ab) {
    int c = blockIdx.x;
    int tid = threadIdx.x;
    double s = 0.0, q = 0.0;
    for (int i = tid; i < nblk; i += 256) {
        s += (double)part[(size_t)i * 64 + c];
        q += (double)part[(size_t)i * 64 + 32 + c];
    }
    __shared__ double rs[256], rq[256];
    rs[tid] = s; rq[tid] = q;
    __syncthreads();
    for (int st = 128; st > 0; st >>= 1) {
        if (tid < st) { rs[tid] += rs[tid + st]; rq[tid] += rq[tid + st]; }
        __syncthreads();
    }
    if (tid == 0) {
        float mean = (float)(rs[0] / cnt);
        float var = (float)(rq[0] / cnt) - mean * mean;
        float a = g[c] * rsqrtf(var + BN_EPS);
        ab[c] = a;
        ab[32 + c] = bta[c] - mean * a;
    }
}

// ---------------- output head ----------------
__global__ void k_transpose_skip(const float* __restrict__ skip, const float* __restrict__ skp_b,
                                 float* __restrict__ Srelu) {
    __shared__ float tile[32][33];
    int b = blockIdx.z;
    int n0 = blockIdx.x * 32, c0 = blockIdx.y * 32;
    int n = n0 + threadIdx.x, c = c0 + threadIdx.y;
    tile[threadIdx.y][threadIdx.x] = (n < NNODE) ? skip[(size_t)(b * NSKIPC + c) * NNODE + n] : 0.f;
    __syncthreads();
    int n2 = n0 + threadIdx.y, c2 = c0 + threadIdx.x;
    float bsum = 0.f;
#pragma unroll
    for (int l = 0; l < LL; l++) bsum += skp_b[l * 256 + c2];
    if (n2 < NNODE)
        Srelu[(size_t)(b * NNODE + n2) * NSKIPC + c2] = fmaxf(tile[threadIdx.x][threadIdx.y] + bsum, 0.f);
}

__global__ void k_headfinal(const float* __restrict__ H, const float* __restrict__ o1b,
                            const float* __restrict__ o2w, const float* __restrict__ o2b,
                            float* __restrict__ out) {
    int warp = threadIdx.x >> 5, lane = threadIdx.x & 31;
    int row = blockIdx.x * 4 + warp;
    if (row >= BB * NNODE) return;
    int b = row / NNODE, n = row % NNODE;
    const float* Hr = H + (size_t)row * NENDC;
    float h[16];
#pragma unroll
    for (int i = 0; i < 16; i++)
        h[i] = fmaxf(Hr[lane + i * 32] + o1b[lane + i * 32], 0.f);
#pragma unroll
    for (int p = 0; p < NPREDC; p++) {
        float acc = 0.f;
#pragma unroll
        for (int i = 0; i < 16; i++) acc += o2w[p * NENDC + lane + i * 32] * h[i];
#pragma unroll
        for (int off = 16; off; off >>= 1) acc += __shfl_down_sync(0xffffffffu, acc, off);
        if (lane == 0) out[(size_t)(b * NPREDC + p) * NNODE + n] = acc + o2b[p];
    }
}

// ---------------- host launcher ----------------
extern "C" void kernel_launch(void* const* d_in, const int* in_sizes, int n_in,
                              void* d_out, int out_size) {
    const float* inputs = (const float*)d_in[0];
    const float* factor = (const float*)d_in[1];
    const float* map_w  = (const float*)d_in[2];
    const float* map_b  = (const float*)d_in[3];
    const float* a1w    = (const float*)d_in[4];
    const float* a1b    = (const float*)d_in[5];
    const float* a2w    = (const float*)d_in[6];
    const float* a2b    = (const float*)d_in[7];
    const float* a3w    = (const float*)d_in[8];
    const float* a3b    = (const float*)d_in[9];
    const float* enter_w = (const float*)d_in[10];
    const float* enter_b = (const float*)d_in[11];
    const float* filt_w = (const float*)d_in[12];
    const float* filt_b = (const float*)d_in[13];
    const float* gate_w = (const float*)d_in[14];
    const float* gate_b = (const float*)d_in[15];
    const float* skp_w  = (const float*)d_in[16];
    const float* skp_b  = (const float*)d_in[17];
    const float* gc_w   = (const float*)d_in[18];
    const float* gc_b   = (const float*)d_in[19];
    const float* bn_g   = (const float*)d_in[20];
    const float* bn_b   = (const float*)d_in[21];
    const float* o1w    = (const float*)d_in[22];
    const float* o1b    = (const float*)d_in[23];
    const float* o2w    = (const float*)d_in[24];
    const float* o2b    = (const float*)d_in[25];

    float *pScat, *pY, *pX0, *pX1, *pXG, *pXGcat, *pWcat, *pSkip, *pSrelu, *pO1T, *pPart, *pAB;
    cudaGetSymbolAddress((void**)&pScat, g_Scat);
    cudaGetSymbolAddress((void**)&pY, g_Y);
    cudaGetSymbolAddress((void**)&pX0, g_X0);
    cudaGetSymbolAddress((void**)&pX1, g_X1);
    cudaGetSymbolAddress((void**)&pXG, g_XG);
    cudaGetSymbolAddress((void**)&pXGcat, g_XGcat);
    cudaGetSymbolAddress((void**)&pWcat, g_Wcat);
    cudaGetSymbolAddress((void**)&pSkip, g_skip);
    cudaGetSymbolAddress((void**)&pSrelu, g_Srelu);
    cudaGetSymbolAddress((void**)&pO1T, g_o1wT);
    cudaGetSymbolAddress((void**)&pPart, g_part);
    cudaGetSymbolAddress((void**)&pAB, g_bnab);

    float* out = (float*)d_out;
    const int ySize = BB * NPREDC * NNODE;
    const int supSize = 2 * NNODE * NNODE;
    int writeSup = (out_size >= ySize + supSize) ? 1 : 0;
    float* outSup = out + ySize;

    static const int Tin[LL] = {13, 12, 10, 9, 7, 6, 4, 3};
    static const int Dd[LL]  = {1, 2, 1, 2, 1, 2, 1, 2};
    static const int To[LL]  = {12, 10, 9, 7, 6, 4, 3, 1};

    // launches 1..3, then gfgemm L0 as 4th (ncu capture target)
    k_fusew<<<1, 64>>>(filt_w, filt_b, gate_w, gate_b, pAB, 1);
    k_tmp<<<dim3(TT, BB), 256>>>(inputs, factor);
    k_enter<<<dim3(4, RFh, BB), 128>>>(inputs, factor, enter_w, enter_b, pX0);
    gfgemm<<<dim3((To[0] * NNODE + 127) / 128, BB), 256>>>(pX0, pXG, pXGcat,
                                                           Tin[0], To[0], Dd[0], 0);
    k_prep<<<512, 256>>>(skp_w, o1w);
    // adaptive adjacency
    k_pq<<<NNODE, 64>>>(factor, map_w, map_b, a1w, a1b);
    k_adjmlp<<<NNODE, 128>>>(a2w, a2b, a3w, a3b);
    k_softmax<<<2 * NNODE, 256>>>(outSup, writeSup);
    tgemm<<<dim3(4, 4, 2), 256>>>(pScat, pScat, pScat + 500, 500, 500, 500, 2000, 2000, 2000,
                                  1000, 1000, 1000);

    float* Xc = pX0;
    float* Xn = pX1;
    for (int i = 0; i < LL - 1; i++) {
        int slotPrev = (i == 0) ? LL : (i - 1);
        int M = BB * 32 * To[i];
        tgemm<<<dim3(16, M / 128), 256>>>(pXG, pScat, pY, M, 2000, 500,
                                          500, 2000, 2000, 0, 0, 0);
        k_gcres<<<dim3(2, To[i], BB), 128>>>(pXG, pY, Xc, Xn,
            gc_w + i * 5120, gc_b + i * 32, pAB + slotPrev * 64, pPart,
            Tin[i], To[i], Dd[i]);
        int nblk = 2 * To[i] * BB;
        k_redstats<<<32, 256>>>(pPart, nblk, (float)(BB * To[i] * NNODE),
                                bn_g + i * 32, bn_b + i * 32, pAB + i * 64);
        int j = i + 1;
        k_fusew<<<1, 64>>>(filt_w + j * 2048, filt_b + j * 32,
                           gate_w + j * 2048, gate_b + j * 32, pAB + i * 64, 0);
        gfgemm<<<dim3((To[j] * NNODE + 127) / 128, BB), 256>>>(Xn, pXG, pXGcat,
                                                               Tin[j], To[j], Dd[j], j);
        float* t = Xc; Xc = Xn; Xn = t;
    }
    // skip = Wcat @ XGcat  (batched over b)
    tgemm<<<dim3(4, 2, BB), 256>>>(pWcat, pXGcat, pSkip, 256, NNODE, 256,
                                   256, NNODE, NNODE, 0, 256 * NNODE, 256 * NNODE);
    // output head
    k_transpose_skip<<<dim3(16, 8, BB), dim3(32, 32)>>>(pSkip, skp_b, pSrelu);
    tgemm<<<dim3(4, 125), 256>>>(pSrelu, pO1T, pY, BB * NNODE, NENDC, NSKIPC,
                                 NSKIPC, NENDC, NENDC, 0, 0, 0);
    k_headfinal<<<(BB * NNODE + 3) / 4, 128>>>(pY, o1b, o2w, o2b, out);
}

// round 11
// speedup vs baseline: 1.2615x; 1.0461x over previous
#include <cuda_runtime.h>
#include <math.h>
#include <stdint.h>

// ---------------- static problem config ----------------
#define BB 32
#define TT 12
#define NNODE 500
#define NSKIPC 256
#define NENDC 512
#define NPREDC 12
#define LL 8
#define RFh 13
#define BN_EPS 1e-5f

typedef unsigned long long ull;
typedef unsigned int u32;

__device__ __forceinline__ ull pack2(float lo, float hi) {
    ull r; asm("mov.b64 %0,{%1,%2};" : "=l"(r) : "f"(lo), "f"(hi)); return r;
}
__device__ __forceinline__ ull fma2(ull a, ull b, ull c) {
    ull d; asm("fma.rn.f32x2 %0,%1,%2,%3;" : "=l"(d) : "l"(a), "l"(b), "l"(c)); return d;
}
__device__ __forceinline__ void unpack2(ull v, float& lo, float& hi) {
    asm("mov.b64 {%0,%1},%2;" : "=f"(lo), "=f"(hi) : "l"(v));
}
__device__ __forceinline__ float to_tf32(float x) {
    u32 r; asm("cvt.rna.tf32.f32 %0, %1;" : "=r"(r) : "f"(x));
    return __uint_as_float(r);
}
__device__ __forceinline__ void mma_tf32(float* c, const u32* a, const u32* b) {
    asm("mma.sync.aligned.m16n8k8.row.col.f32.tf32.tf32.f32 "
        "{%0,%1,%2,%3},{%4,%5,%6,%7},{%8,%9},{%0,%1,%2,%3};"
        : "+f"(c[0]), "+f"(c[1]), "+f"(c[2]), "+f"(c[3])
        : "r"(a[0]), "r"(a[1]), "r"(a[2]), "r"(a[3]), "r"(b[0]), "r"(b[1]));
}
__device__ __forceinline__ void cp16(float* dst, const float* src, int bytes) {
    u32 d = (u32)__cvta_generic_to_shared(dst);
    asm volatile("cp.async.cg.shared.global [%0], [%1], 16, %2;\n"
                 :: "r"(d), "l"(src), "r"(bytes));
}

// ---------------- device scratch ----------------
__device__ float g_P[NNODE * 64];
__device__ float g_Q[NNODE * 64];
__device__ float g_eraw[2 * NNODE * NNODE];
__device__ float g_Scat[NNODE * 2000];            // tf32-rounded supports [A0|A0^2|A1|A1^2]
__device__ float g_tmp[BB * TT * 32 * 2];
__device__ float g_X0[BB * 32 * RFh * NNODE];
__device__ float g_X1[BB * 32 * RFh * NNODE];
__device__ float g_XG[BB * 32 * 12 * NNODE];      // tf32-rounded gated outputs
__device__ float g_Y[12288 * 2000];
__device__ float g_XGcat[BB * 256 * NNODE];       // tf32-rounded last-t gated slices
__device__ float g_Wcat[256 * 256];               // tf32-rounded
__device__ float g_skip[BB * NSKIPC * NNODE];
__device__ float g_Srelu[BB * NNODE * NSKIPC];    // tf32-rounded
__device__ float g_o1wT[NSKIPC * NENDC];          // tf32-rounded
__device__ float g_part[1536 * 64];
__device__ float g_bnab[(LL + 1) * 64];
__device__ float g_Wf[64 * 64];                   // tf32-rounded fused gated-conv weights
__device__ float g_bf[64];

// ---------------- fused one-time prep ----------------
__global__ void k_prep(const float* __restrict__ skp_w, const float* __restrict__ o1w) {
    int idx = blockIdx.x * 256 + threadIdx.x;
    if (idx < 64) g_bnab[LL * 64 + idx] = (idx < 32) ? 1.f : 0.f;
    if (idx < 65536) {
        int o = idx >> 8, r = idx & 255, l = r >> 5, c = r & 31;
        g_Wcat[idx] = to_tf32(skp_w[l * 8192 + o * 32 + c]);
    }
    if (idx < 131072) {
        int h = idx / NSKIPC, c = idx % NSKIPC;
        g_o1wT[c * NENDC + h] = to_tf32(o1w[idx]);
    }
}

// ---------------- layer-0 fused gated-conv weights (identity BN) ----------------
__global__ void k_fusew(const float* __restrict__ fw, const float* __restrict__ fb,
                        const float* __restrict__ gw, const float* __restrict__ gb) {
    int o = threadIdx.x;
    const float* w = (o < 32) ? fw : gw;
    int oo = o & 31;
    float bias = (o < 32) ? fb[oo] : gb[oo];
#pragma unroll
    for (int c = 0; c < 32; c++) {
        g_Wf[o * 64 + c] = to_tf32(w[oo * 64 + c * 2 + 0]);
        g_Wf[o * 64 + 32 + c] = to_tf32(w[oo * 64 + c * 2 + 1]);
    }
    g_bf[o] = bias;
}

// ---------------- BN stats reduce + next-layer weight fusion (one block) ----------------
__global__ void k_statsfusew(const float* __restrict__ part, int nblk, float cnt,
                             const float* __restrict__ g, const float* __restrict__ bta,
                             float* __restrict__ ab,
                             const float* __restrict__ fw, const float* __restrict__ fb,
                             const float* __restrict__ gw, const float* __restrict__ gb) {
    __shared__ float sab[64];
    int tid = threadIdx.x;
    int w = tid >> 5, lane = tid & 31;
    double s = 0.0, q = 0.0;
    for (int i = lane; i < nblk; i += 32) {
        s += (double)part[(size_t)i * 64 + w];
        q += (double)part[(size_t)i * 64 + 32 + w];
    }
#pragma unroll
    for (int off = 16; off; off >>= 1) {
        s += __shfl_down_sync(0xffffffffu, s, off);
        q += __shfl_down_sync(0xffffffffu, q, off);
    }
    if (lane == 0) {
        float mean = (float)(s / cnt);
        float var = (float)(q / cnt) - mean * mean;
        float a = g[w] * rsqrtf(var + BN_EPS);
        float sh = bta[w] - mean * a;
        sab[w] = a; sab[32 + w] = sh;
        ab[w] = a; ab[32 + w] = sh;
    }
    __syncthreads();
    if (tid < 64) {
        int o = tid;
        const float* wsrc = (o < 32) ? fw : gw;
        int oo = o & 31;
        float bias = (o < 32) ? fb[oo] : gb[oo];
        float bsum = 0.f;
#pragma unroll
        for (int c = 0; c < 32; c++) {
            float a = sab[c], bb = sab[32 + c];
            float w0 = wsrc[oo * 64 + c * 2 + 0];
            float w1 = wsrc[oo * 64 + c * 2 + 1];
            g_Wf[o * 64 + c] = to_tf32(w0 * a);
            g_Wf[o * 64 + 32 + c] = to_tf32(w1 * a);
            bsum += (w0 + w1) * bb;
        }
        g_bf[o] = bias + bsum;
    }
}

// ---------------- adjacency ----------------
__global__ void k_pq(const float* __restrict__ factor, const float* __restrict__ map_w,
                     const float* __restrict__ map_b,
                     const float* __restrict__ a1w, const float* __restrict__ a1b) {
    __shared__ float vv[32];
    int j = blockIdx.x, h = threadIdx.x;
    if (h < 32) {
        float acc = map_b[h];
#pragma unroll
        for (int u = 0; u < 32; u++) acc += factor[j * 32 + u] * map_w[u * 32 + h];
        vv[h] = fmaxf(acc, 0.f);
    }
    __syncthreads();
    float p = 0.f, q = a1b[h];
#pragma unroll
    for (int d = 0; d < 32; d++) {
        p += vv[d] * a1w[d * 64 + h];
        q += vv[d] * a1w[(32 + d) * 64 + h];
    }
    g_P[j * 64 + h] = p;
    g_Q[j * 64 + h] = q;
}

__global__ void k_adjmlp(const float* __restrict__ a2w, const float* __restrict__ a2b,
                         const float* __restrict__ a3w, const float* __restrict__ a3b) {
    __shared__ float Pt[128][65];
    __shared__ __align__(16) float sA2[64][32];
    __shared__ float sQ[64];
    __shared__ float sA3[64];
    __shared__ float sA2b[32];
    __shared__ float sA3b[2];
    int i = blockIdx.x, tid = threadIdx.x;
    for (int k = tid; k < 64 * 32; k += 128) sA2[k / 32][k % 32] = a2w[k];
    if (tid < 64) { sQ[tid] = g_Q[i * 64 + tid]; sA3[tid] = a3w[tid]; }
    if (tid < 32) sA2b[tid] = a2b[tid];
    if (tid < 2) sA3b[tid] = a3b[tid];
    for (int j0 = 0; j0 < NNODE; j0 += 128) {
        __syncthreads();
        int cnt = min(128, NNODE - j0);
        for (int k = tid; k < cnt * 64; k += 128)
            Pt[k / 64][k % 64] = g_P[(j0 + (k / 64)) * 64 + (k % 64)];
        __syncthreads();
        if (tid < cnt) {
            int j = j0 + tid;
            float h1[64];
#pragma unroll
            for (int h = 0; h < 64; h++) h1[h] = fmaxf(Pt[tid][h] + sQ[h], 0.f);
            float e0 = sA3b[0], e1 = sA3b[1];
#pragma unroll
            for (int c = 0; c < 32; c++) {
                float acc = sA2b[c];
#pragma unroll
                for (int h = 0; h < 64; h++) acc += h1[h] * sA2[h][c];
                acc = fmaxf(acc, 0.f);
                e0 += acc * sA3[c * 2];
                e1 += acc * sA3[c * 2 + 1];
            }
            g_eraw[i * NNODE + j] = e0;
            g_eraw[NNODE * NNODE + i * NNODE + j] = e1;
        }
    }
}

__global__ void k_softmax(float* __restrict__ outSup, int writeSup) {
    int bid = blockIdx.x;
    int e = bid / NNODE, i = bid % NNODE;
    const float* row = g_eraw + e * NNODE * NNODE + i * NNODE;
    __shared__ float red[256];
    int tid = threadIdx.x;
    float m = -1e30f;
    for (int j = tid; j < NNODE; j += 256) m = fmaxf(m, row[j]);
    red[tid] = m; __syncthreads();
    for (int s = 128; s > 0; s >>= 1) { if (tid < s) red[tid] = fmaxf(red[tid], red[tid + s]); __syncthreads(); }
    m = red[0]; __syncthreads();
    float sum = 0.f;
    for (int j = tid; j < NNODE; j += 256) sum += expf(row[j] - m);
    red[tid] = sum; __syncthreads();
    for (int s = 128; s > 0; s >>= 1) { if (tid < s) red[tid] += red[tid + s]; __syncthreads(); }
    float inv = 1.f / red[0];
    for (int j = tid; j < NNODE; j += 256) {
        float p = expf(row[j] - m) * inv;
        if (j == i) p = fmaxf(p, 1.f);
        g_Scat[i * 2000 + e * 1000 + j] = to_tf32(p);   // pre-rounded GEMM operand
        if (writeSup) outSup[(e * NNODE + i) * NNODE + j] = p;  // exact output
    }
}

// ---------------- tf32 tensor GEMM v3: cp.async 3-stage, raw-bit tf32 ----------------
// Inputs must be pre-rounded to tf32. roundC: round outputs (for A^2 feeding GEMMs).
#define TG_SSZ 4736          // floats per stage: As 128*20 + Bs 16*136
#define TG_SMEM (3 * TG_SSZ * 4)

__device__ __forceinline__ void tg_stage(float* As_s, float* Bs_s,
                                         const float* A, const float* B,
                                         int m0, int n0, int k0,
                                         int M, int N, int K, int lda, int ldb, int tid) {
#pragma unroll
    for (int i = 0; i < 2; i++) {
        int ch = tid + i * 256;
        int row = ch >> 2, kq = (ch & 3) * 4;
        int c = k0 + kq;
        int bytes = 0;
        if (m0 + row < M) {
            int rem = (K - c) * 4;
            bytes = rem > 16 ? 16 : (rem > 0 ? rem : 0);
        }
        cp16(As_s + row * 20 + kq, A + (size_t)(m0 + row) * lda + c, bytes);
    }
#pragma unroll
    for (int i = 0; i < 2; i++) {
        int ch = tid + i * 256;
        int kr = ch >> 5, nq = (ch & 31) * 4;
        int col = n0 + nq;
        int bytes = 0;
        if (k0 + kr < K) {
            int rem = (N - col) * 4;
            bytes = rem > 16 ? 16 : (rem > 0 ? rem : 0);
        }
        cp16(Bs_s + kr * 136 + nq, B + (size_t)(k0 + kr) * ldb + col, bytes);
    }
}

__global__ __launch_bounds__(256, 2)
void tgemm(const float* __restrict__ A, const float* __restrict__ B, float* __restrict__ C,
           int M, int N, int K, int lda, int ldb, int ldc,
           int sA, int sB, int sC, int roundC) {
    extern __shared__ float sdyn[];
    A += (size_t)blockIdx.z * sA;
    B += (size_t)blockIdx.z * sB;
    C += (size_t)blockIdx.z * sC;
    int tid = threadIdx.x;
    int m0 = blockIdx.y * 128, n0 = blockIdx.x * 128;
    int lane = tid & 31, wid = tid >> 5;
    int wm = wid & 1, wn = wid >> 1;
    int gid = lane >> 2, tig = lane & 3;

    float acc[4][4][4];
#pragma unroll
    for (int mi = 0; mi < 4; mi++)
#pragma unroll
        for (int ni = 0; ni < 4; ni++)
#pragma unroll
            for (int r = 0; r < 4; r++) acc[mi][ni][r] = 0.f;

    int nkt = (K + 15) / 16;

    // prologue: stages 0,1
    tg_stage(sdyn, sdyn + 2560, A, B, m0, n0, 0, M, N, K, lda, ldb, tid);
    asm volatile("cp.async.commit_group;");
    if (nkt > 1) {
        tg_stage(sdyn + TG_SSZ, sdyn + TG_SSZ + 2560, A, B, m0, n0, 16, M, N, K, lda, ldb, tid);
        asm volatile("cp.async.commit_group;");
        asm volatile("cp.async.wait_group 1;");
    } else {
        asm volatile("cp.async.wait_group 0;");
    }
    __syncthreads();

    for (int kt = 0; kt < nkt; kt++) {
        bool pf = (kt + 2 < nkt);
        if (pf) {
            int s = (kt + 2) % 3;
            tg_stage(sdyn + s * TG_SSZ, sdyn + s * TG_SSZ + 2560, A, B,
                     m0, n0, (kt + 2) * 16, M, N, K, lda, ldb, tid);
            asm volatile("cp.async.commit_group;");
        }
        const float* As_s = sdyn + (kt % 3) * TG_SSZ;
        const float* Bs_s = As_s + 2560;
#pragma unroll
        for (int ks = 0; ks < 16; ks += 8) {
            u32 af[4][4];
            u32 bf[4][2];
#pragma unroll
            for (int mi = 0; mi < 4; mi++) {
                int mb = wm * 64 + mi * 16 + gid;
                af[mi][0] = __float_as_uint(As_s[mb * 20 + ks + tig]);
                af[mi][1] = __float_as_uint(As_s[(mb + 8) * 20 + ks + tig]);
                af[mi][2] = __float_as_uint(As_s[mb * 20 + ks + tig + 4]);
                af[mi][3] = __float_as_uint(As_s[(mb + 8) * 20 + ks + tig + 4]);
            }
#pragma unroll
            for (int ni = 0; ni < 4; ni++) {
                int nb = wn * 32 + ni * 8 + gid;
                bf[ni][0] = __float_as_uint(Bs_s[(ks + tig) * 136 + nb]);
                bf[ni][1] = __float_as_uint(Bs_s[(ks + tig + 4) * 136 + nb]);
            }
#pragma unroll
            for (int mi = 0; mi < 4; mi++)
#pragma unroll
                for (int ni = 0; ni < 4; ni++)
                    mma_tf32(acc[mi][ni], af[mi], bf[ni]);
        }
        if (pf) asm volatile("cp.async.wait_group 1;");
        else    asm volatile("cp.async.wait_group 0;");
        __syncthreads();
    }

#pragma unroll
    for (int mi = 0; mi < 4; mi++) {
        int r0 = m0 + wm * 64 + mi * 16 + gid;
        int r1 = r0 + 8;
#pragma unroll
        for (int ni = 0; ni < 4; ni++) {
            int cc = n0 + wn * 32 + ni * 8 + tig * 2;
            float c0 = acc[mi][ni][0], c1 = acc[mi][ni][1];
            float c2 = acc[mi][ni][2], c3 = acc[mi][ni][3];
            if (roundC) { c0 = to_tf32(c0); c1 = to_tf32(c1); c2 = to_tf32(c2); c3 = to_tf32(c3); }
            if (r0 < M) {
                if (cc + 1 < N) *(float2*)(C + (size_t)r0 * ldc + cc) = make_float2(c0, c1);
                else if (cc < N) C[(size_t)r0 * ldc + cc] = c0;
            }
            if (r1 < M) {
                if (cc + 1 < N) *(float2*)(C + (size_t)r1 * ldc + cc) = make_float2(c2, c3);
                else if (cc < N) C[(size_t)r1 * ldc + cc] = c2;
            }
        }
    }
}

// ---------------- gated conv as tensor GEMM ----------------
__global__ __launch_bounds__(256)
void gfgemm(const float* __restrict__ X, float* __restrict__ XG, float* __restrict__ XGcat,
            int Tin, int Tout, int dd, int layer) {
    __shared__ __align__(16) float Bs[64][136];
    int tid = threadIdx.x;
    int b = blockIdx.y;
    int n0 = blockIdx.x * 128;
    int ToutN = Tout * NNODE;
    int TinN = Tin * NNODE;
    const float* Xb = X + (size_t)b * 32 * TinN;

    int lane = tid & 31, wid = tid >> 5;
    int wm = wid & 3, wn = wid >> 2;
    int gid = lane >> 2, tig = lane & 3;

    u32 af[8][4];
    {
        int r0 = wm * 16 + gid, r1 = r0 + 8;
#pragma unroll
        for (int ks = 0; ks < 8; ks++) {
            af[ks][0] = __float_as_uint(g_Wf[r0 * 64 + ks * 8 + tig]);
            af[ks][1] = __float_as_uint(g_Wf[r1 * 64 + ks * 8 + tig]);
            af[ks][2] = __float_as_uint(g_Wf[r0 * 64 + ks * 8 + tig + 4]);
            af[ks][3] = __float_as_uint(g_Wf[r1 * 64 + ks * 8 + tig + 4]);
        }
    }
    {
        int lr = tid >> 2, lq = tid & 3;
        size_t rbase = (size_t)(lr & 31) * TinN + (size_t)(lr >> 5) * (dd * NNODE);
        const float* src = Xb + rbase + n0;
#pragma unroll
        for (int i = 0; i < 8; i++) {
            int col = (lq + i * 4) * 4;
            int gcol = n0 + col;
            float4 v;
            if (gcol + 3 < ToutN) {
                v = *(const float4*)(src + col);
            } else {
                v.x = (gcol + 0 < ToutN) ? src[col + 0] : 0.f;
                v.y = (gcol + 1 < ToutN) ? src[col + 1] : 0.f;
                v.z = (gcol + 2 < ToutN) ? src[col + 2] : 0.f;
                v.w = (gcol + 3 < ToutN) ? src[col + 3] : 0.f;
            }
            float4 f = make_float4(to_tf32(v.x), to_tf32(v.y), to_tf32(v.z), to_tf32(v.w));
            *(float4*)&Bs[lr][col] = f;
        }
    }
    __syncthreads();

    float acc[8][4];
#pragma unroll
    for (int ni = 0; ni < 8; ni++)
#pragma unroll
        for (int r = 0; r < 4; r++) acc[ni][r] = 0.f;

#pragma unroll
    for (int ks = 0; ks < 8; ks++) {
#pragma unroll
        for (int ni = 0; ni < 8; ni++) {
            int nb = wn * 64 + ni * 8 + gid;
            u32 bfr[2] = { __float_as_uint(Bs[ks * 8 + tig][nb]),
                           __float_as_uint(Bs[ks * 8 + tig + 4][nb]) };
            mma_tf32(acc[ni], af[ks], bfr);
        }
    }
    __syncthreads();

#pragma unroll
    for (int ni = 0; ni < 8; ni++) {
        int cc = wn * 64 + ni * 8 + tig * 2;
        int r0 = wm * 16 + gid;
        Bs[r0][cc] = acc[ni][0]; Bs[r0][cc + 1] = acc[ni][1];
        Bs[r0 + 8][cc] = acc[ni][2]; Bs[r0 + 8][cc + 1] = acc[ni][3];
    }
    __syncthreads();

    {
        int o = tid >> 3;
        float bff = g_bf[o], bfg = g_bf[o + 32];
        size_t xgbase = (size_t)(b * 32 + o) * ToutN;
        size_t catbase = ((size_t)b * 256 + layer * 32 + o) * NNODE;
        int lastBase = (Tout - 1) * NNODE;
#pragma unroll
        for (int j = 0; j < 4; j++) {
            int col = (tid & 7) * 4 + j * 32;
            int gcol = n0 + col;
            if (gcol >= ToutN) continue;
            float vv[4];
#pragma unroll
            for (int k = 0; k < 4; k++) {
                float f = Bs[o][col + k] + bff;
                float g = Bs[o + 32][col + k] + bfg;
                vv[k] = to_tf32(tanhf(f) * (1.f / (1.f + expf(-g))));
            }
            if (gcol + 3 < ToutN) {
                *(float4*)&XG[xgbase + gcol] = make_float4(vv[0], vv[1], vv[2], vv[3]);
            } else {
#pragma unroll
                for (int k = 0; k < 4; k++)
                    if (gcol + k < ToutN) XG[xgbase + gcol + k] = vv[k];
            }
#pragma unroll
            for (int k = 0; k < 4; k++) {
                int gc = gcol + k;
                if (gc >= lastBase && gc < ToutN)
                    XGcat[catbase + (gc - lastBase)] = vv[k];
            }
        }
    }
}

// ---------------- input split + enter ----------------
__global__ void k_tmp(const float* __restrict__ inputs, const float* __restrict__ factor) {
    int t = blockIdx.x, b = blockIdx.y, tid = threadIdx.x;
    int o = tid >> 2, r = tid & 3;
    int u = o >> 1, f = o & 1;
    const float* inp = inputs + ((size_t)(b * TT + t) * NNODE) * 2 + f;
    float acc = 0.f;
    for (int n = r; n < NNODE; n += 4) acc += inp[n * 2] * factor[n * 32 + u];
    acc += __shfl_down_sync(0xffffffffu, acc, 2);
    acc += __shfl_down_sync(0xffffffffu, acc, 1);
    if (r == 0) g_tmp[(b * TT + t) * 64 + o] = acc;
}

__global__ void k_enter(const float* __restrict__ inputs, const float* __restrict__ factor,
                        const float* __restrict__ ew, const float* __restrict__ eb,
                        float* __restrict__ X0) {
    __shared__ float sw[128], sb[32], stmp[64];
    int b = blockIdx.z, tp = blockIdx.y;
    int tid = threadIdx.x;
    if (tid < 128) sw[tid] = ew[tid];
    if (tid < 32) sb[tid] = eb[tid];
    if (tp > 0 && tid < 64) stmp[tid] = g_tmp[(b * TT + (tp - 1)) * 64 + tid];
    __syncthreads();
    int n = blockIdx.x * 128 + tid;
    if (n >= NNODE) return;
    if (tp == 0) {
#pragma unroll
        for (int o = 0; o < 32; o++)
            X0[((size_t)(b * 32 + o) * RFh + 0) * NNODE + n] = sb[o];
    } else {
        int t = tp - 1;
        float s0 = 0.f, s1 = 0.f;
#pragma unroll
        for (int u = 0; u < 32; u++) {
            float fv = factor[n * 32 + u];
            s0 += fv * stmp[u * 2];
            s1 += fv * stmp[u * 2 + 1];
        }
        float i0 = inputs[((size_t)(b * TT + t) * NNODE + n) * 2 + 0];
        float i1 = inputs[((size_t)(b * TT + t) * NNODE + n) * 2 + 1];
        float r0 = i0 - s0, r1 = i1 - s1;
#pragma unroll
        for (int o = 0; o < 32; o++) {
            float v = sb[o] + sw[o * 4] * s0 + sw[o * 4 + 1] * s1 + sw[o * 4 + 2] * r0 + sw[o * 4 + 3] * r1;
            X0[((size_t)(b * 32 + o) * RFh + tp) * NNODE + n] = v;
        }
    }
}

// ---------------- gc 1x1 + residual(BN-fused) + BN partial stats ----------------
__global__ void k_gcres(const float* __restrict__ XG, const float* __restrict__ Y,
                        const float* __restrict__ Xc, float* __restrict__ Xn,
                        const float* __restrict__ gcw, const float* __restrict__ gcb,
                        const float* __restrict__ abPrev,
                        float* __restrict__ part, int Tin, int Tout, int dd) {
    __shared__ __align__(16) float swg[160 * 32];
    __shared__ float sgb[32], sA[32], sB[32];
    __shared__ float sredS[4][32];
    __shared__ float sredQ[4][32];
    int tid = threadIdx.x;
    for (int idx = tid; idx < 160 * 32; idx += 128) {
        int c = idx / 32, o = idx % 32;
        swg[idx] = gcw[o * 160 + c];
    }
    if (tid < 32) { sgb[tid] = gcb[tid]; sA[tid] = abPrev[tid]; sB[tid] = abPrev[32 + tid]; }
    __syncthreads();
    int n0 = blockIdx.x * 256 + tid * 2;
    int t = blockIdx.y, b = blockIdx.z;
    bool active = (n0 < NNODE);
    ull acc0[16], acc1[16];
#pragma unroll
    for (int q = 0; q < 16; q++) {
        ull bias = active ? pack2(sgb[q * 2], sgb[q * 2 + 1]) : pack2(0.f, 0.f);
        acc0[q] = bias;
        acc1[q] = bias;
    }
    for (int c = 0; c < 32; c++) {
        size_t base = ((size_t)(b * 32 + c) * Tout + t) * NNODE;
        float2 v = active ? *(const float2*)&XG[base + n0] : make_float2(0.f, 0.f);
        ull vd0 = pack2(v.x, v.x), vd1 = pack2(v.y, v.y);
        const ulonglong2* w2 = (const ulonglong2*)&swg[c * 32];
#pragma unroll
        for (int q = 0; q < 8; q++) {
            ulonglong2 w = w2[q];
            acc0[q * 2 + 0] = fma2(vd0, w.x, acc0[q * 2 + 0]);
            acc0[q * 2 + 1] = fma2(vd0, w.y, acc0[q * 2 + 1]);
            acc1[q * 2 + 0] = fma2(vd1, w.x, acc1[q * 2 + 0]);
            acc1[q * 2 + 1] = fma2(vd1, w.y, acc1[q * 2 + 1]);
        }
    }
    for (int e = 0; e < 4; e++) {
        for (int c = 0; c < 32; c++) {
            size_t m = ((size_t)(b * 32 + c) * Tout + t) * 2000 + e * 500;
            float2 v = active ? *(const float2*)&Y[m + n0] : make_float2(0.f, 0.f);
            ull vd0 = pack2(v.x, v.x), vd1 = pack2(v.y, v.y);
            const ulonglong2* w2 = (const ulonglong2*)&swg[(32 + e * 32 + c) * 32];
#pragma unroll
            for (int q = 0; q < 8; q++) {
                ulonglong2 w = w2[q];
                acc0[q * 2 + 0] = fma2(vd0, w.x, acc0[q * 2 + 0]);
                acc0[q * 2 + 1] = fma2(vd0, w.y, acc0[q * 2 + 1]);
                acc1[q * 2 + 0] = fma2(vd1, w.x, acc1[q * 2 + 0]);
                acc1[q * 2 + 1] = fma2(vd1, w.y, acc1[q * 2 + 1]);
            }
        }
    }
    float f0[32], f1[32];
#pragma unroll
    for (int q = 0; q < 16; q++) {
        unpack2(acc0[q], f0[q * 2], f0[q * 2 + 1]);
        unpack2(acc1[q], f1[q * 2], f1[q * 2 + 1]);
    }
    if (active) {
#pragma unroll
        for (int o = 0; o < 32; o++) {
            size_t rbase = ((size_t)(b * 32 + o) * Tin + t + dd) * NNODE;
            size_t wbase = ((size_t)(b * 32 + o) * Tout + t) * NNODE;
            float2 rv = *(const float2*)&Xc[rbase + n0];
            f0[o] += rv.x * sA[o] + sB[o];
            f1[o] += rv.y * sA[o] + sB[o];
            *(float2*)&Xn[wbase + n0] = make_float2(f0[o], f1[o]);
        }
    }
    int lane = tid & 31, warp = tid >> 5;
#pragma unroll
    for (int o = 0; o < 32; o++) {
        float s = active ? (f0[o] + f1[o]) : 0.f;
        float q = active ? (f0[o] * f0[o] + f1[o] * f1[o]) : 0.f;
#pragma unroll
        for (int off = 16; off; off >>= 1) {
            s += __shfl_down_sync(0xffffffffu, s, off);
            q += __shfl_down_sync(0xffffffffu, q, off);
        }
        if (lane == 0) { sredS[warp][o] = s; sredQ[warp][o] = q; }
    }
    __syncthreads();
    if (tid < 64) {
        int o = tid & 31;
        bool isq = (tid >= 32);
        float v = 0.f;
#pragma unroll
        for (int w = 0; w < 4; w++) v += (isq ? sredQ[w][o] : sredS[w][o]);
        size_t bidx = (size_t)(blockIdx.z * gridDim.y + blockIdx.y) * gridDim.x + blockIdx.x;
        part[bidx * 64 + tid] = v;
    }
}

// ---------------- output head ----------------
__global__ void k_transpose_skip(const float* __restrict__ skip, const float* __restrict__ skp_b,
                                 float* __restrict__ Srelu) {
    __shared__ float tile[32][33];
    int b = blockIdx.z;
    int n0 = blockIdx.x * 32, c0 = blockIdx.y * 32;
    int n = n0 + threadIdx.x, c = c0 + threadIdx.y;
    tile[threadIdx.y][threadIdx.x] = (n < NNODE) ? skip[(size_t)(b * NSKIPC + c) * NNODE + n] : 0.f;
    __syncthreads();
    int n2 = n0 + threadIdx.y, c2 = c0 + threadIdx.x;
    float bsum = 0.f;
#pragma unroll
    for (int l = 0; l < LL; l++) bsum += skp_b[l * 256 + c2];
    if (n2 < NNODE)
        Srelu[(size_t)(b * NNODE + n2) * NSKIPC + c2] =
            to_tf32(fmaxf(tile[threadIdx.x][threadIdx.y] + bsum, 0.f));
}

__global__ void k_headfinal(const float* __restrict__ H, const float* __restrict__ o1b,
                            const float* __restrict__ o2w, const float* __restrict__ o2b,
                            float* __restrict__ out) {
    int warp = threadIdx.x >> 5, lane = threadIdx.x & 31;
    int row = blockIdx.x * 4 + warp;
    if (row >= BB * NNODE) return;
    int b = row / NNODE, n = row % NNODE;
    const float* Hr = H + (size_t)row * NENDC;
    float h[16];
#pragma unroll
    for (int i = 0; i < 16; i++)
        h[i] = fmaxf(Hr[lane + i * 32] + o1b[lane + i * 32], 0.f);
#pragma unroll
    for (int p = 0; p < NPREDC; p++) {
        float acc = 0.f;
#pragma unroll
        for (int i = 0; i < 16; i++) acc += o2w[p * NENDC + lane + i * 32] * h[i];
#pragma unroll
        for (int off = 16; off; off >>= 1) acc += __shfl_down_sync(0xffffffffu, acc, off);
        if (lane == 0) out[(size_t)(b * NPREDC + p) * NNODE + n] = acc + o2b[p];
    }
}

// ---------------- host launcher ----------------
extern "C" void kernel_launch(void* const* d_in, const int* in_sizes, int n_in,
                              void* d_out, int out_size) {
    const float* inputs = (const float*)d_in[0];
    const float* factor = (const float*)d_in[1];
    const float* map_w  = (const float*)d_in[2];
    const float* map_b  = (const float*)d_in[3];
    const float* a1w    = (const float*)d_in[4];
    const float* a1b    = (const float*)d_in[5];
    const float* a2w    = (const float*)d_in[6];
    const float* a2b    = (const float*)d_in[7];
    const float* a3w    = (const float*)d_in[8];
    const float* a3b    = (const float*)d_in[9];
    const float* enter_w = (const float*)d_in[10];
    const float* enter_b = (const float*)d_in[11];
    const float* filt_w = (const float*)d_in[12];
    const float* filt_b = (const float*)d_in[13];
    const float* gate_w = (const float*)d_in[14];
    const float* gate_b = (const float*)d_in[15];
    const float* skp_w  = (const float*)d_in[16];
    const float* skp_b  = (const float*)d_in[17];
    const float* gc_w   = (const float*)d_in[18];
    const float* gc_b   = (const float*)d_in[19];
    const float* bn_g   = (const float*)d_in[20];
    const float* bn_b   = (const float*)d_in[21];
    const float* o1w    = (const float*)d_in[22];
    const float* o1b    = (const float*)d_in[23];
    const float* o2w    = (const float*)d_in[24];
    const float* o2b    = (const float*)d_in[25];

    cudaFuncSetAttribute(tgemm, cudaFuncAttributeMaxDynamicSharedMemorySize, TG_SMEM);

    float *pScat, *pY, *pX0, *pX1, *pXG, *pXGcat, *pWcat, *pSkip, *pSrelu, *pO1T, *pPart, *pAB;
    cudaGetSymbolAddress((void**)&pScat, g_Scat);
    cudaGetSymbolAddress((void**)&pY, g_Y);
    cudaGetSymbolAddress((void**)&pX0, g_X0);
    cudaGetSymbolAddress((void**)&pX1, g_X1);
    cudaGetSymbolAddress((void**)&pXG, g_XG);
    cudaGetSymbolAddress((void**)&pXGcat, g_XGcat);
    cudaGetSymbolAddress((void**)&pWcat, g_Wcat);
    cudaGetSymbolAddress((void**)&pSkip, g_skip);
    cudaGetSymbolAddress((void**)&pSrelu, g_Srelu);
    cudaGetSymbolAddress((void**)&pO1T, g_o1wT);
    cudaGetSymbolAddress((void**)&pPart, g_part);
    cudaGetSymbolAddress((void**)&pAB, g_bnab);

    float* out = (float*)d_out;
    const int ySize = BB * NPREDC * NNODE;
    const int supSize = 2 * NNODE * NNODE;
    int writeSup = (out_size >= ySize + supSize) ? 1 : 0;
    float* outSup = out + ySize;

    static const int Tin[LL] = {13, 12, 10, 9, 7, 6, 4, 3};
    static const int Dd[LL]  = {1, 2, 1, 2, 1, 2, 1, 2};
    static const int To[LL]  = {12, 10, 9, 7, 6, 4, 3, 1};

    k_fusew<<<1, 64>>>(filt_w, filt_b, gate_w, gate_b);
    k_tmp<<<dim3(TT, BB), 256>>>(inputs, factor);
    k_enter<<<dim3(4, RFh, BB), 128>>>(inputs, factor, enter_w, enter_b, pX0);
    gfgemm<<<dim3((To[0] * NNODE + 127) / 128, BB), 256>>>(pX0, pXG, pXGcat,
                                                           Tin[0], To[0], Dd[0], 0);
    k_prep<<<512, 256>>>(skp_w, o1w);
    k_pq<<<NNODE, 64>>>(factor, map_w, map_b, a1w, a1b);
    k_adjmlp<<<NNODE, 128>>>(a2w, a2b, a3w, a3b);
    k_softmax<<<2 * NNODE, 256>>>(outSup, writeSup);
    tgemm<<<dim3(4, 4, 2), 256, TG_SMEM>>>(pScat, pScat, pScat + 500, 500, 500, 500,
                                           2000, 2000, 2000, 1000, 1000, 1000, 1);

    float* Xc = pX0;
    float* Xn = pX1;
    for (int i = 0; i < LL - 1; i++) {
        int slotPrev = (i == 0) ? LL : (i - 1);
        int M = BB * 32 * To[i];
        tgemm<<<dim3(16, M / 128), 256, TG_SMEM>>>(pXG, pScat, pY, M, 2000, 500,
                                                   500, 2000, 2000, 0, 0, 0, 0);
        k_gcres<<<dim3(2, To[i], BB), 128>>>(pXG, pY, Xc, Xn,
            gc_w + i * 5120, gc_b + i * 32, pAB + slotPrev * 64, pPart,
            Tin[i], To[i], Dd[i]);
        int nblk = 2 * To[i] * BB;
        int j = i + 1;
        k_statsfusew<<<1, 1024>>>(pPart, nblk, (float)(BB * To[i] * NNODE),
                                  bn_g + i * 32, bn_b + i * 32, pAB + i * 64,
                                  filt_w + j * 2048, filt_b + j * 32,
                                  gate_w + j * 2048, gate_b + j * 32);
        gfgemm<<<dim3((To[j] * NNODE + 127) / 128, BB), 256>>>(Xn, pXG, pXGcat,
                                                               Tin[j], To[j], Dd[j], j);
        float* t = Xc; Xc = Xn; Xn = t;
    }
    // skip = Wcat @ XGcat  (batched over b)
    tgemm<<<dim3(4, 2, BB), 256, TG_SMEM>>>(pWcat, pXGcat, pSkip, 256, NNODE, 256,
                                            256, NNODE, NNODE, 0, 256 * NNODE, 256 * NNODE, 0);
    // output head
    k_transpose_skip<<<dim3(16, 8, BB), dim3(32, 32)>>>(pSkip, skp_b, pSrelu);
    tgemm<<<dim3(4, 125), 256, TG_SMEM>>>(pSrelu, pO1T, pY, BB * NNODE, NENDC, NSKIPC,
                                          NSKIPC, NENDC, NENDC, 0, 0, 0, 0);
    k_headfinal<<<(BB * NNODE + 3) / 4, 128>>>(pY, o1b, o2w, o2b, out);
}

// round 13
// speedup vs baseline: 1.4219x; 1.1271x over previous
#include <cuda_runtime.h>
#include <math.h>
#include <stdint.h>

// ---------------- static problem config ----------------
#define BB 32
#define TT 12
#define NNODE 500
#define NSKIPC 256
#define NENDC 512
#define NPREDC 12
#define LL 8
#define RFh 13
#define BN_EPS 1e-5f

typedef unsigned long long ull;
typedef unsigned int u32;

__device__ __forceinline__ float to_tf32(float x) {
    u32 r; asm("cvt.rna.tf32.f32 %0, %1;" : "=r"(r) : "f"(x));
    return __uint_as_float(r);
}
__device__ __forceinline__ void mma_tf32(float* c, const u32* a, const u32* b) {
    asm("mma.sync.aligned.m16n8k8.row.col.f32.tf32.tf32.f32 "
        "{%0,%1,%2,%3},{%4,%5,%6,%7},{%8,%9},{%0,%1,%2,%3};"
        : "+f"(c[0]), "+f"(c[1]), "+f"(c[2]), "+f"(c[3])
        : "r"(a[0]), "r"(a[1]), "r"(a[2]), "r"(a[3]), "r"(b[0]), "r"(b[1]));
}
__device__ __forceinline__ void cp16(float* dst, const float* src, int bytes) {
    u32 d = (u32)__cvta_generic_to_shared(dst);
    asm volatile("cp.async.cg.shared.global [%0], [%1], 16, %2;\n"
                 :: "r"(d), "l"(src), "r"(bytes));
}

// ---------------- device scratch ----------------
__device__ float g_P[NNODE * 64];
__device__ float g_Q[NNODE * 64];
__device__ float g_eraw[2 * NNODE * NNODE];
__device__ float g_Scat[NNODE * 2000];            // tf32-rounded supports [A0|A0^2|A1|A1^2]
__device__ float g_tmp[BB * TT * 32 * 2];
__device__ float g_X0[BB * 32 * RFh * NNODE];
__device__ float g_X1[BB * 32 * RFh * NNODE];
__device__ float g_XG[BB * 32 * 12 * NNODE];      // tf32-rounded gated outputs
__device__ float g_Y[12288 * 2000];               // tf32-rounded diffusion outputs
__device__ float g_XGcat[BB * 256 * NNODE];       // tf32-rounded last-t gated slices
__device__ float g_Wcat[256 * 256];               // tf32-rounded
__device__ float g_skip[BB * NSKIPC * NNODE];
__device__ float g_Srelu[BB * NNODE * NSKIPC];    // tf32-rounded
__device__ float g_o1wT[NSKIPC * NENDC];          // tf32-rounded
__device__ float g_part[1536 * 64];
__device__ float g_bnab[(LL + 1) * 64];
__device__ float g_Wf[64 * 64];                   // tf32-rounded fused gated-conv weights
__device__ float g_bf[64];
__device__ float g_Wgc[7 * 32 * 160];             // tf32 gc weights [layer][o][k]; k<128 -> Y rows, k>=128 -> XG rows

// ---------------- fused one-time prep ----------------
__global__ void k_prep(const float* __restrict__ skp_w, const float* __restrict__ o1w,
                       const float* __restrict__ gcw) {
    int idx = blockIdx.x * 256 + threadIdx.x;
    if (idx < 64) g_bnab[LL * 64 + idx] = (idx < 32) ? 1.f : 0.f;
    if (idx < 65536) {
        int o = idx >> 8, r = idx & 255, l = r >> 5, c = r & 31;
        g_Wcat[idx] = to_tf32(skp_w[l * 8192 + o * 32 + c]);
    }
    if (idx < 131072) {
        int h = idx / NSKIPC, c = idx % NSKIPC;
        g_o1wT[c * NENDC + h] = to_tf32(o1w[idx]);
    }
    if (idx < 7 * 32 * 160) {
        int l = idx / 5120, rem = idx % 5120, o = rem / 160, k = rem % 160;
        // concat layout: weight col 0..31 = x block, 32..159 = 4 diffusion blocks
        float w = (k < 128) ? gcw[l * 5120 + o * 160 + 32 + k]
                            : gcw[l * 5120 + o * 160 + (k - 128)];
        g_Wgc[idx] = to_tf32(w);
    }
}

// ---------------- layer-0 fused gated-conv weights (identity BN) ----------------
__global__ void k_fusew(const float* __restrict__ fw, const float* __restrict__ fb,
                        const float* __restrict__ gw, const float* __restrict__ gb) {
    int o = threadIdx.x;
    const float* w = (o < 32) ? fw : gw;
    int oo = o & 31;
    float bias = (o < 32) ? fb[oo] : gb[oo];
#pragma unroll
    for (int c = 0; c < 32; c++) {
        g_Wf[o * 64 + c] = to_tf32(w[oo * 64 + c * 2 + 0]);
        g_Wf[o * 64 + 32 + c] = to_tf32(w[oo * 64 + c * 2 + 1]);
    }
    g_bf[o] = bias;
}

// ---------------- BN stats reduce + next-layer weight fusion (one block) ----------------
__global__ void k_statsfusew(const float* __restrict__ part, int nblk, float cnt,
                             const float* __restrict__ g, const float* __restrict__ bta,
                             float* __restrict__ ab,
                             const float* __restrict__ fw, const float* __restrict__ fb,
                             const float* __restrict__ gw, const float* __restrict__ gb) {
    __shared__ float sab[64];
    int tid = threadIdx.x;
    int w = tid >> 5, lane = tid & 31;
    double s = 0.0, q = 0.0;
    for (int i = lane; i < nblk; i += 32) {
        s += (double)part[(size_t)i * 64 + w];
        q += (double)part[(size_t)i * 64 + 32 + w];
    }
#pragma unroll
    for (int off = 16; off; off >>= 1) {
        s += __shfl_down_sync(0xffffffffu, s, off);
        q += __shfl_down_sync(0xffffffffu, q, off);
    }
    if (lane == 0) {
        float mean = (float)(s / cnt);
        float var = (float)(q / cnt) - mean * mean;
        float a = g[w] * rsqrtf(var + BN_EPS);
        float sh = bta[w] - mean * a;
        sab[w] = a; sab[32 + w] = sh;
        ab[w] = a; ab[32 + w] = sh;
    }
    __syncthreads();
    if (tid < 64) {
        int o = tid;
        const float* wsrc = (o < 32) ? fw : gw;
        int oo = o & 31;
        float bias = (o < 32) ? fb[oo] : gb[oo];
        float bsum = 0.f;
#pragma unroll
        for (int c = 0; c < 32; c++) {
            float a = sab[c], bb = sab[32 + c];
            float w0 = wsrc[oo * 64 + c * 2 + 0];
            float w1 = wsrc[oo * 64 + c * 2 + 1];
            g_Wf[o * 64 + c] = to_tf32(w0 * a);
            g_Wf[o * 64 + 32 + c] = to_tf32(w1 * a);
            bsum += (w0 + w1) * bb;
        }
        g_bf[o] = bias + bsum;
    }
}

// ---------------- adjacency ----------------
__global__ void k_pq(const float* __restrict__ factor, const float* __restrict__ map_w,
                     const float* __restrict__ map_b,
                     const float* __restrict__ a1w, const float* __restrict__ a1b) {
    __shared__ float vv[32];
    int j = blockIdx.x, h = threadIdx.x;
    if (h < 32) {
        float acc = map_b[h];
#pragma unroll
        for (int u = 0; u < 32; u++) acc += factor[j * 32 + u] * map_w[u * 32 + h];
        vv[h] = fmaxf(acc, 0.f);
    }
    __syncthreads();
    float p = 0.f, q = a1b[h];
#pragma unroll
    for (int d = 0; d < 32; d++) {
        p += vv[d] * a1w[d * 64 + h];
        q += vv[d] * a1w[(32 + d) * 64 + h];
    }
    g_P[j * 64 + h] = p;
    g_Q[j * 64 + h] = q;
}

__global__ void k_adjmlp(const float* __restrict__ a2w, const float* __restrict__ a2b,
                         const float* __restrict__ a3w, const float* __restrict__ a3b) {
    __shared__ float Pt[128][65];
    __shared__ __align__(16) float sA2[64][32];
    __shared__ float sQ[64];
    __shared__ float sA3[64];
    __shared__ float sA2b[32];
    __shared__ float sA3b[2];
    int i = blockIdx.x, tid = threadIdx.x;
    for (int k = tid; k < 64 * 32; k += 128) sA2[k / 32][k % 32] = a2w[k];
    if (tid < 64) { sQ[tid] = g_Q[i * 64 + tid]; sA3[tid] = a3w[tid]; }
    if (tid < 32) sA2b[tid] = a2b[tid];
    if (tid < 2) sA3b[tid] = a3b[tid];
    for (int j0 = 0; j0 < NNODE; j0 += 128) {
        __syncthreads();
        int cnt = min(128, NNODE - j0);
        for (int k = tid; k < cnt * 64; k += 128)
            Pt[k / 64][k % 64] = g_P[(j0 + (k / 64)) * 64 + (k % 64)];
        __syncthreads();
        if (tid < cnt) {
            int j = j0 + tid;
            float h1[64];
#pragma unroll
            for (int h = 0; h < 64; h++) h1[h] = fmaxf(Pt[tid][h] + sQ[h], 0.f);
            float e0 = sA3b[0], e1 = sA3b[1];
#pragma unroll
            for (int c = 0; c < 32; c++) {
                float acc = sA2b[c];
#pragma unroll
                for (int h = 0; h < 64; h++) acc += h1[h] * sA2[h][c];
                acc = fmaxf(acc, 0.f);
                e0 += acc * sA3[c * 2];
                e1 += acc * sA3[c * 2 + 1];
            }
            g_eraw[i * NNODE + j] = e0;
            g_eraw[NNODE * NNODE + i * NNODE + j] = e1;
        }
    }
}

__global__ void k_softmax(float* __restrict__ outSup, int writeSup) {
    int bid = blockIdx.x;
    int e = bid / NNODE, i = bid % NNODE;
    const float* row = g_eraw + e * NNODE * NNODE + i * NNODE;
    __shared__ float red[256];
    int tid = threadIdx.x;
    float m = -1e30f;
    for (int j = tid; j < NNODE; j += 256) m = fmaxf(m, row[j]);
    red[tid] = m; __syncthreads();
    for (int s = 128; s > 0; s >>= 1) { if (tid < s) red[tid] = fmaxf(red[tid], red[tid + s]); __syncthreads(); }
    m = red[0]; __syncthreads();
    float sum = 0.f;
    for (int j = tid; j < NNODE; j += 256) sum += expf(row[j] - m);
    red[tid] = sum; __syncthreads();
    for (int s = 128; s > 0; s >>= 1) { if (tid < s) red[tid] += red[tid + s]; __syncthreads(); }
    float inv = 1.f / red[0];
    for (int j = tid; j < NNODE; j += 256) {
        float p = expf(row[j] - m) * inv;
        if (j == i) p = fmaxf(p, 1.f);
        g_Scat[i * 2000 + e * 1000 + j] = to_tf32(p);
        if (writeSup) outSup[(e * NNODE + i) * NNODE + j] = p;
    }
}

// ---------------- tf32 tensor GEMM: cp.async 3-stage, raw-bit tf32 ----------------
#define TG_SSZ 4736
#define TG_SMEM (3 * TG_SSZ * 4)

__device__ __forceinline__ void tg_stage(float* As_s, float* Bs_s,
                                         const float* A, const float* B,
                                         int m0, int n0, int k0,
                                         int M, int N, int K, int lda, int ldb, int tid) {
#pragma unroll
    for (int i = 0; i < 2; i++) {
        int ch = tid + i * 256;
        int row = ch >> 2, kq = (ch & 3) * 4;
        int c = k0 + kq;
        int bytes = 0;
        if (m0 + row < M) {
            int rem = (K - c) * 4;
            bytes = rem > 16 ? 16 : (rem > 0 ? rem : 0);
        }
        cp16(As_s + row * 20 + kq, A + (size_t)(m0 + row) * lda + c, bytes);
    }
#pragma unroll
    for (int i = 0; i < 2; i++) {
        int ch = tid + i * 256;
        int kr = ch >> 5, nq = (ch & 31) * 4;
        int col = n0 + nq;
        int bytes = 0;
        if (k0 + kr < K) {
            int rem = (N - col) * 4;
            bytes = rem > 16 ? 16 : (rem > 0 ? rem : 0);
        }
        cp16(Bs_s + kr * 136 + nq, B + (size_t)(k0 + kr) * ldb + col, bytes);
    }
}

__global__ __launch_bounds__(256, 2)
void tgemm(const float* __restrict__ A, const float* __restrict__ B, float* __restrict__ C,
           int M, int N, int K, int lda, int ldb, int ldc,
           int sA, int sB, int sC, int roundC) {
    extern __shared__ float sdyn[];
    A += (size_t)blockIdx.z * sA;
    B += (size_t)blockIdx.z * sB;
    C += (size_t)blockIdx.z * sC;
    int tid = threadIdx.x;
    int m0 = blockIdx.y * 128, n0 = blockIdx.x * 128;
    int lane = tid & 31, wid = tid >> 5;
    int wm = wid & 1, wn = wid >> 1;
    int gid = lane >> 2, tig = lane & 3;

    float acc[4][4][4];
#pragma unroll
    for (int mi = 0; mi < 4; mi++)
#pragma unroll
        for (int ni = 0; ni < 4; ni++)
#pragma unroll
            for (int r = 0; r < 4; r++) acc[mi][ni][r] = 0.f;

    int nkt = (K + 15) / 16;

    tg_stage(sdyn, sdyn + 2560, A, B, m0, n0, 0, M, N, K, lda, ldb, tid);
    asm volatile("cp.async.commit_group;");
    if (nkt > 1) {
        tg_stage(sdyn + TG_SSZ, sdyn + TG_SSZ + 2560, A, B, m0, n0, 16, M, N, K, lda, ldb, tid);
        asm volatile("cp.async.commit_group;");
        asm volatile("cp.async.wait_group 1;");
    } else {
        asm volatile("cp.async.wait_group 0;");
    }
    __syncthreads();

    for (int kt = 0; kt < nkt; kt++) {
        bool pf = (kt + 2 < nkt);
        if (pf) {
            int s = (kt + 2) % 3;
            tg_stage(sdyn + s * TG_SSZ, sdyn + s * TG_SSZ + 2560, A, B,
                     m0, n0, (kt + 2) * 16, M, N, K, lda, ldb, tid);
            asm volatile("cp.async.commit_group;");
        }
        const float* As_s = sdyn + (kt % 3) * TG_SSZ;
        const float* Bs_s = As_s + 2560;
#pragma unroll
        for (int ks = 0; ks < 16; ks += 8) {
            u32 af[4][4];
            u32 bf[4][2];
#pragma unroll
            for (int mi = 0; mi < 4; mi++) {
                int mb = wm * 64 + mi * 16 + gid;
                af[mi][0] = __float_as_uint(As_s[mb * 20 + ks + tig]);
                af[mi][1] = __float_as_uint(As_s[(mb + 8) * 20 + ks + tig]);
                af[mi][2] = __float_as_uint(As_s[mb * 20 + ks + tig + 4]);
                af[mi][3] = __float_as_uint(As_s[(mb + 8) * 20 + ks + tig + 4]);
            }
#pragma unroll
            for (int ni = 0; ni < 4; ni++) {
                int nb = wn * 32 + ni * 8 + gid;
                bf[ni][0] = __float_as_uint(Bs_s[(ks + tig) * 136 + nb]);
                bf[ni][1] = __float_as_uint(Bs_s[(ks + tig + 4) * 136 + nb]);
            }
#pragma unroll
            for (int mi = 0; mi < 4; mi++)
#pragma unroll
                for (int ni = 0; ni < 4; ni++)
                    mma_tf32(acc[mi][ni], af[mi], bf[ni]);
        }
        if (pf) asm volatile("cp.async.wait_group 1;");
        else    asm volatile("cp.async.wait_group 0;");
        __syncthreads();
    }

#pragma unroll
    for (int mi = 0; mi < 4; mi++) {
        int r0 = m0 + wm * 64 + mi * 16 + gid;
        int r1 = r0 + 8;
#pragma unroll
        for (int ni = 0; ni < 4; ni++) {
            int cc = n0 + wn * 32 + ni * 8 + tig * 2;
            float c0 = acc[mi][ni][0], c1 = acc[mi][ni][1];
            float c2 = acc[mi][ni][2], c3 = acc[mi][ni][3];
            if (roundC) { c0 = to_tf32(c0); c1 = to_tf32(c1); c2 = to_tf32(c2); c3 = to_tf32(c3); }
            if (r0 < M) {
                if (cc + 1 < N) *(float2*)(C + (size_t)r0 * ldc + cc) = make_float2(c0, c1);
                else if (cc < N) C[(size_t)r0 * ldc + cc] = c0;
            }
            if (r1 < M) {
                if (cc + 1 < N) *(float2*)(C + (size_t)r1 * ldc + cc) = make_float2(c2, c3);
                else if (cc < N) C[(size_t)r1 * ldc + cc] = c2;
            }
        }
    }
}

// ---------------- gated conv as tensor GEMM ----------------
__global__ __launch_bounds__(256)
void gfgemm(const float* __restrict__ X, float* __restrict__ XG, float* __restrict__ XGcat,
            int Tin, int Tout, int dd, int layer) {
    __shared__ __align__(16) float Bs[64][136];
    int tid = threadIdx.x;
    int b = blockIdx.y;
    int n0 = blockIdx.x * 128;
    int ToutN = Tout * NNODE;
    int TinN = Tin * NNODE;
    const float* Xb = X + (size_t)b * 32 * TinN;

    int lane = tid & 31, wid = tid >> 5;
    int wm = wid & 3, wn = wid >> 2;
    int gid = lane >> 2, tig = lane & 3;

    u32 af[8][4];
    {
        int r0 = wm * 16 + gid, r1 = r0 + 8;
#pragma unroll
        for (int ks = 0; ks < 8; ks++) {
            af[ks][0] = __float_as_uint(g_Wf[r0 * 64 + ks * 8 + tig]);
            af[ks][1] = __float_as_uint(g_Wf[r1 * 64 + ks * 8 + tig]);
            af[ks][2] = __float_as_uint(g_Wf[r0 * 64 + ks * 8 + tig + 4]);
            af[ks][3] = __float_as_uint(g_Wf[r1 * 64 + ks * 8 + tig + 4]);
        }
    }
    {
        int lr = tid >> 2, lq = tid & 3;
        size_t rbase = (size_t)(lr & 31) * TinN + (size_t)(lr >> 5) * (dd * NNODE);
        const float* src = Xb + rbase + n0;
#pragma unroll
        for (int i = 0; i < 8; i++) {
            int col = (lq + i * 4) * 4;
            int gcol = n0 + col;
            float4 v;
            if (gcol + 3 < ToutN) {
                v = *(const float4*)(src + col);
            } else {
                v.x = (gcol + 0 < ToutN) ? src[col + 0] : 0.f;
                v.y = (gcol + 1 < ToutN) ? src[col + 1] : 0.f;
                v.z = (gcol + 2 < ToutN) ? src[col + 2] : 0.f;
                v.w = (gcol + 3 < ToutN) ? src[col + 3] : 0.f;
            }
            float4 f = make_float4(to_tf32(v.x), to_tf32(v.y), to_tf32(v.z), to_tf32(v.w));
            *(float4*)&Bs[lr][col] = f;
        }
    }
    __syncthreads();

    float acc[8][4];
#pragma unroll
    for (int ni = 0; ni < 8; ni++)
#pragma unroll
        for (int r = 0; r < 4; r++) acc[ni][r] = 0.f;

#pragma unroll
    for (int ks = 0; ks < 8; ks++) {
#pragma unroll
        for (int ni = 0; ni < 8; ni++) {
            int nb = wn * 64 + ni * 8 + gid;
            u32 bfr[2] = { __float_as_uint(Bs[ks * 8 + tig][nb]),
                           __float_as_uint(Bs[ks * 8 + tig + 4][nb]) };
            mma_tf32(acc[ni], af[ks], bfr);
        }
    }
    __syncthreads();

#pragma unroll
    for (int ni = 0; ni < 8; ni++) {
        int cc = wn * 64 + ni * 8 + tig * 2;
        int r0 = wm * 16 + gid;
        Bs[r0][cc] = acc[ni][0]; Bs[r0][cc + 1] = acc[ni][1];
        Bs[r0 + 8][cc] = acc[ni][2]; Bs[r0 + 8][cc + 1] = acc[ni][3];
    }
    __syncthreads();

    {
        int o = tid >> 3;
        float bff = g_bf[o], bfg = g_bf[o + 32];
        size_t xgbase = (size_t)(b * 32 + o) * ToutN;
        size_t catbase = ((size_t)b * 256 + layer * 32 + o) * NNODE;
        int lastBase = (Tout - 1) * NNODE;
#pragma unroll
        for (int j = 0; j < 4; j++) {
            int col = (tid & 7) * 4 + j * 32;
            int gcol = n0 + col;
            if (gcol >= ToutN) continue;
            float vv[4];
#pragma unroll
            for (int k = 0; k < 4; k++) {
                float f = Bs[o][col + k] + bff;
                float g = Bs[o + 32][col + k] + bfg;
                vv[k] = to_tf32(tanhf(f) * (1.f / (1.f + expf(-g))));
            }
            if (gcol + 3 < ToutN) {
                *(float4*)&XG[xgbase + gcol] = make_float4(vv[0], vv[1], vv[2], vv[3]);
            } else {
#pragma unroll
                for (int k = 0; k < 4; k++)
                    if (gcol + k < ToutN) XG[xgbase + gcol + k] = vv[k];
            }
#pragma unroll
            for (int k = 0; k < 4; k++) {
                int gc = gcol + k;
                if (gc >= lastBase && gc < ToutN)
                    XGcat[catbase + (gc - lastBase)] = vv[k];
            }
        }
    }
}

// ---------------- gc 1x1 conv as tensor GEMM + residual + BN stats ----------------
// per CTA: (b,t), 128-col n-block. C[32,128] = Wgc[32,160] @ B[160,128].
// B rows k<128: Y[(b*32+(k&31))*Tout+t][(k>>5)*500 + n]; k>=128: XG[(b*32+k-128)*Tout+t][n]
__global__ __launch_bounds__(256)
void gc2gemm(const float* __restrict__ Y, const float* __restrict__ XG,
             const float* __restrict__ Xc, float* __restrict__ Xn,
             const float* __restrict__ Wgc, const float* __restrict__ gcb,
             const float* __restrict__ abPrev, float* __restrict__ part,
             int Tin, int Tout, int dd) {
    __shared__ __align__(16) float Bs[32][136];
    __shared__ float sbias[32], sA[32], sBsh[32];
    __shared__ float sSum[32], sSq[32];
    int tid = threadIdx.x;
    int b = blockIdx.z, t = blockIdx.y, n0 = blockIdx.x * 128;
    if (tid < 32) {
        sbias[tid] = gcb[tid];
        sA[tid] = abPrev[tid];
        sBsh[tid] = abPrev[32 + tid];
        sSum[tid] = 0.f;
        sSq[tid] = 0.f;
    }
    int lane = tid & 31, wid = tid >> 5;
    int wm = wid & 1, wn = wid >> 1;      // 2(m) x 4(n); warp tile 16 x 32
    int gid = lane >> 2, tig = lane & 3;
    int lr = tid >> 3, lq = tid & 7;

    float acc[4][4];
#pragma unroll
    for (int ni = 0; ni < 4; ni++)
#pragma unroll
        for (int r = 0; r < 4; r++) acc[ni][r] = 0.f;

    for (int kc = 0; kc < 5; kc++) {      // K = 160 = 5 * 32
        int k = kc * 32 + lr;
        const float* src;
        if (k < 128)
            src = Y + ((size_t)(b * 32 + (k & 31)) * Tout + t) * 2000 + (k >> 5) * 500;
        else
            src = XG + ((size_t)(b * 32 + (k - 128)) * Tout + t) * NNODE;
        __syncthreads();    // also orders sSum/sbias init before use
#pragma unroll
        for (int i = 0; i < 4; i++) {
            int col = lq * 4 + i * 32;
            int gcol = n0 + col;
            float4 v = (gcol < NNODE) ? *(const float4*)(src + gcol)
                                      : make_float4(0.f, 0.f, 0.f, 0.f);
            *(float4*)&Bs[lr][col] = v;
        }
        __syncthreads();
#pragma unroll
        for (int s = 0; s < 4; s++) {
            int ka = kc * 32 + s * 8;
            const float* W0 = Wgc + (size_t)(wm * 16 + gid) * 160 + ka + tig;
            u32 af[4];
            af[0] = __float_as_uint(W0[0]);
            af[1] = __float_as_uint(W0[8 * 160]);
            af[2] = __float_as_uint(W0[4]);
            af[3] = __float_as_uint(W0[8 * 160 + 4]);
#pragma unroll
            for (int ni = 0; ni < 4; ni++) {
                int nb = wn * 32 + ni * 8 + gid;
                u32 bfr[2] = { __float_as_uint(Bs[s * 8 + tig][nb]),
                               __float_as_uint(Bs[s * 8 + tig + 4][nb]) };
                mma_tf32(acc[ni], af, bfr);
            }
        }
    }

    // epilogue: bias + BN-fused residual, write Xn, stats
    int r0 = wm * 16 + gid, r1 = r0 + 8;
    float bias0 = sbias[r0], a0 = sA[r0], sh0 = sBsh[r0];
    float bias1 = sbias[r1], a1 = sA[r1], sh1 = sBsh[r1];
    size_t xcb0 = ((size_t)(b * 32 + r0) * Tin + t + dd) * NNODE;
    size_t xcb1 = ((size_t)(b * 32 + r1) * Tin + t + dd) * NNODE;
    size_t xnb0 = ((size_t)(b * 32 + r0) * Tout + t) * NNODE;
    size_t xnb1 = ((size_t)(b * 32 + r1) * Tout + t) * NNODE;
    float lS0 = 0.f, lQ0 = 0.f, lS1 = 0.f, lQ1 = 0.f;
#pragma unroll
    for (int ni = 0; ni < 4; ni++) {
        int cc = n0 + wn * 32 + ni * 8 + tig * 2;
        if (cc < NNODE) {   // NNODE even, cc even -> pair in-bounds
            float2 rv0 = *(const float2*)&Xc[xcb0 + cc];
            float v00 = acc[ni][0] + bias0 + rv0.x * a0 + sh0;
            float v01 = acc[ni][1] + bias0 + rv0.y * a0 + sh0;
            *(float2*)&Xn[xnb0 + cc] = make_float2(v00, v01);
            lS0 += v00 + v01; lQ0 += v00 * v00 + v01 * v01;
            float2 rv1 = *(const float2*)&Xc[xcb1 + cc];
            float v10 = acc[ni][2] + bias1 + rv1.x * a1 + sh1;
            float v11 = acc[ni][3] + bias1 + rv1.y * a1 + sh1;
            *(float2*)&Xn[xnb1 + cc] = make_float2(v10, v11);
            lS1 += v10 + v11; lQ1 += v10 * v10 + v11 * v11;
        }
    }
#pragma unroll
    for (int off = 2; off; off >>= 1) {
        lS0 += __shfl_down_sync(0xffffffffu, lS0, off, 4);
        lQ0 += __shfl_down_sync(0xffffffffu, lQ0, off, 4);
        lS1 += __shfl_down_sync(0xffffffffu, lS1, off, 4);
        lQ1 += __shfl_down_sync(0xffffffffu, lQ1, off, 4);
    }
    if (tig == 0) {
        atomicAdd(&sSum[r0], lS0); atomicAdd(&sSq[r0], lQ0);
        atomicAdd(&sSum[r1], lS1); atomicAdd(&sSq[r1], lQ1);
    }
    __syncthreads();
    if (tid < 64) {
        int o = tid & 31;
        size_t bidx = ((size_t)blockIdx.z * gridDim.y + blockIdx.y) * gridDim.x + blockIdx.x;
        part[bidx * 64 + tid] = (tid < 32) ? sSum[o] : sSq[o];
    }
}

// ---------------- input split + enter ----------------
__global__ void k_tmp(const float* __restrict__ inputs, const float* __restrict__ factor) {
    int t = blockIdx.x, b = blockIdx.y, tid = threadIdx.x;
    int o = tid >> 2, r = tid & 3;
    int u = o >> 1, f = o & 1;
    const float* inp = inputs + ((size_t)(b * TT + t) * NNODE) * 2 + f;
    float acc = 0.f;
    for (int n = r; n < NNODE; n += 4) acc += inp[n * 2] * factor[n * 32 + u];
    acc += __shfl_down_sync(0xffffffffu, acc, 2);
    acc += __shfl_down_sync(0xffffffffu, acc, 1);
    if (r == 0) g_tmp[(b * TT + t) * 64 + o] = acc;
}

__global__ void k_enter(const float* __restrict__ inputs, const float* __restrict__ factor,
                        const float* __restrict__ ew, const float* __restrict__ eb,
                        float* __restrict__ X0) {
    __shared__ float sw[128], sb[32], stmp[64];
    int b = blockIdx.z, tp = blockIdx.y;
    int tid = threadIdx.x;
    if (tid < 128) sw[tid] = ew[tid];
    if (tid < 32) sb[tid] = eb[tid];
    if (tp > 0 && tid < 64) stmp[tid] = g_tmp[(b * TT + (tp - 1)) * 64 + tid];
    __syncthreads();
    int n = blockIdx.x * 128 + tid;
    if (n >= NNODE) return;
    if (tp == 0) {
#pragma unroll
        for (int o = 0; o < 32; o++)
            X0[((size_t)(b * 32 + o) * RFh + 0) * NNODE + n] = sb[o];
    } else {
        int t = tp - 1;
        float s0 = 0.f, s1 = 0.f;
#pragma unroll
        for (int u = 0; u < 32; u++) {
            float fv = factor[n * 32 + u];
            s0 += fv * stmp[u * 2];
            s1 += fv * stmp[u * 2 + 1];
        }
        float i0 = inputs[((size_t)(b * TT + t) * NNODE + n) * 2 + 0];
        float i1 = inputs[((size_t)(b * TT + t) * NNODE + n) * 2 + 1];
        float r0 = i0 - s0, r1 = i1 - s1;
#pragma unroll
        for (int o = 0; o < 32; o++) {
            float v = sb[o] + sw[o * 4] * s0 + sw[o * 4 + 1] * s1 + sw[o * 4 + 2] * r0 + sw[o * 4 + 3] * r1;
            X0[((size_t)(b * 32 + o) * RFh + tp) * NNODE + n] = v;
        }
    }
}

// ---------------- output head ----------------
__global__ void k_transpose_skip(const float* __restrict__ skip, const float* __restrict__ skp_b,
                                 float* __restrict__ Srelu) {
    __shared__ float tile[32][33];
    int b = blockIdx.z;
    int n0 = blockIdx.x * 32, c0 = blockIdx.y * 32;
    int n = n0 + threadIdx.x, c = c0 + threadIdx.y;
    tile[threadIdx.y][threadIdx.x] = (n < NNODE) ? skip[(size_t)(b * NSKIPC + c) * NNODE + n] : 0.f;
    __syncthreads();
    int n2 = n0 + threadIdx.y, c2 = c0 + threadIdx.x;
    float bsum = 0.f;
#pragma unroll
    for (int l = 0; l < LL; l++) bsum += skp_b[l * 256 + c2];
    if (n2 < NNODE)
        Srelu[(size_t)(b * NNODE + n2) * NSKIPC + c2] =
            to_tf32(fmaxf(tile[threadIdx.x][threadIdx.y] + bsum, 0.f));
}

__global__ void k_headfinal(const float* __restrict__ H, const float* __restrict__ o1b,
                            const float* __restrict__ o2w, const float* __restrict__ o2b,
                            float* __restrict__ out) {
    int warp = threadIdx.x >> 5, lane = threadIdx.x & 31;
    int row = blockIdx.x * 4 + warp;
    if (row >= BB * NNODE) return;
    int b = row / NNODE, n = row % NNODE;
    const float* Hr = H + (size_t)row * NENDC;
    float h[16];
#pragma unroll
    for (int i = 0; i < 16; i++)
        h[i] = fmaxf(Hr[lane + i * 32] + o1b[lane + i * 32], 0.f);
#pragma unroll
    for (int p = 0; p < NPREDC; p++) {
        float acc = 0.f;
#pragma unroll
        for (int i = 0; i < 16; i++) acc += o2w[p * NENDC + lane + i * 32] * h[i];
#pragma unroll
        for (int off = 16; off; off >>= 1) acc += __shfl_down_sync(0xffffffffu, acc, off);
        if (lane == 0) out[(size_t)(b * NPREDC + p) * NNODE + n] = acc + o2b[p];
    }
}

// ---------------- host launcher ----------------
extern "C" void kernel_launch(void* const* d_in, const int* in_sizes, int n_in,
                              void* d_out, int out_size) {
    const float* inputs = (const float*)d_in[0];
    const float* factor = (const float*)d_in[1];
    const float* map_w  = (const float*)d_in[2];
    const float* map_b  = (const float*)d_in[3];
    const float* a1w    = (const float*)d_in[4];
    const float* a1b    = (const float*)d_in[5];
    const float* a2w    = (const float*)d_in[6];
    const float* a2b    = (const float*)d_in[7];
    const float* a3w    = (const float*)d_in[8];
    const float* a3b    = (const float*)d_in[9];
    const float* enter_w = (const float*)d_in[10];
    const float* enter_b = (const float*)d_in[11];
    const float* filt_w = (const float*)d_in[12];
    const float* filt_b = (const float*)d_in[13];
    const float* gate_w = (const float*)d_in[14];
    const float* gate_b = (const float*)d_in[15];
    const float* skp_w  = (const float*)d_in[16];
    const float* skp_b  = (const float*)d_in[17];
    const float* gc_w   = (const float*)d_in[18];
    const float* gc_b   = (const float*)d_in[19];
    const float* bn_g   = (const float*)d_in[20];
    const float* bn_b   = (const float*)d_in[21];
    const float* o1w    = (const float*)d_in[22];
    const float* o1b    = (const float*)d_in[23];
    const float* o2w    = (const float*)d_in[24];
    const float* o2b    = (const float*)d_in[25];

    cudaFuncSetAttribute(tgemm, cudaFuncAttributeMaxDynamicSharedMemorySize, TG_SMEM);

    float *pScat, *pY, *pX0, *pX1, *pXG, *pXGcat, *pWcat, *pSkip, *pSrelu, *pO1T, *pPart, *pAB, *pWgc;
    cudaGetSymbolAddress((void**)&pScat, g_Scat);
    cudaGetSymbolAddress((void**)&pY, g_Y);
    cudaGetSymbolAddress((void**)&pX0, g_X0);
    cudaGetSymbolAddress((void**)&pX1, g_X1);
    cudaGetSymbolAddress((void**)&pXG, g_XG);
    cudaGetSymbolAddress((void**)&pXGcat, g_XGcat);
    cudaGetSymbolAddress((void**)&pWcat, g_Wcat);
    cudaGetSymbolAddress((void**)&pSkip, g_skip);
    cudaGetSymbolAddress((void**)&pSrelu, g_Srelu);
    cudaGetSymbolAddress((void**)&pO1T, g_o1wT);
    cudaGetSymbolAddress((void**)&pPart, g_part);
    cudaGetSymbolAddress((void**)&pAB, g_bnab);
    cudaGetSymbolAddress((void**)&pWgc, g_Wgc);

    float* out = (float*)d_out;
    const int ySize = BB * NPREDC * NNODE;
    const int supSize = 2 * NNODE * NNODE;
    int writeSup = (out_size >= ySize + supSize) ? 1 : 0;
    float* outSup = out + ySize;

    static const int Tin[LL] = {13, 12, 10, 9, 7, 6, 4, 3};
    static const int Dd[LL]  = {1, 2, 1, 2, 1, 2, 1, 2};
    static const int To[LL]  = {12, 10, 9, 7, 6, 4, 3, 1};

    k_fusew<<<1, 64>>>(filt_w, filt_b, gate_w, gate_b);
    k_tmp<<<dim3(TT, BB), 256>>>(inputs, factor);
    k_enter<<<dim3(4, RFh, BB), 128>>>(inputs, factor, enter_w, enter_b, pX0);
    gfgemm<<<dim3((To[0] * NNODE + 127) / 128, BB), 256>>>(pX0, pXG, pXGcat,
                                                           Tin[0], To[0], Dd[0], 0);
    k_prep<<<512, 256>>>(skp_w, o1w, gc_w);
    k_pq<<<NNODE, 64>>>(factor, map_w, map_b, a1w, a1b);
    k_adjmlp<<<NNODE, 128>>>(a2w, a2b, a3w, a3b);
    k_softmax<<<2 * NNODE, 256>>>(outSup, writeSup);
    tgemm<<<dim3(4, 4, 2), 256, TG_SMEM>>>(pScat, pScat, pScat + 500, 500, 500, 500,
                                           2000, 2000, 2000, 1000, 1000, 1000, 1);

    float* Xc = pX0;
    float* Xn = pX1;
    for (int i = 0; i < LL - 1; i++) {
        int slotPrev = (i == 0) ? LL : (i - 1);
        int M = BB * 32 * To[i];
        // diffusion: Y pre-rounded to tf32 (roundC=1) so gc2gemm consumes raw bits
        tgemm<<<dim3(16, M / 128), 256, TG_SMEM>>>(pXG, pScat, pY, M, 2000, 500,
                                                   500, 2000, 2000, 0, 0, 0, 1);
        gc2gemm<<<dim3(4, To[i], BB), 256>>>(pY, pXG, Xc, Xn,
            pWgc + i * 5120, gc_b + i * 32, pAB + slotPrev * 64, pPart,
            Tin[i], To[i], Dd[i]);
        int nblk = 4 * To[i] * BB;
        int j = i + 1;
        k_statsfusew<<<1, 1024>>>(pPart, nblk, (float)(BB * To[i] * NNODE),
                                  bn_g + i * 32, bn_b + i * 32, pAB + i * 64,
                                  filt_w + j * 2048, filt_b + j * 32,
                                  gate_w + j * 2048, gate_b + j * 32);
        gfgemm<<<dim3((To[j] * NNODE + 127) / 128, BB), 256>>>(Xn, pXG, pXGcat,
                                                               Tin[j], To[j], Dd[j], j);
        float* t = Xc; Xc = Xn; Xn = t;
    }
    // skip = Wcat @ XGcat  (batched over b)
    tgemm<<<dim3(4, 2, BB), 256, TG_SMEM>>>(pWcat, pXGcat, pSkip, 256, NNODE, 256,
                                            256, NNODE, NNODE, 0, 256 * NNODE, 256 * NNODE, 0);
    // output head
    k_transpose_skip<<<dim3(16, 8, BB), dim3(32, 32)>>>(pSkip, skp_b, pSrelu);
    tgemm<<<dim3(4, 125), 256, TG_SMEM>>>(pSrelu, pO1T, pY, BB * NNODE, NENDC, NSKIPC,
                                          NSKIPC, NENDC, NENDC, 0, 0, 0, 0);
    k_headfinal<<<(BB * NNODE + 3) / 4, 128>>>(pY, o1b, o2w, o2b, out);
}

// round 14
// speedup vs baseline: 1.4379x; 1.0113x over previous
#include <cuda_runtime.h>
#include <math.h>
#include <stdint.h>

// ---------------- static problem config ----------------
#define BB 32
#define TT 12
#define NNODE 500
#define NSKIPC 256
#define NENDC 512
#define NPREDC 12
#define LL 8
#define RFh 13
#define BN_EPS 1e-5f

typedef unsigned long long ull;
typedef unsigned int u32;

__device__ __forceinline__ float to_tf32(float x) {
    u32 r; asm("cvt.rna.tf32.f32 %0, %1;" : "=r"(r) : "f"(x));
    return __uint_as_float(r);
}
__device__ __forceinline__ void mma_tf32(float* c, const u32* a, const u32* b) {
    asm("mma.sync.aligned.m16n8k8.row.col.f32.tf32.tf32.f32 "
        "{%0,%1,%2,%3},{%4,%5,%6,%7},{%8,%9},{%0,%1,%2,%3};"
        : "+f"(c[0]), "+f"(c[1]), "+f"(c[2]), "+f"(c[3])
        : "r"(a[0]), "r"(a[1]), "r"(a[2]), "r"(a[3]), "r"(b[0]), "r"(b[1]));
}
__device__ __forceinline__ void cp16(float* dst, const float* src, int bytes) {
    u32 d = (u32)__cvta_generic_to_shared(dst);
    asm volatile("cp.async.cg.shared.global [%0], [%1], 16, %2;\n"
                 :: "r"(d), "l"(src), "r"(bytes));
}

// ---------------- device scratch ----------------
__device__ float g_P[NNODE * 64];
__device__ float g_Q[NNODE * 64];
__device__ float g_eraw[2 * NNODE * NNODE];
__device__ float g_Scat[NNODE * 2000];            // tf32-rounded supports [A0|A0^2|A1|A1^2]
__device__ float g_tmp[BB * TT * 32 * 2];
__device__ float g_X0[BB * 32 * RFh * NNODE];
__device__ float g_X1[BB * 32 * RFh * NNODE];
__device__ float g_XG[BB * 32 * 12 * NNODE];      // tf32-rounded gated outputs
__device__ float g_Y[12288 * 2000];               // tf32-rounded diffusion outputs
__device__ float g_XGcat[BB * 256 * NNODE];       // tf32-rounded last-t gated slices
__device__ float g_Wcat[256 * 256];               // tf32-rounded
__device__ float g_skip[BB * NSKIPC * NNODE];
__device__ float g_Srelu[BB * NNODE * NSKIPC];    // tf32-rounded
__device__ float g_o1wT[NSKIPC * NENDC];          // tf32-rounded
__device__ float g_part[1536 * 64];
__device__ float g_bnab[(LL + 1) * 64];
// fused gated-conv weights, ROW-INTERLEAVED: channel c filter at row (c>>3)*16+(c&7),
// gate at row +8 -> f/g of same channel land in the same mma accumulator thread.
__device__ float g_Wf[64 * 64];
__device__ float g_bf[64];
__device__ float g_Wgc[7 * 32 * 160];             // tf32 gc weights [layer][o][k]; k<128 -> Y rows, k>=128 -> XG rows

// ---------------- fused one-time prep ----------------
__global__ void k_prep(const float* __restrict__ skp_w, const float* __restrict__ o1w,
                       const float* __restrict__ gcw) {
    int idx = blockIdx.x * 256 + threadIdx.x;
    if (idx < 64) g_bnab[LL * 64 + idx] = (idx < 32) ? 1.f : 0.f;
    if (idx < 65536) {
        int o = idx >> 8, r = idx & 255, l = r >> 5, c = r & 31;
        g_Wcat[idx] = to_tf32(skp_w[l * 8192 + o * 32 + c]);
    }
    if (idx < 131072) {
        int h = idx / NSKIPC, c = idx % NSKIPC;
        g_o1wT[c * NENDC + h] = to_tf32(o1w[idx]);
    }
    if (idx < 7 * 32 * 160) {
        int l = idx / 5120, rem = idx % 5120, o = rem / 160, k = rem % 160;
        float w = (k < 128) ? gcw[l * 5120 + o * 160 + 32 + k]
                            : gcw[l * 5120 + o * 160 + (k - 128)];
        g_Wgc[idx] = to_tf32(w);
    }
}

__device__ __forceinline__ int wfrow(int o) {   // o: 0-31 filter ch, 32-63 gate ch
    int oo = o & 31;
    return ((oo >> 3) << 4) + (oo & 7) + ((o < 32) ? 0 : 8);
}

// ---------------- layer-0 fused gated-conv weights (identity BN) ----------------
__global__ void k_fusew(const float* __restrict__ fw, const float* __restrict__ fb,
                        const float* __restrict__ gw, const float* __restrict__ gb) {
    int o = threadIdx.x;
    const float* w = (o < 32) ? fw : gw;
    int oo = o & 31;
    float bias = (o < 32) ? fb[oo] : gb[oo];
    int row = wfrow(o);
#pragma unroll
    for (int c = 0; c < 32; c++) {
        g_Wf[row * 64 + c] = to_tf32(w[oo * 64 + c * 2 + 0]);
        g_Wf[row * 64 + 32 + c] = to_tf32(w[oo * 64 + c * 2 + 1]);
    }
    g_bf[o] = bias;
}

// ---------------- BN stats reduce + next-layer weight fusion (one block) ----------------
__global__ void k_statsfusew(const float* __restrict__ part, int nblk, float cnt,
                             const float* __restrict__ g, const float* __restrict__ bta,
                             float* __restrict__ ab,
                             const float* __restrict__ fw, const float* __restrict__ fb,
                             const float* __restrict__ gw, const float* __restrict__ gb) {
    __shared__ float sab[64];
    int tid = threadIdx.x;
    int w = tid >> 5, lane = tid & 31;
    double s = 0.0, q = 0.0;
    for (int i = lane; i < nblk; i += 32) {
        s += (double)part[(size_t)i * 64 + w];
        q += (double)part[(size_t)i * 64 + 32 + w];
    }
#pragma unroll
    for (int off = 16; off; off >>= 1) {
        s += __shfl_down_sync(0xffffffffu, s, off);
        q += __shfl_down_sync(0xffffffffu, q, off);
    }
    if (lane == 0) {
        float mean = (float)(s / cnt);
        float var = (float)(q / cnt) - mean * mean;
        float a = g[w] * rsqrtf(var + BN_EPS);
        float sh = bta[w] - mean * a;
        sab[w] = a; sab[32 + w] = sh;
        ab[w] = a; ab[32 + w] = sh;
    }
    __syncthreads();
    if (tid < 64) {
        int o = tid;
        const float* wsrc = (o < 32) ? fw : gw;
        int oo = o & 31;
        float bias = (o < 32) ? fb[oo] : gb[oo];
        int row = wfrow(o);
        float bsum = 0.f;
#pragma unroll
        for (int c = 0; c < 32; c++) {
            float a = sab[c], bb = sab[32 + c];
            float w0 = wsrc[oo * 64 + c * 2 + 0];
            float w1 = wsrc[oo * 64 + c * 2 + 1];
            g_Wf[row * 64 + c] = to_tf32(w0 * a);
            g_Wf[row * 64 + 32 + c] = to_tf32(w1 * a);
            bsum += (w0 + w1) * bb;
        }
        g_bf[o] = bias + bsum;
    }
}

// ---------------- adjacency ----------------
__global__ void k_pq(const float* __restrict__ factor, const float* __restrict__ map_w,
                     const float* __restrict__ map_b,
                     const float* __restrict__ a1w, const float* __restrict__ a1b) {
    __shared__ float vv[32];
    int j = blockIdx.x, h = threadIdx.x;
    if (h < 32) {
        float acc = map_b[h];
#pragma unroll
        for (int u = 0; u < 32; u++) acc += factor[j * 32 + u] * map_w[u * 32 + h];
        vv[h] = fmaxf(acc, 0.f);
    }
    __syncthreads();
    float p = 0.f, q = a1b[h];
#pragma unroll
    for (int d = 0; d < 32; d++) {
        p += vv[d] * a1w[d * 64 + h];
        q += vv[d] * a1w[(32 + d) * 64 + h];
    }
    g_P[j * 64 + h] = p;
    g_Q[j * 64 + h] = q;
}

__global__ void k_adjmlp(const float* __restrict__ a2w, const float* __restrict__ a2b,
                         const float* __restrict__ a3w, const float* __restrict__ a3b) {
    __shared__ float Pt[128][65];
    __shared__ __align__(16) float sA2[64][32];
    __shared__ float sQ[64];
    __shared__ float sA3[64];
    __shared__ float sA2b[32];
    __shared__ float sA3b[2];
    int i = blockIdx.x, tid = threadIdx.x;
    for (int k = tid; k < 64 * 32; k += 128) sA2[k / 32][k % 32] = a2w[k];
    if (tid < 64) { sQ[tid] = g_Q[i * 64 + tid]; sA3[tid] = a3w[tid]; }
    if (tid < 32) sA2b[tid] = a2b[tid];
    if (tid < 2) sA3b[tid] = a3b[tid];
    for (int j0 = 0; j0 < NNODE; j0 += 128) {
        __syncthreads();
        int cnt = min(128, NNODE - j0);
        for (int k = tid; k < cnt * 64; k += 128)
            Pt[k / 64][k % 64] = g_P[(j0 + (k / 64)) * 64 + (k % 64)];
        __syncthreads();
        if (tid < cnt) {
            int j = j0 + tid;
            float h1[64];
#pragma unroll
            for (int h = 0; h < 64; h++) h1[h] = fmaxf(Pt[tid][h] + sQ[h], 0.f);
            float e0 = sA3b[0], e1 = sA3b[1];
#pragma unroll
            for (int c = 0; c < 32; c++) {
                float acc = sA2b[c];
#pragma unroll
                for (int h = 0; h < 64; h++) acc += h1[h] * sA2[h][c];
                acc = fmaxf(acc, 0.f);
                e0 += acc * sA3[c * 2];
                e1 += acc * sA3[c * 2 + 1];
            }
            g_eraw[i * NNODE + j] = e0;
            g_eraw[NNODE * NNODE + i * NNODE + j] = e1;
        }
    }
}

__global__ void k_softmax(float* __restrict__ outSup, int writeSup) {
    int bid = blockIdx.x;
    int e = bid / NNODE, i = bid % NNODE;
    const float* row = g_eraw + e * NNODE * NNODE + i * NNODE;
    __shared__ float red[256];
    int tid = threadIdx.x;
    float m = -1e30f;
    for (int j = tid; j < NNODE; j += 256) m = fmaxf(m, row[j]);
    red[tid] = m; __syncthreads();
    for (int s = 128; s > 0; s >>= 1) { if (tid < s) red[tid] = fmaxf(red[tid], red[tid + s]); __syncthreads(); }
    m = red[0]; __syncthreads();
    float sum = 0.f;
    for (int j = tid; j < NNODE; j += 256) sum += expf(row[j] - m);
    red[tid] = sum; __syncthreads();
    for (int s = 128; s > 0; s >>= 1) { if (tid < s) red[tid] += red[tid + s]; __syncthreads(); }
    float inv = 1.f / red[0];
    for (int j = tid; j < NNODE; j += 256) {
        float p = expf(row[j] - m) * inv;
        if (j == i) p = fmaxf(p, 1.f);
        g_Scat[i * 2000 + e * 1000 + j] = to_tf32(p);
        if (writeSup) outSup[(e * NNODE + i) * NNODE + j] = p;
    }
}

// ---------------- tf32 tensor GEMM: cp.async 4-stage, raw-bit tf32 ----------------
#define TG_SSZ 4736
#define TG_NST 4
#define TG_SMEM (TG_NST * TG_SSZ * 4)

__device__ __forceinline__ void tg_stage(float* As_s, float* Bs_s,
                                         const float* A, const float* B,
                                         int m0, int n0, int k0,
                                         int M, int N, int K, int lda, int ldb, int tid) {
#pragma unroll
    for (int i = 0; i < 2; i++) {
        int ch = tid + i * 256;
        int row = ch >> 2, kq = (ch & 3) * 4;
        int c = k0 + kq;
        int bytes = 0;
        if (m0 + row < M) {
            int rem = (K - c) * 4;
            bytes = rem > 16 ? 16 : (rem > 0 ? rem : 0);
        }
        cp16(As_s + row * 20 + kq, A + (size_t)(m0 + row) * lda + c, bytes);
    }
#pragma unroll
    for (int i = 0; i < 2; i++) {
        int ch = tid + i * 256;
        int kr = ch >> 5, nq = (ch & 31) * 4;
        int col = n0 + nq;
        int bytes = 0;
        if (k0 + kr < K) {
            int rem = (N - col) * 4;
            bytes = rem > 16 ? 16 : (rem > 0 ? rem : 0);
        }
        cp16(Bs_s + kr * 136 + nq, B + (size_t)(k0 + kr) * ldb + col, bytes);
    }
}

__global__ __launch_bounds__(256, 2)
void tgemm(const float* __restrict__ A, const float* __restrict__ B, float* __restrict__ C,
           int M, int N, int K, int lda, int ldb, int ldc,
           int sA, int sB, int sC, int roundC) {
    extern __shared__ float sdyn[];
    A += (size_t)blockIdx.z * sA;
    B += (size_t)blockIdx.z * sB;
    C += (size_t)blockIdx.z * sC;
    int tid = threadIdx.x;
    int m0 = blockIdx.y * 128, n0 = blockIdx.x * 128;
    int lane = tid & 31, wid = tid >> 5;
    int wm = wid & 1, wn = wid >> 1;
    int gid = lane >> 2, tig = lane & 3;

    float acc[4][4][4];
#pragma unroll
    for (int mi = 0; mi < 4; mi++)
#pragma unroll
        for (int ni = 0; ni < 4; ni++)
#pragma unroll
            for (int r = 0; r < 4; r++) acc[mi][ni][r] = 0.f;

    int nkt = (K + 15) / 16;

    // prologue: stage up to 3 chunks
    int pre = nkt < 3 ? nkt : 3;
    for (int s = 0; s < pre; s++) {
        tg_stage(sdyn + s * TG_SSZ, sdyn + s * TG_SSZ + 2560, A, B,
                 m0, n0, s * 16, M, N, K, lda, ldb, tid);
        asm volatile("cp.async.commit_group;");
    }
    if (pre == 3)      asm volatile("cp.async.wait_group 2;");
    else if (pre == 2) asm volatile("cp.async.wait_group 1;");
    else               asm volatile("cp.async.wait_group 0;");
    __syncthreads();

    for (int kt = 0; kt < nkt; kt++) {
        if (kt + 3 < nkt) {
            int s = (kt + 3) & (TG_NST - 1);
            tg_stage(sdyn + s * TG_SSZ, sdyn + s * TG_SSZ + 2560, A, B,
                     m0, n0, (kt + 3) * 16, M, N, K, lda, ldb, tid);
            asm volatile("cp.async.commit_group;");
        }
        const float* As_s = sdyn + (kt & (TG_NST - 1)) * TG_SSZ;
        const float* Bs_s = As_s + 2560;
#pragma unroll
        for (int ks = 0; ks < 16; ks += 8) {
            u32 af[4][4];
            u32 bf[4][2];
#pragma unroll
            for (int mi = 0; mi < 4; mi++) {
                int mb = wm * 64 + mi * 16 + gid;
                af[mi][0] = __float_as_uint(As_s[mb * 20 + ks + tig]);
                af[mi][1] = __float_as_uint(As_s[(mb + 8) * 20 + ks + tig]);
                af[mi][2] = __float_as_uint(As_s[mb * 20 + ks + tig + 4]);
                af[mi][3] = __float_as_uint(As_s[(mb + 8) * 20 + ks + tig + 4]);
            }
#pragma unroll
            for (int ni = 0; ni < 4; ni++) {
                int nb = wn * 32 + ni * 8 + gid;
                bf[ni][0] = __float_as_uint(Bs_s[(ks + tig) * 136 + nb]);
                bf[ni][1] = __float_as_uint(Bs_s[(ks + tig + 4) * 136 + nb]);
            }
#pragma unroll
            for (int mi = 0; mi < 4; mi++)
#pragma unroll
                for (int ni = 0; ni < 4; ni++)
                    mma_tf32(acc[mi][ni], af[mi], bf[ni]);
        }
        // ensure stage kt+1 is complete before next iteration
        if (kt + 1 < nkt) {
            int after = nkt - kt - 2;       // groups committed after stage kt+1
            if (after >= 2)      asm volatile("cp.async.wait_group 2;");
            else if (after == 1) asm volatile("cp.async.wait_group 1;");
            else                 asm volatile("cp.async.wait_group 0;");
        }
        __syncthreads();
    }

#pragma unroll
    for (int mi = 0; mi < 4; mi++) {
        int r0 = m0 + wm * 64 + mi * 16 + gid;
        int r1 = r0 + 8;
#pragma unroll
        for (int ni = 0; ni < 4; ni++) {
            int cc = n0 + wn * 32 + ni * 8 + tig * 2;
            float c0 = acc[mi][ni][0], c1 = acc[mi][ni][1];
            float c2 = acc[mi][ni][2], c3 = acc[mi][ni][3];
            if (roundC) { c0 = to_tf32(c0); c1 = to_tf32(c1); c2 = to_tf32(c2); c3 = to_tf32(c3); }
            if (r0 < M) {
                if (cc + 1 < N) *(float2*)(C + (size_t)r0 * ldc + cc) = make_float2(c0, c1);
                else if (cc < N) C[(size_t)r0 * ldc + cc] = c0;
            }
            if (r1 < M) {
                if (cc + 1 < N) *(float2*)(C + (size_t)r1 * ldc + cc) = make_float2(c2, c3);
                else if (cc < N) C[(size_t)r1 * ldc + cc] = c2;
            }
        }
    }
}

// ---------------- gated conv as tensor GEMM v2: f/g interleaved, thread-local epilogue ----------------
__global__ __launch_bounds__(256)
void gfgemm(const float* __restrict__ X, float* __restrict__ XG, float* __restrict__ XGcat,
            int Tin, int Tout, int dd, int layer) {
    __shared__ __align__(16) float Bs[64][136];
    int tid = threadIdx.x;
    int b = blockIdx.y;
    int n0 = blockIdx.x * 128;
    int ToutN = Tout * NNODE;
    int TinN = Tin * NNODE;
    const float* Xb = X + (size_t)b * 32 * TinN;

    int lane = tid & 31, wid = tid >> 5;
    int wm = wid & 3, wn = wid >> 2;      // 4(m-tiles of 16) x 2(n-halves of 64)
    int gid = lane >> 2, tig = lane & 3;

    // A fragments: rows wm*16+gid (filter ch c=wm*8+gid) and +8 (gate same ch)
    u32 af[8][4];
    {
        int r0 = wm * 16 + gid, r1 = r0 + 8;
#pragma unroll
        for (int ks = 0; ks < 8; ks++) {
            af[ks][0] = __float_as_uint(g_Wf[r0 * 64 + ks * 8 + tig]);
            af[ks][1] = __float_as_uint(g_Wf[r1 * 64 + ks * 8 + tig]);
            af[ks][2] = __float_as_uint(g_Wf[r0 * 64 + ks * 8 + tig + 4]);
            af[ks][3] = __float_as_uint(g_Wf[r1 * 64 + ks * 8 + tig + 4]);
        }
    }
    // stage B tile (64 rows x 128 cols) with tf32 conversion
    {
        int lr = tid >> 2, lq = tid & 3;
        size_t rbase = (size_t)(lr & 31) * TinN + (size_t)(lr >> 5) * (dd * NNODE);
        const float* src = Xb + rbase + n0;
#pragma unroll
        for (int i = 0; i < 8; i++) {
            int col = (lq + i * 4) * 4;
            int gcol = n0 + col;
            float4 v;
            if (gcol + 3 < ToutN) {
                v = *(const float4*)(src + col);
            } else {
                v.x = (gcol + 0 < ToutN) ? src[col + 0] : 0.f;
                v.y = (gcol + 1 < ToutN) ? src[col + 1] : 0.f;
                v.z = (gcol + 2 < ToutN) ? src[col + 2] : 0.f;
                v.w = (gcol + 3 < ToutN) ? src[col + 3] : 0.f;
            }
            float4 f = make_float4(to_tf32(v.x), to_tf32(v.y), to_tf32(v.z), to_tf32(v.w));
            *(float4*)&Bs[lr][col] = f;
        }
    }
    __syncthreads();

    float acc[8][4];
#pragma unroll
    for (int ni = 0; ni < 8; ni++)
#pragma unroll
        for (int r = 0; r < 4; r++) acc[ni][r] = 0.f;

#pragma unroll
    for (int ks = 0; ks < 8; ks++) {
#pragma unroll
        for (int ni = 0; ni < 8; ni++) {
            int nb = wn * 64 + ni * 8 + gid;
            u32 bfr[2] = { __float_as_uint(Bs[ks * 8 + tig][nb]),
                           __float_as_uint(Bs[ks * 8 + tig + 4][nb]) };
            mma_tf32(acc[ni], af[ks], bfr);
        }
    }

    // thread-local epilogue: acc[ni][0..1]=filter, acc[ni][2..3]=gate (same channel)
    {
        int c = wm * 8 + gid;
        float bff = g_bf[c], bfg = g_bf[32 + c];
        size_t xgbase = (size_t)(b * 32 + c) * ToutN;
        size_t catbase = ((size_t)b * 256 + layer * 32 + c) * NNODE;
        int lastBase = (Tout - 1) * NNODE;
#pragma unroll
        for (int ni = 0; ni < 8; ni++) {
            int gcol = n0 + wn * 64 + ni * 8 + tig * 2;
            if (gcol >= ToutN) continue;   // gcol even, ToutN even -> pair safe
            float f0 = acc[ni][0] + bff, f1 = acc[ni][1] + bff;
            float g0 = acc[ni][2] + bfg, g1 = acc[ni][3] + bfg;
            float v0 = to_tf32(tanhf(f0) * (1.f / (1.f + expf(-g0))));
            float v1 = to_tf32(tanhf(f1) * (1.f / (1.f + expf(-g1))));
            *(float2*)&XG[xgbase + gcol] = make_float2(v0, v1);
            if (gcol >= lastBase) {
                XGcat[catbase + (gcol - lastBase)] = v0;
                XGcat[catbase + (gcol - lastBase) + 1] = v1;
            }
        }
    }
}

// ---------------- gc 1x1 conv as tensor GEMM + residual + BN stats ----------------
__global__ __launch_bounds__(256)
void gc2gemm(const float* __restrict__ Y, const float* __restrict__ XG,
             const float* __restrict__ Xc, float* __restrict__ Xn,
             const float* __restrict__ Wgc, const float* __restrict__ gcb,
             const float* __restrict__ abPrev, float* __restrict__ part,
             int Tin, int Tout, int dd) {
    __shared__ __align__(16) float Bs[32][136];
    __shared__ float sbias[32], sA[32], sBsh[32];
    __shared__ float sSum[32], sSq[32];
    int tid = threadIdx.x;
    int b = blockIdx.z, t = blockIdx.y, n0 = blockIdx.x * 128;
    if (tid < 32) {
        sbias[tid] = gcb[tid];
        sA[tid] = abPrev[tid];
        sBsh[tid] = abPrev[32 + tid];
        sSum[tid] = 0.f;
        sSq[tid] = 0.f;
    }
    int lane = tid & 31, wid = tid >> 5;
    int wm = wid & 1, wn = wid >> 1;
    int gid = lane >> 2, tig = lane & 3;
    int lr = tid >> 3, lq = tid & 7;

    float acc[4][4];
#pragma unroll
    for (int ni = 0; ni < 4; ni++)
#pragma unroll
        for (int r = 0; r < 4; r++) acc[ni][r] = 0.f;

    for (int kc = 0; kc < 5; kc++) {
        int k = kc * 32 + lr;
        const float* src;
        if (k < 128)
            src = Y + ((size_t)(b * 32 + (k & 31)) * Tout + t) * 2000 + (k >> 5) * 500;
        else
            src = XG + ((size_t)(b * 32 + (k - 128)) * Tout + t) * NNODE;
        __syncthreads();
#pragma unroll
        for (int i = 0; i < 4; i++) {
            int col = lq * 4 + i * 32;
            int gcol = n0 + col;
            float4 v = (gcol < NNODE) ? *(const float4*)(src + gcol)
                                      : make_float4(0.f, 0.f, 0.f, 0.f);
            *(float4*)&Bs[lr][col] = v;
        }
        __syncthreads();
#pragma unroll
        for (int s = 0; s < 4; s++) {
            int ka = kc * 32 + s * 8;
            const float* W0 = Wgc + (size_t)(wm * 16 + gid) * 160 + ka + tig;
            u32 af[4];
            af[0] = __float_as_uint(W0[0]);
            af[1] = __float_as_uint(W0[8 * 160]);
            af[2] = __float_as_uint(W0[4]);
            af[3] = __float_as_uint(W0[8 * 160 + 4]);
#pragma unroll
            for (int ni = 0; ni < 4; ni++) {
                int nb = wn * 32 + ni * 8 + gid;
                u32 bfr[2] = { __float_as_uint(Bs[s * 8 + tig][nb]),
                               __float_as_uint(Bs[s * 8 + tig + 4][nb]) };
                mma_tf32(acc[ni], af, bfr);
            }
        }
    }

    int r0 = wm * 16 + gid, r1 = r0 + 8;
    float bias0 = sbias[r0], a0 = sA[r0], sh0 = sBsh[r0];
    float bias1 = sbias[r1], a1 = sA[r1], sh1 = sBsh[r1];
    size_t xcb0 = ((size_t)(b * 32 + r0) * Tin + t + dd) * NNODE;
    size_t xcb1 = ((size_t)(b * 32 + r1) * Tin + t + dd) * NNODE;
    size_t xnb0 = ((size_t)(b * 32 + r0) * Tout + t) * NNODE;
    size_t xnb1 = ((size_t)(b * 32 + r1) * Tout + t) * NNODE;
    float lS0 = 0.f, lQ0 = 0.f, lS1 = 0.f, lQ1 = 0.f;
#pragma unroll
    for (int ni = 0; ni < 4; ni++) {
        int cc = n0 + wn * 32 + ni * 8 + tig * 2;
        if (cc < NNODE) {
            float2 rv0 = *(const float2*)&Xc[xcb0 + cc];
            float v00 = acc[ni][0] + bias0 + rv0.x * a0 + sh0;
            float v01 = acc[ni][1] + bias0 + rv0.y * a0 + sh0;
            *(float2*)&Xn[xnb0 + cc] = make_float2(v00, v01);
            lS0 += v00 + v01; lQ0 += v00 * v00 + v01 * v01;
            float2 rv1 = *(const float2*)&Xc[xcb1 + cc];
            float v10 = acc[ni][2] + bias1 + rv1.x * a1 + sh1;
            float v11 = acc[ni][3] + bias1 + rv1.y * a1 + sh1;
            *(float2*)&Xn[xnb1 + cc] = make_float2(v10, v11);
            lS1 += v10 + v11; lQ1 += v10 * v10 + v11 * v11;
        }
    }
#pragma unroll
    for (int off = 2; off; off >>= 1) {
        lS0 += __shfl_down_sync(0xffffffffu, lS0, off, 4);
        lQ0 += __shfl_down_sync(0xffffffffu, lQ0, off, 4);
        lS1 += __shfl_down_sync(0xffffffffu, lS1, off, 4);
        lQ1 += __shfl_down_sync(0xffffffffu, lQ1, off, 4);
    }
    if (tig == 0) {
        atomicAdd(&sSum[r0], lS0); atomicAdd(&sSq[r0], lQ0);
        atomicAdd(&sSum[r1], lS1); atomicAdd(&sSq[r1], lQ1);
    }
    __syncthreads();
    if (tid < 64) {
        int o = tid & 31;
        size_t bidx = ((size_t)blockIdx.z * gridDim.y + blockIdx.y) * gridDim.x + blockIdx.x;
        part[bidx * 64 + tid] = (tid < 32) ? sSum[o] : sSq[o];
    }
}

// ---------------- input split + enter ----------------
__global__ void k_tmp(const float* __restrict__ inputs, const float* __restrict__ factor) {
    int t = blockIdx.x, b = blockIdx.y, tid = threadIdx.x;
    int o = tid >> 2, r = tid & 3;
    int u = o >> 1, f = o & 1;
    const float* inp = inputs + ((size_t)(b * TT + t) * NNODE) * 2 + f;
    float acc = 0.f;
    for (int n = r; n < NNODE; n += 4) acc += inp[n * 2] * factor[n * 32 + u];
    acc += __shfl_down_sync(0xffffffffu, acc, 2);
    acc += __shfl_down_sync(0xffffffffu, acc, 1);
    if (r == 0) g_tmp[(b * TT + t) * 64 + o] = acc;
}

__global__ void k_enter(const float* __restrict__ inputs, const float* __restrict__ factor,
                        const float* __restrict__ ew, const float* __restrict__ eb,
                        float* __restrict__ X0) {
    __shared__ float sw[128], sb[32], stmp[64];
    int b = blockIdx.z, tp = blockIdx.y;
    int tid = threadIdx.x;
    if (tid < 128) sw[tid] = ew[tid];
    if (tid < 32) sb[tid] = eb[tid];
    if (tp > 0 && tid < 64) stmp[tid] = g_tmp[(b * TT + (tp - 1)) * 64 + tid];
    __syncthreads();
    int n = blockIdx.x * 128 + tid;
    if (n >= NNODE) return;
    if (tp == 0) {
#pragma unroll
        for (int o = 0; o < 32; o++)
            X0[((size_t)(b * 32 + o) * RFh + 0) * NNODE + n] = sb[o];
    } else {
        int t = tp - 1;
        float s0 = 0.f, s1 = 0.f;
#pragma unroll
        for (int u = 0; u < 32; u++) {
            float fv = factor[n * 32 + u];
            s0 += fv * stmp[u * 2];
            s1 += fv * stmp[u * 2 + 1];
        }
        float i0 = inputs[((size_t)(b * TT + t) * NNODE + n) * 2 + 0];
        float i1 = inputs[((size_t)(b * TT + t) * NNODE + n) * 2 + 1];
        float r0 = i0 - s0, r1 = i1 - s1;
#pragma unroll
        for (int o = 0; o < 32; o++) {
            float v = sb[o] + sw[o * 4] * s0 + sw[o * 4 + 1] * s1 + sw[o * 4 + 2] * r0 + sw[o * 4 + 3] * r1;
            X0[((size_t)(b * 32 + o) * RFh + tp) * NNODE + n] = v;
        }
    }
}

// ---------------- output head ----------------
__global__ void k_transpose_skip(const float* __restrict__ skip, const float* __restrict__ skp_b,
                                 float* __restrict__ Srelu) {
    __shared__ float tile[32][33];
    int b = blockIdx.z;
    int n0 = blockIdx.x * 32, c0 = blockIdx.y * 32;
    int n = n0 + threadIdx.x, c = c0 + threadIdx.y;
    tile[threadIdx.y][threadIdx.x] = (n < NNODE) ? skip[(size_t)(b * NSKIPC + c) * NNODE + n] : 0.f;
    __syncthreads();
    int n2 = n0 + threadIdx.y, c2 = c0 + threadIdx.x;
    float bsum = 0.f;
#pragma unroll
    for (int l = 0; l < LL; l++) bsum += skp_b[l * 256 + c2];
    if (n2 < NNODE)
        Srelu[(size_t)(b * NNODE + n2) * NSKIPC + c2] =
            to_tf32(fmaxf(tile[threadIdx.x][threadIdx.y] + bsum, 0.f));
}

__global__ void k_headfinal(const float* __restrict__ H, const float* __restrict__ o1b,
                            const float* __restrict__ o2w, const float* __restrict__ o2b,
                            float* __restrict__ out) {
    int warp = threadIdx.x >> 5, lane = threadIdx.x & 31;
    int row = blockIdx.x * 4 + warp;
    if (row >= BB * NNODE) return;
    int b = row / NNODE, n = row % NNODE;
    const float* Hr = H + (size_t)row * NENDC;
    float h[16];
#pragma unroll
    for (int i = 0; i < 16; i++)
        h[i] = fmaxf(Hr[lane + i * 32] + o1b[lane + i * 32], 0.f);
#pragma unroll
    for (int p = 0; p < NPREDC; p++) {
        float acc = 0.f;
#pragma unroll
        for (int i = 0; i < 16; i++) acc += o2w[p * NENDC + lane + i * 32] * h[i];
#pragma unroll
        for (int off = 16; off; off >>= 1) acc += __shfl_down_sync(0xffffffffu, acc, off);
        if (lane == 0) out[(size_t)(b * NPREDC + p) * NNODE + n] = acc + o2b[p];
    }
}

// ---------------- host launcher ----------------
extern "C" void kernel_launch(void* const* d_in, const int* in_sizes, int n_in,
                              void* d_out, int out_size) {
    const float* inputs = (const float*)d_in[0];
    const float* factor = (const float*)d_in[1];
    const float* map_w  = (const float*)d_in[2];
    const float* map_b  = (const float*)d_in[3];
    const float* a1w    = (const float*)d_in[4];
    const float* a1b    = (const float*)d_in[5];
    const float* a2w    = (const float*)d_in[6];
    const float* a2b    = (const float*)d_in[7];
    const float* a3w    = (const float*)d_in[8];
    const float* a3b    = (const float*)d_in[9];
    const float* enter_w = (const float*)d_in[10];
    const float* enter_b = (const float*)d_in[11];
    const float* filt_w = (const float*)d_in[12];
    const float* filt_b = (const float*)d_in[13];
    const float* gate_w = (const float*)d_in[14];
    const float* gate_b = (const float*)d_in[15];
    const float* skp_w  = (const float*)d_in[16];
    const float* skp_b  = (const float*)d_in[17];
    const float* gc_w   = (const float*)d_in[18];
    const float* gc_b   = (const float*)d_in[19];
    const float* bn_g   = (const float*)d_in[20];
    const float* bn_b   = (const float*)d_in[21];
    const float* o1w    = (const float*)d_in[22];
    const float* o1b    = (const float*)d_in[23];
    const float* o2w    = (const float*)d_in[24];
    const float* o2b    = (const float*)d_in[25];

    cudaFuncSetAttribute(tgemm, cudaFuncAttributeMaxDynamicSharedMemorySize, TG_SMEM);

    float *pScat, *pY, *pX0, *pX1, *pXG, *pXGcat, *pWcat, *pSkip, *pSrelu, *pO1T, *pPart, *pAB, *pWgc;
    cudaGetSymbolAddress((void**)&pScat, g_Scat);
    cudaGetSymbolAddress((void**)&pY, g_Y);
    cudaGetSymbolAddress((void**)&pX0, g_X0);
    cudaGetSymbolAddress((void**)&pX1, g_X1);
    cudaGetSymbolAddress((void**)&pXG, g_XG);
    cudaGetSymbolAddress((void**)&pXGcat, g_XGcat);
    cudaGetSymbolAddress((void**)&pWcat, g_Wcat);
    cudaGetSymbolAddress((void**)&pSkip, g_skip);
    cudaGetSymbolAddress((void**)&pSrelu, g_Srelu);
    cudaGetSymbolAddress((void**)&pO1T, g_o1wT);
    cudaGetSymbolAddress((void**)&pPart, g_part);
    cudaGetSymbolAddress((void**)&pAB, g_bnab);
    cudaGetSymbolAddress((void**)&pWgc, g_Wgc);

    float* out = (float*)d_out;
    const int ySize = BB * NPREDC * NNODE;
    const int supSize = 2 * NNODE * NNODE;
    int writeSup = (out_size >= ySize + supSize) ? 1 : 0;
    float* outSup = out + ySize;

    static const int Tin[LL] = {13, 12, 10, 9, 7, 6, 4, 3};
    static const int Dd[LL]  = {1, 2, 1, 2, 1, 2, 1, 2};
    static const int To[LL]  = {12, 10, 9, 7, 6, 4, 3, 1};

    k_fusew<<<1, 64>>>(filt_w, filt_b, gate_w, gate_b);
    k_tmp<<<dim3(TT, BB), 256>>>(inputs, factor);
    k_enter<<<dim3(4, RFh, BB), 128>>>(inputs, factor, enter_w, enter_b, pX0);
    gfgemm<<<dim3((To[0] * NNODE + 127) / 128, BB), 256>>>(pX0, pXG, pXGcat,
                                                           Tin[0], To[0], Dd[0], 0);
    k_prep<<<512, 256>>>(skp_w, o1w, gc_w);
    k_pq<<<NNODE, 64>>>(factor, map_w, map_b, a1w, a1b);
    k_adjmlp<<<NNODE, 128>>>(a2w, a2b, a3w, a3b);
    k_softmax<<<2 * NNODE, 256>>>(outSup, writeSup);
    tgemm<<<dim3(4, 4, 2), 256, TG_SMEM>>>(pScat, pScat, pScat + 500, 500, 500, 500,
                                           2000, 2000, 2000, 1000, 1000, 1000, 1);

    float* Xc = pX0;
    float* Xn = pX1;
    for (int i = 0; i < LL - 1; i++) {
        int slotPrev = (i == 0) ? LL : (i - 1);
        int M = BB * 32 * To[i];
        tgemm<<<dim3(16, M / 128), 256, TG_SMEM>>>(pXG, pScat, pY, M, 2000, 500,
                                                   500, 2000, 2000, 0, 0, 0, 1);
        gc2gemm<<<dim3(4, To[i], BB), 256>>>(pY, pXG, Xc, Xn,
            pWgc + i * 5120, gc_b + i * 32, pAB + slotPrev * 64, pPart,
            Tin[i], To[i], Dd[i]);
        int nblk = 4 * To[i] * BB;
        int j = i + 1;
        k_statsfusew<<<1, 1024>>>(pPart, nblk, (float)(BB * To[i] * NNODE),
                                  bn_g + i * 32, bn_b + i * 32, pAB + i * 64,
                                  filt_w + j * 2048, filt_b + j * 32,
                                  gate_w + j * 2048, gate_b + j * 32);
        gfgemm<<<dim3((To[j] * NNODE + 127) / 128, BB), 256>>>(Xn, pXG, pXGcat,
                                                               Tin[j], To[j], Dd[j], j);
        float* t = Xc; Xc = Xn; Xn = t;
    }
    // skip = Wcat @ XGcat  (batched over b)
    tgemm<<<dim3(4, 2, BB), 256, TG_SMEM>>>(pWcat, pXGcat, pSkip, 256, NNODE, 256,
                                            256, NNODE, NNODE, 0, 256 * NNODE, 256 * NNODE, 0);
    // output head
    k_transpose_skip<<<dim3(16, 8, BB), dim3(32, 32)>>>(pSkip, skp_b, pSrelu);
    tgemm<<<dim3(4, 125), 256, TG_SMEM>>>(pSrelu, pO1T, pY, BB * NNODE, NENDC, NSKIPC,
                                          NSKIPC, NENDC, NENDC, 0, 0, 0, 0);
    k_headfinal<<<(BB * NNODE + 3) / 4, 128>>>(pY, o1b, o2w, o2b, out);
}

// round 15
// speedup vs baseline: 1.6730x; 1.1635x over previous
#include <cuda_runtime.h>
#include <math.h>
#include <stdint.h>

// ---------------- static problem config ----------------
#define BB 32
#define TT 12
#define NNODE 500
#define NSKIPC 256
#define NENDC 512
#define NPREDC 12
#define LL 8
#define RFh 13
#define BN_EPS 1e-5f

typedef unsigned long long ull;
typedef unsigned int u32;

__device__ __forceinline__ float to_tf32(float x) {
    u32 r; asm("cvt.rna.tf32.f32 %0, %1;" : "=r"(r) : "f"(x));
    return __uint_as_float(r);
}
__device__ __forceinline__ void mma_tf32(float* c, const u32* a, const u32* b) {
    asm("mma.sync.aligned.m16n8k8.row.col.f32.tf32.tf32.f32 "
        "{%0,%1,%2,%3},{%4,%5,%6,%7},{%8,%9},{%0,%1,%2,%3};"
        : "+f"(c[0]), "+f"(c[1]), "+f"(c[2]), "+f"(c[3])
        : "r"(a[0]), "r"(a[1]), "r"(a[2]), "r"(a[3]), "r"(b[0]), "r"(b[1]));
}
__device__ __forceinline__ void cp16(float* dst, const float* src, int bytes) {
    u32 d = (u32)__cvta_generic_to_shared(dst);
    asm volatile("cp.async.cg.shared.global [%0], [%1], 16, %2;\n"
                 :: "r"(d), "l"(src), "r"(bytes));
}

// ---------------- device scratch ----------------
__device__ float g_P[NNODE * 64];
__device__ float g_Q[NNODE * 64];
__device__ float g_eraw[2 * NNODE * NNODE];
__device__ float g_Scat[NNODE * 2000];            // tf32-rounded supports [A0|A0^2|A1|A1^2]
__device__ float g_tmp[BB * TT * 32 * 2];
__device__ float g_X0[BB * 32 * RFh * NNODE];
__device__ float g_X1[BB * 32 * RFh * NNODE];
__device__ float g_XG[BB * 32 * 12 * NNODE];      // tf32-rounded gated outputs
__device__ float g_Y[12288 * 2000];               // tf32-rounded diffusion outputs
__device__ float g_XGcat[BB * 256 * NNODE];       // tf32-rounded last-t gated slices
__device__ float g_Wcat[256 * 256];               // tf32-rounded
__device__ float g_skip[BB * NSKIPC * NNODE];
__device__ float g_Srelu[BB * NNODE * NSKIPC];    // tf32-rounded
__device__ float g_o1wT[NSKIPC * NENDC];          // tf32-rounded
__device__ float g_stats2[7 * 64];                // per-layer BN stats accumulators (atomic)
__device__ float g_Wgc[7 * 32 * 160];             // tf32 gc weights [layer][o][k]; k<128 -> Y rows, k>=128 -> XG rows

// ---------------- fused one-time prep ----------------
__global__ void k_prep(const float* __restrict__ skp_w, const float* __restrict__ o1w,
                       const float* __restrict__ gcw) {
    int idx = blockIdx.x * 256 + threadIdx.x;
    if (idx < 7 * 64) g_stats2[idx] = 0.f;
    if (idx < 65536) {
        int o = idx >> 8, r = idx & 255, l = r >> 5, c = r & 31;
        g_Wcat[idx] = to_tf32(skp_w[l * 8192 + o * 32 + c]);
    }
    if (idx < 131072) {
        int h = idx / NSKIPC, c = idx % NSKIPC;
        g_o1wT[c * NENDC + h] = to_tf32(o1w[idx]);
    }
    if (idx < 7 * 32 * 160) {
        int l = idx / 5120, rem = idx % 5120, o = rem / 160, k = rem % 160;
        float w = (k < 128) ? gcw[l * 5120 + o * 160 + 32 + k]
                            : gcw[l * 5120 + o * 160 + (k - 128)];
        g_Wgc[idx] = to_tf32(w);
    }
}

__device__ __forceinline__ int wfrow(int o) {   // o: 0-31 filter ch, 32-63 gate ch
    int oo = o & 31;
    return ((oo >> 3) << 4) + (oo & 7) + ((o < 32) ? 0 : 8);
}

// ---------------- adjacency ----------------
__global__ void k_pq(const float* __restrict__ factor, const float* __restrict__ map_w,
                     const float* __restrict__ map_b,
                     const float* __restrict__ a1w, const float* __restrict__ a1b) {
    __shared__ float vv[32];
    int j = blockIdx.x, h = threadIdx.x;
    if (h < 32) {
        float acc = map_b[h];
#pragma unroll
        for (int u = 0; u < 32; u++) acc += factor[j * 32 + u] * map_w[u * 32 + h];
        vv[h] = fmaxf(acc, 0.f);
    }
    __syncthreads();
    float p = 0.f, q = a1b[h];
#pragma unroll
    for (int d = 0; d < 32; d++) {
        p += vv[d] * a1w[d * 64 + h];
        q += vv[d] * a1w[(32 + d) * 64 + h];
    }
    g_P[j * 64 + h] = p;
    g_Q[j * 64 + h] = q;
}

__global__ void k_adjmlp(const float* __restrict__ a2w, const float* __restrict__ a2b,
                         const float* __restrict__ a3w, const float* __restrict__ a3b) {
    __shared__ float Pt[128][65];
    __shared__ __align__(16) float sA2[64][32];
    __shared__ float sQ[64];
    __shared__ float sA3[64];
    __shared__ float sA2b[32];
    __shared__ float sA3b[2];
    int i = blockIdx.x, tid = threadIdx.x;
    for (int k = tid; k < 64 * 32; k += 128) sA2[k / 32][k % 32] = a2w[k];
    if (tid < 64) { sQ[tid] = g_Q[i * 64 + tid]; sA3[tid] = a3w[tid]; }
    if (tid < 32) sA2b[tid] = a2b[tid];
    if (tid < 2) sA3b[tid] = a3b[tid];
    for (int j0 = 0; j0 < NNODE; j0 += 128) {
        __syncthreads();
        int cnt = min(128, NNODE - j0);
        for (int k = tid; k < cnt * 64; k += 128)
            Pt[k / 64][k % 64] = g_P[(j0 + (k / 64)) * 64 + (k % 64)];
        __syncthreads();
        if (tid < cnt) {
            int j = j0 + tid;
            float h1[64];
#pragma unroll
            for (int h = 0; h < 64; h++) h1[h] = fmaxf(Pt[tid][h] + sQ[h], 0.f);
            float e0 = sA3b[0], e1 = sA3b[1];
#pragma unroll
            for (int c = 0; c < 32; c++) {
                float acc = sA2b[c];
#pragma unroll
                for (int h = 0; h < 64; h++) acc += h1[h] * sA2[h][c];
                acc = fmaxf(acc, 0.f);
                e0 += acc * sA3[c * 2];
                e1 += acc * sA3[c * 2 + 1];
            }
            g_eraw[i * NNODE + j] = e0;
            g_eraw[NNODE * NNODE + i * NNODE + j] = e1;
        }
    }
}

__global__ void k_softmax(float* __restrict__ outSup, int writeSup) {
    int bid = blockIdx.x;
    int e = bid / NNODE, i = bid % NNODE;
    const float* row = g_eraw + e * NNODE * NNODE + i * NNODE;
    __shared__ float red[256];
    int tid = threadIdx.x;
    float m = -1e30f;
    for (int j = tid; j < NNODE; j += 256) m = fmaxf(m, row[j]);
    red[tid] = m; __syncthreads();
    for (int s = 128; s > 0; s >>= 1) { if (tid < s) red[tid] = fmaxf(red[tid], red[tid + s]); __syncthreads(); }
    m = red[0]; __syncthreads();
    float sum = 0.f;
    for (int j = tid; j < NNODE; j += 256) sum += expf(row[j] - m);
    red[tid] = sum; __syncthreads();
    for (int s = 128; s > 0; s >>= 1) { if (tid < s) red[tid] += red[tid + s]; __syncthreads(); }
    float inv = 1.f / red[0];
    for (int j = tid; j < NNODE; j += 256) {
        float p = expf(row[j] - m) * inv;
        if (j == i) p = fmaxf(p, 1.f);
        g_Scat[i * 2000 + e * 1000 + j] = to_tf32(p);
        if (writeSup) outSup[(e * NNODE + i) * NNODE + j] = p;
    }
}

// ---------------- tf32 tensor GEMM: cp.async 4-stage, raw-bit tf32 ----------------
#define TG_SSZ 4736
#define TG_NST 4
#define TG_SMEM (TG_NST * TG_SSZ * 4)

__device__ __forceinline__ void tg_stage(float* As_s, float* Bs_s,
                                         const float* A, const float* B,
                                         int m0, int n0, int k0,
                                         int M, int N, int K, int lda, int ldb, int tid) {
#pragma unroll
    for (int i = 0; i < 2; i++) {
        int ch = tid + i * 256;
        int row = ch >> 2, kq = (ch & 3) * 4;
        int c = k0 + kq;
        int bytes = 0;
        if (m0 + row < M) {
            int rem = (K - c) * 4;
            bytes = rem > 16 ? 16 : (rem > 0 ? rem : 0);
        }
        cp16(As_s + row * 20 + kq, A + (size_t)(m0 + row) * lda + c, bytes);
    }
#pragma unroll
    for (int i = 0; i < 2; i++) {
        int ch = tid + i * 256;
        int kr = ch >> 5, nq = (ch & 31) * 4;
        int col = n0 + nq;
        int bytes = 0;
        if (k0 + kr < K) {
            int rem = (N - col) * 4;
            bytes = rem > 16 ? 16 : (rem > 0 ? rem : 0);
        }
        cp16(Bs_s + kr * 136 + nq, B + (size_t)(k0 + kr) * ldb + col, bytes);
    }
}

__global__ __launch_bounds__(256, 2)
void tgemm(const float* __restrict__ A, const float* __restrict__ B, float* __restrict__ C,
           int M, int N, int K, int lda, int ldb, int ldc,
           int sA, int sB, int sC, int roundC) {
    extern __shared__ float sdyn[];
    A += (size_t)blockIdx.z * sA;
    B += (size_t)blockIdx.z * sB;
    C += (size_t)blockIdx.z * sC;
    int tid = threadIdx.x;
    int m0 = blockIdx.y * 128, n0 = blockIdx.x * 128;
    int lane = tid & 31, wid = tid >> 5;
    int wm = wid & 1, wn = wid >> 1;
    int gid = lane >> 2, tig = lane & 3;

    float acc[4][4][4];
#pragma unroll
    for (int mi = 0; mi < 4; mi++)
#pragma unroll
        for (int ni = 0; ni < 4; ni++)
#pragma unroll
            for (int r = 0; r < 4; r++) acc[mi][ni][r] = 0.f;

    int nkt = (K + 15) / 16;

    int pre = nkt < 3 ? nkt : 3;
    for (int s = 0; s < pre; s++) {
        tg_stage(sdyn + s * TG_SSZ, sdyn + s * TG_SSZ + 2560, A, B,
                 m0, n0, s * 16, M, N, K, lda, ldb, tid);
        asm volatile("cp.async.commit_group;");
    }
    if (pre == 3)      asm volatile("cp.async.wait_group 2;");
    else if (pre == 2) asm volatile("cp.async.wait_group 1;");
    else               asm volatile("cp.async.wait_group 0;");
    __syncthreads();

    for (int kt = 0; kt < nkt; kt++) {
        if (kt + 3 < nkt) {
            int s = (kt + 3) & (TG_NST - 1);
            tg_stage(sdyn + s * TG_SSZ, sdyn + s * TG_SSZ + 2560, A, B,
                     m0, n0, (kt + 3) * 16, M, N, K, lda, ldb, tid);
            asm volatile("cp.async.commit_group;");
        }
        const float* As_s = sdyn + (kt & (TG_NST - 1)) * TG_SSZ;
        const float* Bs_s = As_s + 2560;
#pragma unroll
        for (int ks = 0; ks < 16; ks += 8) {
            u32 af[4][4];
            u32 bf[4][2];
#pragma unroll
            for (int mi = 0; mi < 4; mi++) {
                int mb = wm * 64 + mi * 16 + gid;
                af[mi][0] = __float_as_uint(As_s[mb * 20 + ks + tig]);
                af[mi][1] = __float_as_uint(As_s[(mb + 8) * 20 + ks + tig]);
                af[mi][2] = __float_as_uint(As_s[mb * 20 + ks + tig + 4]);
                af[mi][3] = __float_as_uint(As_s[(mb + 8) * 20 + ks + tig + 4]);
            }
#pragma unroll
            for (int ni = 0; ni < 4; ni++) {
                int nb = wn * 32 + ni * 8 + gid;
                bf[ni][0] = __float_as_uint(Bs_s[(ks + tig) * 136 + nb]);
                bf[ni][1] = __float_as_uint(Bs_s[(ks + tig + 4) * 136 + nb]);
            }
#pragma unroll
            for (int mi = 0; mi < 4; mi++)
#pragma unroll
                for (int ni = 0; ni < 4; ni++)
                    mma_tf32(acc[mi][ni], af[mi], bf[ni]);
        }
        if (kt + 1 < nkt) {
            int after = nkt - kt - 2;
            if (after >= 2)      asm volatile("cp.async.wait_group 2;");
            else if (after == 1) asm volatile("cp.async.wait_group 1;");
            else                 asm volatile("cp.async.wait_group 0;");
        }
        __syncthreads();
    }

#pragma unroll
    for (int mi = 0; mi < 4; mi++) {
        int r0 = m0 + wm * 64 + mi * 16 + gid;
        int r1 = r0 + 8;
#pragma unroll
        for (int ni = 0; ni < 4; ni++) {
            int cc = n0 + wn * 32 + ni * 8 + tig * 2;
            float c0 = acc[mi][ni][0], c1 = acc[mi][ni][1];
            float c2 = acc[mi][ni][2], c3 = acc[mi][ni][3];
            if (roundC) { c0 = to_tf32(c0); c1 = to_tf32(c1); c2 = to_tf32(c2); c3 = to_tf32(c3); }
            if (r0 < M) {
                if (cc + 1 < N) *(float2*)(C + (size_t)r0 * ldc + cc) = make_float2(c0, c1);
                else if (cc < N) C[(size_t)r0 * ldc + cc] = c0;
            }
            if (r1 < M) {
                if (cc + 1 < N) *(float2*)(C + (size_t)r1 * ldc + cc) = make_float2(c2, c3);
                else if (cc < N) C[(size_t)r1 * ldc + cc] = c2;
            }
        }
    }
}

// ---------------- gated conv GEMM v3: in-kernel BN-stats consume + weight fusion ----------------
// dyn smem: Bs[64][136] then sWf[64][68]
#define GF_SMEM ((64 * 136 + 64 * 68) * 4)

__global__ __launch_bounds__(256)
void gfgemm(const float* __restrict__ X, float* __restrict__ XG, float* __restrict__ XGcat,
            const float* __restrict__ fw, const float* __restrict__ fb,
            const float* __restrict__ gw, const float* __restrict__ gb,
            const float* __restrict__ stats, float cnt,
            const float* __restrict__ bng, const float* __restrict__ bnb,
            int Tin, int Tout, int dd, int layer) {
    extern __shared__ float sm[];
    float* Bs = sm;                    // [64][136]
    float* sWf = sm + 64 * 136;        // [64][68]
    __shared__ float sab[64], sbf[64];
    int tid = threadIdx.x;
    int b = blockIdx.y;
    int n0 = blockIdx.x * 128;
    int ToutN = Tout * NNODE;
    int TinN = Tin * NNODE;
    const float* Xb = X + (size_t)b * 32 * TinN;

    int lane = tid & 31, wid = tid >> 5;
    int wm = wid & 3, wn = wid >> 2;
    int gid = lane >> 2, tig = lane & 3;

    // (a, sh) from stats slot (identity if NULL)
    if (tid < 32) {
        float a = 1.f, sh = 0.f;
        if (stats) {
            float mean = stats[tid] / cnt;
            float var = stats[32 + tid] / cnt - mean * mean;
            a = bng[tid] * rsqrtf(var + BN_EPS);
            sh = bnb[tid] - mean * a;
        }
        sab[tid] = a; sab[32 + tid] = sh;
    }
    // stage B tile (all threads; independent of sab)
    {
        int lr = tid >> 2, lq = tid & 3;
        size_t rbase = (size_t)(lr & 31) * TinN + (size_t)(lr >> 5) * (dd * NNODE);
        const float* src = Xb + rbase + n0;
#pragma unroll
        for (int i = 0; i < 8; i++) {
            int col = (lq + i * 4) * 4;
            int gcol = n0 + col;
            float4 v;
            if (gcol + 3 < ToutN) {
                v = *(const float4*)(src + col);
            } else {
                v.x = (gcol + 0 < ToutN) ? src[col + 0] : 0.f;
                v.y = (gcol + 1 < ToutN) ? src[col + 1] : 0.f;
                v.z = (gcol + 2 < ToutN) ? src[col + 2] : 0.f;
                v.w = (gcol + 3 < ToutN) ? src[col + 3] : 0.f;
            }
            float4 f = make_float4(to_tf32(v.x), to_tf32(v.y), to_tf32(v.z), to_tf32(v.w));
            *(float4*)&Bs[lr * 136 + col] = f;
        }
    }
    __syncthreads();   // sab + Bs visible
    // fuse weights (BN folded) into SMEM
    if (tid < 64) {
        int o = tid, oo = o & 31;
        const float* wsrc = (o < 32) ? fw : gw;
        float bias = (o < 32) ? fb[oo] : gb[oo];
        int row = wfrow(o);
        float bsum = 0.f;
#pragma unroll
        for (int c = 0; c < 32; c++) {
            float a = sab[c], bb = sab[32 + c];
            float w0 = wsrc[oo * 64 + c * 2 + 0];
            float w1 = wsrc[oo * 64 + c * 2 + 1];
            sWf[row * 68 + c] = to_tf32(w0 * a);
            sWf[row * 68 + 32 + c] = to_tf32(w1 * a);
            bsum += (w0 + w1) * bb;
        }
        sbf[o] = bias + bsum;
    }
    __syncthreads();   // sWf, sbf visible

    // A fragments from SMEM (conflict-free: stride 68)
    u32 af[8][4];
    {
        int r0 = wm * 16 + gid, r1 = r0 + 8;
#pragma unroll
        for (int ks = 0; ks < 8; ks++) {
            af[ks][0] = __float_as_uint(sWf[r0 * 68 + ks * 8 + tig]);
            af[ks][1] = __float_as_uint(sWf[r1 * 68 + ks * 8 + tig]);
            af[ks][2] = __float_as_uint(sWf[r0 * 68 + ks * 8 + tig + 4]);
            af[ks][3] = __float_as_uint(sWf[r1 * 68 + ks * 8 + tig + 4]);
        }
    }

    float acc[8][4];
#pragma unroll
    for (int ni = 0; ni < 8; ni++)
#pragma unroll
        for (int r = 0; r < 4; r++) acc[ni][r] = 0.f;

#pragma unroll
    for (int ks = 0; ks < 8; ks++) {
#pragma unroll
        for (int ni = 0; ni < 8; ni++) {
            int nb = wn * 64 + ni * 8 + gid;
            u32 bfr[2] = { __float_as_uint(Bs[(ks * 8 + tig) * 136 + nb]),
                           __float_as_uint(Bs[(ks * 8 + tig + 4) * 136 + nb]) };
            mma_tf32(acc[ni], af[ks], bfr);
        }
    }

    // thread-local epilogue: acc[ni][0..1]=filter, acc[ni][2..3]=gate (same channel)
    {
        int c = wm * 8 + gid;
        float bff = sbf[c], bfg = sbf[32 + c];
        size_t xgbase = (size_t)(b * 32 + c) * ToutN;
        size_t catbase = ((size_t)b * 256 + layer * 32 + c) * NNODE;
        int lastBase = (Tout - 1) * NNODE;
#pragma unroll
        for (int ni = 0; ni < 8; ni++) {
            int gcol = n0 + wn * 64 + ni * 8 + tig * 2;
            if (gcol >= ToutN) continue;
            float f0 = acc[ni][0] + bff, f1 = acc[ni][1] + bff;
            float g0 = acc[ni][2] + bfg, g1 = acc[ni][3] + bfg;
            float v0 = to_tf32(tanhf(f0) * (1.f / (1.f + expf(-g0))));
            float v1 = to_tf32(tanhf(f1) * (1.f / (1.f + expf(-g1))));
            *(float2*)&XG[xgbase + gcol] = make_float2(v0, v1);
            if (gcol >= lastBase) {
                XGcat[catbase + (gcol - lastBase)] = v0;
                XGcat[catbase + (gcol - lastBase) + 1] = v1;
            }
        }
    }
}

// ---------------- gc 1x1 conv GEMM + residual(BN from stats slot) + atomic BN stats ----------------
__global__ __launch_bounds__(256)
void gc2gemm(const float* __restrict__ Y, const float* __restrict__ XG,
             const float* __restrict__ Xc, float* __restrict__ Xn,
             const float* __restrict__ Wgc, const float* __restrict__ gcb,
             const float* __restrict__ statsPrev, float cntPrev,
             const float* __restrict__ bngP, const float* __restrict__ bnbP,
             float* __restrict__ statsOut,
             int Tin, int Tout, int dd) {
    __shared__ __align__(16) float Bs[32][136];
    __shared__ float sbias[32], sA[32], sBsh[32];
    __shared__ float sSum[32], sSq[32];
    int tid = threadIdx.x;
    int b = blockIdx.z, t = blockIdx.y, n0 = blockIdx.x * 128;
    if (tid < 32) {
        sbias[tid] = gcb[tid];
        float a = 1.f, sh = 0.f;
        if (statsPrev) {
            float mean = statsPrev[tid] / cntPrev;
            float var = statsPrev[32 + tid] / cntPrev - mean * mean;
            a = bngP[tid] * rsqrtf(var + BN_EPS);
            sh = bnbP[tid] - mean * a;
        }
        sA[tid] = a;
        sBsh[tid] = sh;
        sSum[tid] = 0.f;
        sSq[tid] = 0.f;
    }
    int lane = tid & 31, wid = tid >> 5;
    int wm = wid & 1, wn = wid >> 1;
    int gid = lane >> 2, tig = lane & 3;
    int lr = tid >> 3, lq = tid & 7;

    float acc[4][4];
#pragma unroll
    for (int ni = 0; ni < 4; ni++)
#pragma unroll
        for (int r = 0; r < 4; r++) acc[ni][r] = 0.f;

    for (int kc = 0; kc < 5; kc++) {
        int k = kc * 32 + lr;
        const float* src;
        if (k < 128)
            src = Y + ((size_t)(b * 32 + (k & 31)) * Tout + t) * 2000 + (k >> 5) * 500;
        else
            src = XG + ((size_t)(b * 32 + (k - 128)) * Tout + t) * NNODE;
        __syncthreads();
#pragma unroll
        for (int i = 0; i < 4; i++) {
            int col = lq * 4 + i * 32;
            int gcol = n0 + col;
            float4 v = (gcol < NNODE) ? *(const float4*)(src + gcol)
                                      : make_float4(0.f, 0.f, 0.f, 0.f);
            *(float4*)&Bs[lr][col] = v;
        }
        __syncthreads();
#pragma unroll
        for (int s = 0; s < 4; s++) {
            int ka = kc * 32 + s * 8;
            const float* W0 = Wgc + (size_t)(wm * 16 + gid) * 160 + ka + tig;
            u32 af[4];
            af[0] = __float_as_uint(W0[0]);
            af[1] = __float_as_uint(W0[8 * 160]);
            af[2] = __float_as_uint(W0[4]);
            af[3] = __float_as_uint(W0[8 * 160 + 4]);
#pragma unroll
            for (int ni = 0; ni < 4; ni++) {
                int nb = wn * 32 + ni * 8 + gid;
                u32 bfr[2] = { __float_as_uint(Bs[s * 8 + tig][nb]),
                               __float_as_uint(Bs[s * 8 + tig + 4][nb]) };
                mma_tf32(acc[ni], af, bfr);
            }
        }
    }

    int r0 = wm * 16 + gid, r1 = r0 + 8;
    float bias0 = sbias[r0], a0 = sA[r0], sh0 = sBsh[r0];
    float bias1 = sbias[r1], a1 = sA[r1], sh1 = sBsh[r1];
    size_t xcb0 = ((size_t)(b * 32 + r0) * Tin + t + dd) * NNODE;
    size_t xcb1 = ((size_t)(b * 32 + r1) * Tin + t + dd) * NNODE;
    size_t xnb0 = ((size_t)(b * 32 + r0) * Tout + t) * NNODE;
    size_t xnb1 = ((size_t)(b * 32 + r1) * Tout + t) * NNODE;
    float lS0 = 0.f, lQ0 = 0.f, lS1 = 0.f, lQ1 = 0.f;
#pragma unroll
    for (int ni = 0; ni < 4; ni++) {
        int cc = n0 + wn * 32 + ni * 8 + tig * 2;
        if (cc < NNODE) {
            float2 rv0 = *(const float2*)&Xc[xcb0 + cc];
            float v00 = acc[ni][0] + bias0 + rv0.x * a0 + sh0;
            float v01 = acc[ni][1] + bias0 + rv0.y * a0 + sh0;
            *(float2*)&Xn[xnb0 + cc] = make_float2(v00, v01);
            lS0 += v00 + v01; lQ0 += v00 * v00 + v01 * v01;
            float2 rv1 = *(const float2*)&Xc[xcb1 + cc];
            float v10 = acc[ni][2] + bias1 + rv1.x * a1 + sh1;
            float v11 = acc[ni][3] + bias1 + rv1.y * a1 + sh1;
            *(float2*)&Xn[xnb1 + cc] = make_float2(v10, v11);
            lS1 += v10 + v11; lQ1 += v10 * v10 + v11 * v11;
        }
    }
#pragma unroll
    for (int off = 2; off; off >>= 1) {
        lS0 += __shfl_down_sync(0xffffffffu, lS0, off, 4);
        lQ0 += __shfl_down_sync(0xffffffffu, lQ0, off, 4);
        lS1 += __shfl_down_sync(0xffffffffu, lS1, off, 4);
        lQ1 += __shfl_down_sync(0xffffffffu, lQ1, off, 4);
    }
    if (tig == 0) {
        atomicAdd(&sSum[r0], lS0); atomicAdd(&sSq[r0], lQ0);
        atomicAdd(&sSum[r1], lS1); atomicAdd(&sSq[r1], lQ1);
    }
    __syncthreads();
    if (tid < 64) {
        int o = tid & 31;
        atomicAdd(&statsOut[tid], (tid < 32) ? sSum[o] : sSq[o]);
    }
}

// ---------------- input split + enter ----------------
__global__ void k_tmp(const float* __restrict__ inputs, const float* __restrict__ factor) {
    int t = blockIdx.x, b = blockIdx.y, tid = threadIdx.x;
    int o = tid >> 2, r = tid & 3;
    int u = o >> 1, f = o & 1;
    const float* inp = inputs + ((size_t)(b * TT + t) * NNODE) * 2 + f;
    float acc = 0.f;
    for (int n = r; n < NNODE; n += 4) acc += inp[n * 2] * factor[n * 32 + u];
    acc += __shfl_down_sync(0xffffffffu, acc, 2);
    acc += __shfl_down_sync(0xffffffffu, acc, 1);
    if (r == 0) g_tmp[(b * TT + t) * 64 + o] = acc;
}

__global__ void k_enter(const float* __restrict__ inputs, const float* __restrict__ factor,
                        const float* __restrict__ ew, const float* __restrict__ eb,
                        float* __restrict__ X0) {
    __shared__ float sw[128], sb[32], stmp[64];
    int b = blockIdx.z, tp = blockIdx.y;
    int tid = threadIdx.x;
    if (tid < 128) sw[tid] = ew[tid];
    if (tid < 32) sb[tid] = eb[tid];
    if (tp > 0 && tid < 64) stmp[tid] = g_tmp[(b * TT + (tp - 1)) * 64 + tid];
    __syncthreads();
    int n = blockIdx.x * 128 + tid;
    if (n >= NNODE) return;
    if (tp == 0) {
#pragma unroll
        for (int o = 0; o < 32; o++)
            X0[((size_t)(b * 32 + o) * RFh + 0) * NNODE + n] = sb[o];
    } else {
        int t = tp - 1;
        float s0 = 0.f, s1 = 0.f;
#pragma unroll
        for (int u = 0; u < 32; u++) {
            float fv = factor[n * 32 + u];
            s0 += fv * stmp[u * 2];
            s1 += fv * stmp[u * 2 + 1];
        }
        float i0 = inputs[((size_t)(b * TT + t) * NNODE + n) * 2 + 0];
        float i1 = inputs[((size_t)(b * TT + t) * NNODE + n) * 2 + 1];
        float r0 = i0 - s0, r1 = i1 - s1;
#pragma unroll
        for (int o = 0; o < 32; o++) {
            float v = sb[o] + sw[o * 4] * s0 + sw[o * 4 + 1] * s1 + sw[o * 4 + 2] * r0 + sw[o * 4 + 3] * r1;
            X0[((size_t)(b * 32 + o) * RFh + tp) * NNODE + n] = v;
        }
    }
}

// ---------------- output head ----------------
__global__ void k_transpose_skip(const float* __restrict__ skip, const float* __restrict__ skp_b,
                                 float* __restrict__ Srelu) {
    __shared__ float tile[32][33];
    int b = blockIdx.z;
    int n0 = blockIdx.x * 32, c0 = blockIdx.y * 32;
    int n = n0 + threadIdx.x, c = c0 + threadIdx.y;
    tile[threadIdx.y][threadIdx.x] = (n < NNODE) ? skip[(size_t)(b * NSKIPC + c) * NNODE + n] : 0.f;
    __syncthreads();
    int n2 = n0 + threadIdx.y, c2 = c0 + threadIdx.x;
    float bsum = 0.f;
#pragma unroll
    for (int l = 0; l < LL; l++) bsum += skp_b[l * 256 + c2];
    if (n2 < NNODE)
        Srelu[(size_t)(b * NNODE + n2) * NSKIPC + c2] =
            to_tf32(fmaxf(tile[threadIdx.x][threadIdx.y] + bsum, 0.f));
}

__global__ void k_headfinal(const float* __restrict__ H, const float* __restrict__ o1b,
                            const float* __restrict__ o2w, const float* __restrict__ o2b,
                            float* __restrict__ out) {
    int warp = threadIdx.x >> 5, lane = threadIdx.x & 31;
    int row = blockIdx.x * 4 + warp;
    if (row >= BB * NNODE) return;
    int b = row / NNODE, n = row % NNODE;
    const float* Hr = H + (size_t)row * NENDC;
    float h[16];
#pragma unroll
    for (int i = 0; i < 16; i++)
        h[i] = fmaxf(Hr[lane + i * 32] + o1b[lane + i * 32], 0.f);
#pragma unroll
    for (int p = 0; p < NPREDC; p++) {
        float acc = 0.f;
#pragma unroll
        for (int i = 0; i < 16; i++) acc += o2w[p * NENDC + lane + i * 32] * h[i];
#pragma unroll
        for (int off = 16; off; off >>= 1) acc += __shfl_down_sync(0xffffffffu, acc, off);
        if (lane == 0) out[(size_t)(b * NPREDC + p) * NNODE + n] = acc + o2b[p];
    }
}

// ---------------- host launcher ----------------
extern "C" void kernel_launch(void* const* d_in, const int* in_sizes, int n_in,
                              void* d_out, int out_size) {
    const float* inputs = (const float*)d_in[0];
    const float* factor = (const float*)d_in[1];
    const float* map_w  = (const float*)d_in[2];
    const float* map_b  = (const float*)d_in[3];
    const float* a1w    = (const float*)d_in[4];
    const float* a1b    = (const float*)d_in[5];
    const float* a2w    = (const float*)d_in[6];
    const float* a2b    = (const float*)d_in[7];
    const float* a3w    = (const float*)d_in[8];
    const float* a3b    = (const float*)d_in[9];
    const float* enter_w = (const float*)d_in[10];
    const float* enter_b = (const float*)d_in[11];
    const float* filt_w = (const float*)d_in[12];
    const float* filt_b = (const float*)d_in[13];
    const float* gate_w = (const float*)d_in[14];
    const float* gate_b = (const float*)d_in[15];
    const float* skp_w  = (const float*)d_in[16];
    const float* skp_b  = (const float*)d_in[17];
    const float* gc_w   = (const float*)d_in[18];
    const float* gc_b   = (const float*)d_in[19];
    const float* bn_g   = (const float*)d_in[20];
    const float* bn_b   = (const float*)d_in[21];
    const float* o1w    = (const float*)d_in[22];
    const float* o1b    = (const float*)d_in[23];
    const float* o2w    = (const float*)d_in[24];
    const float* o2b    = (const float*)d_in[25];

    cudaFuncSetAttribute(tgemm, cudaFuncAttributeMaxDynamicSharedMemorySize, TG_SMEM);
    cudaFuncSetAttribute(gfgemm, cudaFuncAttributeMaxDynamicSharedMemorySize, GF_SMEM);

    float *pScat, *pY, *pX0, *pX1, *pXG, *pXGcat, *pWcat, *pSkip, *pSrelu, *pO1T, *pStats, *pWgc;
    cudaGetSymbolAddress((void**)&pScat, g_Scat);
    cudaGetSymbolAddress((void**)&pY, g_Y);
    cudaGetSymbolAddress((void**)&pX0, g_X0);
    cudaGetSymbolAddress((void**)&pX1, g_X1);
    cudaGetSymbolAddress((void**)&pXG, g_XG);
    cudaGetSymbolAddress((void**)&pXGcat, g_XGcat);
    cudaGetSymbolAddress((void**)&pWcat, g_Wcat);
    cudaGetSymbolAddress((void**)&pSkip, g_skip);
    cudaGetSymbolAddress((void**)&pSrelu, g_Srelu);
    cudaGetSymbolAddress((void**)&pO1T, g_o1wT);
    cudaGetSymbolAddress((void**)&pStats, g_stats2);
    cudaGetSymbolAddress((void**)&pWgc, g_Wgc);

    float* out = (float*)d_out;
    const int ySize = BB * NPREDC * NNODE;
    const int supSize = 2 * NNODE * NNODE;
    int writeSup = (out_size >= ySize + supSize) ? 1 : 0;
    float* outSup = out + ySize;

    static const int Tin[LL] = {13, 12, 10, 9, 7, 6, 4, 3};
    static const int Dd[LL]  = {1, 2, 1, 2, 1, 2, 1, 2};
    static const int To[LL]  = {12, 10, 9, 7, 6, 4, 3, 1};

    k_tmp<<<dim3(TT, BB), 256>>>(inputs, factor);
    k_enter<<<dim3(4, RFh, BB), 128>>>(inputs, factor, enter_w, enter_b, pX0);
    k_prep<<<512, 256>>>(skp_w, o1w, gc_w);
    gfgemm<<<dim3((To[0] * NNODE + 127) / 128, BB), 256, GF_SMEM>>>(
        pX0, pXG, pXGcat, filt_w, filt_b, gate_w, gate_b,
        nullptr, 1.f, bn_g, bn_b, Tin[0], To[0], Dd[0], 0);
    k_pq<<<NNODE, 64>>>(factor, map_w, map_b, a1w, a1b);
    k_adjmlp<<<NNODE, 128>>>(a2w, a2b, a3w, a3b);
    k_softmax<<<2 * NNODE, 256>>>(outSup, writeSup);
    tgemm<<<dim3(4, 4, 2), 256, TG_SMEM>>>(pScat, pScat, pScat + 500, 500, 500, 500,
                                           2000, 2000, 2000, 1000, 1000, 1000, 1);

    float* Xc = pX0;
    float* Xn = pX1;
    for (int i = 0; i < LL - 1; i++) {
        int M = BB * 32 * To[i];
        tgemm<<<dim3(16, M / 128), 256, TG_SMEM>>>(pXG, pScat, pY, M, 2000, 500,
                                                   500, 2000, 2000, 0, 0, 0, 1);
        const float* stP = (i == 0) ? nullptr : (pStats + (i - 1) * 64);
        float cntP = (i == 0) ? 1.f : (float)(BB * To[i - 1] * NNODE);
        gc2gemm<<<dim3(4, To[i], BB), 256>>>(pY, pXG, Xc, Xn,
            pWgc + i * 5120, gc_b + i * 32,
            stP, cntP, bn_g + ((i > 0) ? (i - 1) : 0) * 32, bn_b + ((i > 0) ? (i - 1) : 0) * 32,
            pStats + i * 64, Tin[i], To[i], Dd[i]);
        int j = i + 1;
        gfgemm<<<dim3((To[j] * NNODE + 127) / 128, BB), 256, GF_SMEM>>>(
            Xn, pXG, pXGcat,
            filt_w + j * 2048, filt_b + j * 32, gate_w + j * 2048, gate_b + j * 32,
            pStats + i * 64, (float)(BB * To[i] * NNODE), bn_g + i * 32, bn_b + i * 32,
            Tin[j], To[j], Dd[j], j);
        float* t = Xc; Xc = Xn; Xn = t;
    }
    // skip = Wcat @ XGcat  (batched over b)
    tgemm<<<dim3(4, 2, BB), 256, TG_SMEM>>>(pWcat, pXGcat, pSkip, 256, NNODE, 256,
                                            256, NNODE, NNODE, 0, 256 * NNODE, 256 * NNODE, 0);
    // output head
    k_transpose_skip<<<dim3(16, 8, BB), dim3(32, 32)>>>(pSkip, skp_b, pSrelu);
    tgemm<<<dim3(4, 125), 256, TG_SMEM>>>(pSrelu, pO1T, pY, BB * NNODE, NENDC, NSKIPC,
                                          NSKIPC, NENDC, NENDC, 0, 0, 0, 0);
    k_headfinal<<<(BB * NNODE + 3) / 4, 128>>>(pY, o1b, o2w, o2b, out);
}

// round 16
// speedup vs baseline: 1.7043x; 1.0188x over previous
#include <cuda_runtime.h>
#include <math.h>
#include <stdint.h>

// ---------------- static problem config ----------------
#define BB 32
#define TT 12
#define NNODE 500
#define NSKIPC 256
#define NENDC 512
#define NPREDC 12
#define LL 8
#define RFh 13
#define BN_EPS 1e-5f

typedef unsigned long long ull;
typedef unsigned int u32;

__device__ __forceinline__ float to_tf32(float x) {
    u32 r; asm("cvt.rna.tf32.f32 %0, %1;" : "=r"(r) : "f"(x));
    return __uint_as_float(r);
}
__device__ __forceinline__ void mma_tf32(float* c, const u32* a, const u32* b) {
    asm("mma.sync.aligned.m16n8k8.row.col.f32.tf32.tf32.f32 "
        "{%0,%1,%2,%3},{%4,%5,%6,%7},{%8,%9},{%0,%1,%2,%3};"
        : "+f"(c[0]), "+f"(c[1]), "+f"(c[2]), "+f"(c[3])
        : "r"(a[0]), "r"(a[1]), "r"(a[2]), "r"(a[3]), "r"(b[0]), "r"(b[1]));
}
__device__ __forceinline__ void cp16(float* dst, const float* src, int bytes) {
    u32 d = (u32)__cvta_generic_to_shared(dst);
    asm volatile("cp.async.cg.shared.global [%0], [%1], 16, %2;\n"
                 :: "r"(d), "l"(src), "r"(bytes));
}

// ---------------- device scratch ----------------
__device__ float g_P[NNODE * 64];
__device__ float g_Q[NNODE * 64];
__device__ float g_eraw[2 * NNODE * NNODE];
__device__ float g_Scat[NNODE * 2000];            // tf32-rounded supports [A0|A0^2|A1|A1^2]
__device__ float g_tmp[BB * TT * 32 * 2];
__device__ float g_X0[BB * 32 * RFh * NNODE];     // tf32-rounded
__device__ float g_X1[BB * 32 * RFh * NNODE];     // tf32-rounded
__device__ float g_XG[BB * 32 * 12 * NNODE];      // tf32-rounded gated outputs
__device__ float g_Y[12288 * 2000];               // tf32-rounded diffusion outputs
__device__ float g_XGcat[BB * 256 * NNODE];       // tf32-rounded last-t gated slices
__device__ float g_Wcat[256 * 256];               // tf32-rounded
__device__ float g_skip[BB * NSKIPC * NNODE];
__device__ float g_Srelu[BB * NNODE * NSKIPC];    // tf32-rounded
__device__ float g_o1wT[NSKIPC * NENDC];          // tf32-rounded
__device__ float g_stats2[7 * 64];                // per-layer BN stats accumulators (atomic)
__device__ float g_Wgc[7 * 32 * 160];             // tf32 gc weights [layer][o][k]

// ---------------- fused one-time prep ----------------
__global__ void k_prep(const float* __restrict__ skp_w, const float* __restrict__ o1w,
                       const float* __restrict__ gcw) {
    int idx = blockIdx.x * 256 + threadIdx.x;
    if (idx < 7 * 64) g_stats2[idx] = 0.f;
    if (idx < 65536) {
        int o = idx >> 8, r = idx & 255, l = r >> 5, c = r & 31;
        g_Wcat[idx] = to_tf32(skp_w[l * 8192 + o * 32 + c]);
    }
    if (idx < 131072) {
        int h = idx / NSKIPC, c = idx % NSKIPC;
        g_o1wT[c * NENDC + h] = to_tf32(o1w[idx]);
    }
    if (idx < 7 * 32 * 160) {
        int l = idx / 5120, rem = idx % 5120, o = rem / 160, k = rem % 160;
        float w = (k < 128) ? gcw[l * 5120 + o * 160 + 32 + k]
                            : gcw[l * 5120 + o * 160 + (k - 128)];
        g_Wgc[idx] = to_tf32(w);
    }
}

__device__ __forceinline__ int wfrow(int o) {   // o: 0-31 filter ch, 32-63 gate ch
    int oo = o & 31;
    return ((oo >> 3) << 4) + (oo & 7) + ((o < 32) ? 0 : 8);
}

// ---------------- adjacency ----------------
__global__ void k_pq(const float* __restrict__ factor, const float* __restrict__ map_w,
                     const float* __restrict__ map_b,
                     const float* __restrict__ a1w, const float* __restrict__ a1b) {
    __shared__ float vv[32];
    int j = blockIdx.x, h = threadIdx.x;
    if (h < 32) {
        float acc = map_b[h];
#pragma unroll
        for (int u = 0; u < 32; u++) acc += factor[j * 32 + u] * map_w[u * 32 + h];
        vv[h] = fmaxf(acc, 0.f);
    }
    __syncthreads();
    float p = 0.f, q = a1b[h];
#pragma unroll
    for (int d = 0; d < 32; d++) {
        p += vv[d] * a1w[d * 64 + h];
        q += vv[d] * a1w[(32 + d) * 64 + h];
    }
    g_P[j * 64 + h] = p;
    g_Q[j * 64 + h] = q;
}

__global__ void k_adjmlp(const float* __restrict__ a2w, const float* __restrict__ a2b,
                         const float* __restrict__ a3w, const float* __restrict__ a3b) {
    __shared__ float Pt[128][65];
    __shared__ __align__(16) float sA2[64][32];
    __shared__ float sQ[64];
    __shared__ float sA3[64];
    __shared__ float sA2b[32];
    __shared__ float sA3b[2];
    int i = blockIdx.x, tid = threadIdx.x;
    for (int k = tid; k < 64 * 32; k += 128) sA2[k / 32][k % 32] = a2w[k];
    if (tid < 64) { sQ[tid] = g_Q[i * 64 + tid]; sA3[tid] = a3w[tid]; }
    if (tid < 32) sA2b[tid] = a2b[tid];
    if (tid < 2) sA3b[tid] = a3b[tid];
    for (int j0 = 0; j0 < NNODE; j0 += 128) {
        __syncthreads();
        int cnt = min(128, NNODE - j0);
        for (int k = tid; k < cnt * 64; k += 128)
            Pt[k / 64][k % 64] = g_P[(j0 + (k / 64)) * 64 + (k % 64)];
        __syncthreads();
        if (tid < cnt) {
            int j = j0 + tid;
            float h1[64];
#pragma unroll
            for (int h = 0; h < 64; h++) h1[h] = fmaxf(Pt[tid][h] + sQ[h], 0.f);
            float e0 = sA3b[0], e1 = sA3b[1];
#pragma unroll
            for (int c = 0; c < 32; c++) {
                float acc = sA2b[c];
#pragma unroll
                for (int h = 0; h < 64; h++) acc += h1[h] * sA2[h][c];
                acc = fmaxf(acc, 0.f);
                e0 += acc * sA3[c * 2];
                e1 += acc * sA3[c * 2 + 1];
            }
            g_eraw[i * NNODE + j] = e0;
            g_eraw[NNODE * NNODE + i * NNODE + j] = e1;
        }
    }
}

__global__ void k_softmax(float* __restrict__ outSup, int writeSup) {
    int bid = blockIdx.x;
    int e = bid / NNODE, i = bid % NNODE;
    const float* row = g_eraw + e * NNODE * NNODE + i * NNODE;
    __shared__ float red[256];
    int tid = threadIdx.x;
    float m = -1e30f;
    for (int j = tid; j < NNODE; j += 256) m = fmaxf(m, row[j]);
    red[tid] = m; __syncthreads();
    for (int s = 128; s > 0; s >>= 1) { if (tid < s) red[tid] = fmaxf(red[tid], red[tid + s]); __syncthreads(); }
    m = red[0]; __syncthreads();
    float sum = 0.f;
    for (int j = tid; j < NNODE; j += 256) sum += expf(row[j] - m);
    red[tid] = sum; __syncthreads();
    for (int s = 128; s > 0; s >>= 1) { if (tid < s) red[tid] += red[tid + s]; __syncthreads(); }
    float inv = 1.f / red[0];
    for (int j = tid; j < NNODE; j += 256) {
        float p = expf(row[j] - m) * inv;
        if (j == i) p = fmaxf(p, 1.f);
        g_Scat[i * 2000 + e * 1000 + j] = to_tf32(p);
        if (writeSup) outSup[(e * NNODE + i) * NNODE + j] = p;
    }
}

// ---------------- tf32 tensor GEMM: cp.async 4-stage, raw-bit tf32 ----------------
#define TG_SSZ 4736
#define TG_NST 4
#define TG_SMEM (TG_NST * TG_SSZ * 4)

__device__ __forceinline__ void tg_stage(float* As_s, float* Bs_s,
                                         const float* A, const float* B,
                                         int m0, int n0, int k0,
                                         int M, int N, int K, int lda, int ldb, int tid) {
#pragma unroll
    for (int i = 0; i < 2; i++) {
        int ch = tid + i * 256;
        int row = ch >> 2, kq = (ch & 3) * 4;
        int c = k0 + kq;
        int bytes = 0;
        if (m0 + row < M) {
            int rem = (K - c) * 4;
            bytes = rem > 16 ? 16 : (rem > 0 ? rem : 0);
        }
        cp16(As_s + row * 20 + kq, A + (size_t)(m0 + row) * lda + c, bytes);
    }
#pragma unroll
    for (int i = 0; i < 2; i++) {
        int ch = tid + i * 256;
        int kr = ch >> 5, nq = (ch & 31) * 4;
        int col = n0 + nq;
        int bytes = 0;
        if (k0 + kr < K) {
            int rem = (N - col) * 4;
            bytes = rem > 16 ? 16 : (rem > 0 ? rem : 0);
        }
        cp16(Bs_s + kr * 136 + nq, B + (size_t)(k0 + kr) * ldb + col, bytes);
    }
}

__global__ __launch_bounds__(256, 2)
void tgemm(const float* __restrict__ A, const float* __restrict__ B, float* __restrict__ C,
           int M, int N, int K, int lda, int ldb, int ldc,
           int sA, int sB, int sC, int roundC) {
    extern __shared__ float sdyn[];
    A += (size_t)blockIdx.z * sA;
    B += (size_t)blockIdx.z * sB;
    C += (size_t)blockIdx.z * sC;
    int tid = threadIdx.x;
    int m0 = blockIdx.y * 128, n0 = blockIdx.x * 128;
    int lane = tid & 31, wid = tid >> 5;
    int wm = wid & 1, wn = wid >> 1;
    int gid = lane >> 2, tig = lane & 3;

    float acc[4][4][4];
#pragma unroll
    for (int mi = 0; mi < 4; mi++)
#pragma unroll
        for (int ni = 0; ni < 4; ni++)
#pragma unroll
            for (int r = 0; r < 4; r++) acc[mi][ni][r] = 0.f;

    int nkt = (K + 15) / 16;

    int pre = nkt < 3 ? nkt : 3;
    for (int s = 0; s < pre; s++) {
        tg_stage(sdyn + s * TG_SSZ, sdyn + s * TG_SSZ + 2560, A, B,
                 m0, n0, s * 16, M, N, K, lda, ldb, tid);
        asm volatile("cp.async.commit_group;");
    }
    if (pre == 3)      asm volatile("cp.async.wait_group 2;");
    else if (pre == 2) asm volatile("cp.async.wait_group 1;");
    else               asm volatile("cp.async.wait_group 0;");
    __syncthreads();

    for (int kt = 0; kt < nkt; kt++) {
        if (kt + 3 < nkt) {
            int s = (kt + 3) & (TG_NST - 1);
            tg_stage(sdyn + s * TG_SSZ, sdyn + s * TG_SSZ + 2560, A, B,
                     m0, n0, (kt + 3) * 16, M, N, K, lda, ldb, tid);
            asm volatile("cp.async.commit_group;");
        }
        const float* As_s = sdyn + (kt & (TG_NST - 1)) * TG_SSZ;
        const float* Bs_s = As_s + 2560;
#pragma unroll
        for (int ks = 0; ks < 16; ks += 8) {
            u32 af[4][4];
            u32 bf[4][2];
#pragma unroll
            for (int mi = 0; mi < 4; mi++) {
                int mb = wm * 64 + mi * 16 + gid;
                af[mi][0] = __float_as_uint(As_s[mb * 20 + ks + tig]);
                af[mi][1] = __float_as_uint(As_s[(mb + 8) * 20 + ks + tig]);
                af[mi][2] = __float_as_uint(As_s[mb * 20 + ks + tig + 4]);
                af[mi][3] = __float_as_uint(As_s[(mb + 8) * 20 + ks + tig + 4]);
            }
#pragma unroll
            for (int ni = 0; ni < 4; ni++) {
                int nb = wn * 32 + ni * 8 + gid;
                bf[ni][0] = __float_as_uint(Bs_s[(ks + tig) * 136 + nb]);
                bf[ni][1] = __float_as_uint(Bs_s[(ks + tig + 4) * 136 + nb]);
            }
#pragma unroll
            for (int mi = 0; mi < 4; mi++)
#pragma unroll
                for (int ni = 0; ni < 4; ni++)
                    mma_tf32(acc[mi][ni], af[mi], bf[ni]);
        }
        if (kt + 1 < nkt) {
            int after = nkt - kt - 2;
            if (after >= 2)      asm volatile("cp.async.wait_group 2;");
            else if (after == 1) asm volatile("cp.async.wait_group 1;");
            else                 asm volatile("cp.async.wait_group 0;");
        }
        __syncthreads();
    }

#pragma unroll
    for (int mi = 0; mi < 4; mi++) {
        int r0 = m0 + wm * 64 + mi * 16 + gid;
        int r1 = r0 + 8;
#pragma unroll
        for (int ni = 0; ni < 4; ni++) {
            int cc = n0 + wn * 32 + ni * 8 + tig * 2;
            float c0 = acc[mi][ni][0], c1 = acc[mi][ni][1];
            float c2 = acc[mi][ni][2], c3 = acc[mi][ni][3];
            if (roundC) { c0 = to_tf32(c0); c1 = to_tf32(c1); c2 = to_tf32(c2); c3 = to_tf32(c3); }
            if (r0 < M) {
                if (cc + 1 < N) *(float2*)(C + (size_t)r0 * ldc + cc) = make_float2(c0, c1);
                else if (cc < N) C[(size_t)r0 * ldc + cc] = c0;
            }
            if (r1 < M) {
                if (cc + 1 < N) *(float2*)(C + (size_t)r1 * ldc + cc) = make_float2(c2, c3);
                else if (cc < N) C[(size_t)r1 * ldc + cc] = c2;
            }
        }
    }
}

// ---------------- gated conv GEMM v4: cp.async staging + 4x parallel fusion ----------------
// X pre-rounded to tf32. dyn smem: Bs[64][136] then sWf[64][68]
#define GF_SMEM ((64 * 136 + 64 * 68) * 4)

__global__ __launch_bounds__(256)
void gfgemm(const float* __restrict__ X, float* __restrict__ XG, float* __restrict__ XGcat,
            const float* __restrict__ fw, const float* __restrict__ fb,
            const float* __restrict__ gw, const float* __restrict__ gb,
            const float* __restrict__ stats, float cnt,
            const float* __restrict__ bng, const float* __restrict__ bnb,
            int Tin, int Tout, int dd, int layer) {
    extern __shared__ float sm[];
    float* Bs = sm;                    // [64][136]
    float* sWf = sm + 64 * 136;        // [64][68]
    __shared__ float sab[64], sbf[64];
    int tid = threadIdx.x;
    int b = blockIdx.y;
    int n0 = blockIdx.x * 128;
    int ToutN = Tout * NNODE;
    int TinN = Tin * NNODE;
    const float* Xb = X + (size_t)b * 32 * TinN;

    int lane = tid & 31, wid = tid >> 5;
    int wm = wid & 3, wn = wid >> 2;
    int gid = lane >> 2, tig = lane & 3;

    // issue async B staging first (raw bits; X already tf32)
    {
        int lr = tid >> 2, lq = tid & 3;
        size_t rbase = (size_t)(lr & 31) * TinN + (size_t)(lr >> 5) * (dd * NNODE);
        const float* src = Xb + rbase + n0;
#pragma unroll
        for (int i = 0; i < 8; i++) {
            int col = (lq + i * 4) * 4;
            int gcol = n0 + col;
            int rem = (ToutN - gcol) * 4;
            int bytes = rem > 16 ? 16 : (rem > 0 ? rem : 0);
            cp16(Bs + lr * 136 + col, src + col, bytes);
        }
        asm volatile("cp.async.commit_group;");
    }
    // (a, sh) from stats slot + bias init
    if (tid < 64) sbf[tid] = (tid < 32) ? fb[tid] : gb[tid & 31];
    if (tid < 32) {
        float a = 1.f, sh = 0.f;
        if (stats) {
            float mean = stats[tid] / cnt;
            float var = stats[32 + tid] / cnt - mean * mean;
            a = bng[tid] * rsqrtf(var + BN_EPS);
            sh = bnb[tid] - mean * a;
        }
        sab[tid] = a; sab[32 + tid] = sh;
    }
    __syncthreads();   // sab, sbf visible
    // fuse weights: 256 threads, o = tid&63, 8 channels each
    {
        int o = tid & 63, cg = tid >> 6;
        int oo = o & 31;
        const float* wsrc = (o < 32) ? fw : gw;
        int row = wfrow(o);
        float bsum = 0.f;
#pragma unroll
        for (int cc = 0; cc < 8; cc++) {
            int c = cg * 8 + cc;
            float a = sab[c], bb = sab[32 + c];
            float w0 = wsrc[oo * 64 + c * 2 + 0];
            float w1 = wsrc[oo * 64 + c * 2 + 1];
            sWf[row * 68 + c] = to_tf32(w0 * a);
            sWf[row * 68 + 32 + c] = to_tf32(w1 * a);
            bsum += (w0 + w1) * bb;
        }
        atomicAdd(&sbf[o], bsum);
    }
    asm volatile("cp.async.wait_group 0;");
    __syncthreads();   // sWf, sbf, Bs visible

    u32 af[8][4];
    {
        int r0 = wm * 16 + gid, r1 = r0 + 8;
#pragma unroll
        for (int ks = 0; ks < 8; ks++) {
            af[ks][0] = __float_as_uint(sWf[r0 * 68 + ks * 8 + tig]);
            af[ks][1] = __float_as_uint(sWf[r1 * 68 + ks * 8 + tig]);
            af[ks][2] = __float_as_uint(sWf[r0 * 68 + ks * 8 + tig + 4]);
            af[ks][3] = __float_as_uint(sWf[r1 * 68 + ks * 8 + tig + 4]);
        }
    }

    float acc[8][4];
#pragma unroll
    for (int ni = 0; ni < 8; ni++)
#pragma unroll
        for (int r = 0; r < 4; r++) acc[ni][r] = 0.f;

#pragma unroll
    for (int ks = 0; ks < 8; ks++) {
#pragma unroll
        for (int ni = 0; ni < 8; ni++) {
            int nb = wn * 64 + ni * 8 + gid;
            u32 bfr[2] = { __float_as_uint(Bs[(ks * 8 + tig) * 136 + nb]),
                           __float_as_uint(Bs[(ks * 8 + tig + 4) * 136 + nb]) };
            mma_tf32(acc[ni], af[ks], bfr);
        }
    }

    {
        int c = wm * 8 + gid;
        float bff = sbf[c], bfg = sbf[32 + c];
        size_t xgbase = (size_t)(b * 32 + c) * ToutN;
        size_t catbase = ((size_t)b * 256 + layer * 32 + c) * NNODE;
        int lastBase = (Tout - 1) * NNODE;
#pragma unroll
        for (int ni = 0; ni < 8; ni++) {
            int gcol = n0 + wn * 64 + ni * 8 + tig * 2;
            if (gcol >= ToutN) continue;
            float f0 = acc[ni][0] + bff, f1 = acc[ni][1] + bff;
            float g0 = acc[ni][2] + bfg, g1 = acc[ni][3] + bfg;
            float v0 = to_tf32(tanhf(f0) * (1.f / (1.f + expf(-g0))));
            float v1 = to_tf32(tanhf(f1) * (1.f / (1.f + expf(-g1))));
            *(float2*)&XG[xgbase + gcol] = make_float2(v0, v1);
            if (gcol >= lastBase) {
                XGcat[catbase + (gcol - lastBase)] = v0;
                XGcat[catbase + (gcol - lastBase) + 1] = v1;
            }
        }
    }
}

// ---------------- gc 1x1 conv GEMM: double-buffered cp.async staging ----------------
__global__ __launch_bounds__(256)
void gc2gemm(const float* __restrict__ Y, const float* __restrict__ XG,
             const float* __restrict__ Xc, float* __restrict__ Xn,
             const float* __restrict__ Wgc, const float* __restrict__ gcb,
             const float* __restrict__ statsPrev, float cntPrev,
             const float* __restrict__ bngP, const float* __restrict__ bnbP,
             float* __restrict__ statsOut,
             int Tin, int Tout, int dd) {
    __shared__ __align__(16) float Bs[2][32][136];
    __shared__ float sbias[32], sA[32], sBsh[32];
    __shared__ float sSum[32], sSq[32];
    int tid = threadIdx.x;
    int b = blockIdx.z, t = blockIdx.y, n0 = blockIdx.x * 128;
    int lane = tid & 31, wid = tid >> 5;
    int wm = wid & 1, wn = wid >> 1;
    int gid = lane >> 2, tig = lane & 3;
    int lr = tid >> 3, lq = tid & 7;

    // row source pointer for a given K-chunk
    auto rowsrc = [&](int kc) -> const float* {
        int k = kc * 32 + lr;
        if (k < 128)
            return Y + ((size_t)(b * 32 + (k & 31)) * Tout + t) * 2000 + (k >> 5) * 500;
        return XG + ((size_t)(b * 32 + (k - 128)) * Tout + t) * NNODE;
    };
    auto stage = [&](int kc, int buf) {
        const float* src = rowsrc(kc);
#pragma unroll
        for (int i = 0; i < 4; i++) {
            int col = lq * 4 + i * 32;
            int gcol = n0 + col;
            int rem = (NNODE - gcol) * 4;
            int bytes = rem > 16 ? 16 : (rem > 0 ? rem : 0);
            cp16(&Bs[buf][lr][col], src + gcol, bytes);
        }
        asm volatile("cp.async.commit_group;");
    };

    stage(0, 0);
    stage(1, 1);
    if (tid < 32) {
        sbias[tid] = gcb[tid];
        float a = 1.f, sh = 0.f;
        if (statsPrev) {
            float mean = statsPrev[tid] / cntPrev;
            float var = statsPrev[32 + tid] / cntPrev - mean * mean;
            a = bngP[tid] * rsqrtf(var + BN_EPS);
            sh = bnbP[tid] - mean * a;
        }
        sA[tid] = a;
        sBsh[tid] = sh;
        sSum[tid] = 0.f;
        sSq[tid] = 0.f;
    }

    float acc[4][4];
#pragma unroll
    for (int ni = 0; ni < 4; ni++)
#pragma unroll
        for (int r = 0; r < 4; r++) acc[ni][r] = 0.f;

    for (int kc = 0; kc < 5; kc++) {
        if (kc < 4) asm volatile("cp.async.wait_group 1;");
        else        asm volatile("cp.async.wait_group 0;");
        __syncthreads();
        int buf = kc & 1;
#pragma unroll
        for (int s = 0; s < 4; s++) {
            int ka = kc * 32 + s * 8;
            const float* W0 = Wgc + (size_t)(wm * 16 + gid) * 160 + ka + tig;
            u32 af[4];
            af[0] = __float_as_uint(W0[0]);
            af[1] = __float_as_uint(W0[8 * 160]);
            af[2] = __float_as_uint(W0[4]);
            af[3] = __float_as_uint(W0[8 * 160 + 4]);
#pragma unroll
            for (int ni = 0; ni < 4; ni++) {
                int nb = wn * 32 + ni * 8 + gid;
                u32 bfr[2] = { __float_as_uint(Bs[buf][s * 8 + tig][nb]),
                               __float_as_uint(Bs[buf][s * 8 + tig + 4][nb]) };
                mma_tf32(acc[ni], af, bfr);
            }
        }
        __syncthreads();    // done reading buf before restaging it
        if (kc + 2 < 5) stage(kc + 2, buf);
    }

    int r0 = wm * 16 + gid, r1 = r0 + 8;
    float bias0 = sbias[r0], a0 = sA[r0], sh0 = sBsh[r0];
    float bias1 = sbias[r1], a1 = sA[r1], sh1 = sBsh[r1];
    size_t xcb0 = ((size_t)(b * 32 + r0) * Tin + t + dd) * NNODE;
    size_t xcb1 = ((size_t)(b * 32 + r1) * Tin + t + dd) * NNODE;
    size_t xnb0 = ((size_t)(b * 32 + r0) * Tout + t) * NNODE;
    size_t xnb1 = ((size_t)(b * 32 + r1) * Tout + t) * NNODE;
    float lS0 = 0.f, lQ0 = 0.f, lS1 = 0.f, lQ1 = 0.f;
#pragma unroll
    for (int ni = 0; ni < 4; ni++) {
        int cc = n0 + wn * 32 + ni * 8 + tig * 2;
        if (cc < NNODE) {
            float2 rv0 = *(const float2*)&Xc[xcb0 + cc];
            float v00 = to_tf32(acc[ni][0] + bias0 + rv0.x * a0 + sh0);
            float v01 = to_tf32(acc[ni][1] + bias0 + rv0.y * a0 + sh0);
            *(float2*)&Xn[xnb0 + cc] = make_float2(v00, v01);
            lS0 += v00 + v01; lQ0 += v00 * v00 + v01 * v01;
            float2 rv1 = *(const float2*)&Xc[xcb1 + cc];
            float v10 = to_tf32(acc[ni][2] + bias1 + rv1.x * a1 + sh1);
            float v11 = to_tf32(acc[ni][3] + bias1 + rv1.y * a1 + sh1);
            *(float2*)&Xn[xnb1 + cc] = make_float2(v10, v11);
            lS1 += v10 + v11; lQ1 += v10 * v10 + v11 * v11;
        }
    }
#pragma unroll
    for (int off = 2; off; off >>= 1) {
        lS0 += __shfl_down_sync(0xffffffffu, lS0, off, 4);
        lQ0 += __shfl_down_sync(0xffffffffu, lQ0, off, 4);
        lS1 += __shfl_down_sync(0xffffffffu, lS1, off, 4);
        lQ1 += __shfl_down_sync(0xffffffffu, lQ1, off, 4);
    }
    if (tig == 0) {
        atomicAdd(&sSum[r0], lS0); atomicAdd(&sSq[r0], lQ0);
        atomicAdd(&sSum[r1], lS1); atomicAdd(&sSq[r1], lQ1);
    }
    __syncthreads();
    if (tid < 64) {
        int o = tid & 31;
        atomicAdd(&statsOut[tid], (tid < 32) ? sSum[o] : sSq[o]);
    }
}

// ---------------- input split + enter ----------------
__global__ void k_tmp(const float* __restrict__ inputs, const float* __restrict__ factor) {
    int t = blockIdx.x, b = blockIdx.y, tid = threadIdx.x;
    int o = tid >> 2, r = tid & 3;
    int u = o >> 1, f = o & 1;
    const float* inp = inputs + ((size_t)(b * TT + t) * NNODE) * 2 + f;
    float acc = 0.f;
    for (int n = r; n < NNODE; n += 4) acc += inp[n * 2] * factor[n * 32 + u];
    acc += __shfl_down_sync(0xffffffffu, acc, 2);
    acc += __shfl_down_sync(0xffffffffu, acc, 1);
    if (r == 0) g_tmp[(b * TT + t) * 64 + o] = acc;
}

__global__ void k_enter(const float* __restrict__ inputs, const float* __restrict__ factor,
                        const float* __restrict__ ew, const float* __restrict__ eb,
                        float* __restrict__ X0) {
    __shared__ float sw[128], sb[32], stmp[64];
    int b = blockIdx.z, tp = blockIdx.y;
    int tid = threadIdx.x;
    if (tid < 128) sw[tid] = ew[tid];
    if (tid < 32) sb[tid] = eb[tid];
    if (tp > 0 && tid < 64) stmp[tid] = g_tmp[(b * TT + (tp - 1)) * 64 + tid];
    __syncthreads();
    int n = blockIdx.x * 128 + tid;
    if (n >= NNODE) return;
    if (tp == 0) {
#pragma unroll
        for (int o = 0; o < 32; o++)
            X0[((size_t)(b * 32 + o) * RFh + 0) * NNODE + n] = to_tf32(sb[o]);
    } else {
        int t = tp - 1;
        float s0 = 0.f, s1 = 0.f;
#pragma unroll
        for (int u = 0; u < 32; u++) {
            float fv = factor[n * 32 + u];
            s0 += fv * stmp[u * 2];
            s1 += fv * stmp[u * 2 + 1];
        }
        float i0 = inputs[((size_t)(b * TT + t) * NNODE + n) * 2 + 0];
        float i1 = inputs[((size_t)(b * TT + t) * NNODE + n) * 2 + 1];
        float r0 = i0 - s0, r1 = i1 - s1;
#pragma unroll
        for (int o = 0; o < 32; o++) {
            float v = sb[o] + sw[o * 4] * s0 + sw[o * 4 + 1] * s1 + sw[o * 4 + 2] * r0 + sw[o * 4 + 3] * r1;
            X0[((size_t)(b * 32 + o) * RFh + tp) * NNODE + n] = to_tf32(v);
        }
    }
}

// ---------------- output head ----------------
__global__ void k_transpose_skip(const float* __restrict__ skip, const float* __restrict__ skp_b,
                                 float* __restrict__ Srelu) {
    __shared__ float tile[32][33];
    int b = blockIdx.z;
    int n0 = blockIdx.x * 32, c0 = blockIdx.y * 32;
    int n = n0 + threadIdx.x, c = c0 + threadIdx.y;
    tile[threadIdx.y][threadIdx.x] = (n < NNODE) ? skip[(size_t)(b * NSKIPC + c) * NNODE + n] : 0.f;
    __syncthreads();
    int n2 = n0 + threadIdx.y, c2 = c0 + threadIdx.x;
    float bsum = 0.f;
#pragma unroll
    for (int l = 0; l < LL; l++) bsum += skp_b[l * 256 + c2];
    if (n2 < NNODE)
        Srelu[(size_t)(b * NNODE + n2) * NSKIPC + c2] =
            to_tf32(fmaxf(tile[threadIdx.x][threadIdx.y] + bsum, 0.f));
}

__global__ void k_headfinal(const float* __restrict__ H, const float* __restrict__ o1b,
                            const float* __restrict__ o2w, const float* __restrict__ o2b,
                            float* __restrict__ out) {
    int warp = threadIdx.x >> 5, lane = threadIdx.x & 31;
    int row = blockIdx.x * 4 + warp;
    if (row >= BB * NNODE) return;
    int b = row / NNODE, n = row % NNODE;
    const float* Hr = H + (size_t)row * NENDC;
    float h[16];
#pragma unroll
    for (int i = 0; i < 16; i++)
        h[i] = fmaxf(Hr[lane + i * 32] + o1b[lane + i * 32], 0.f);
#pragma unroll
    for (int p = 0; p < NPREDC; p++) {
        float acc = 0.f;
#pragma unroll
        for (int i = 0; i < 16; i++) acc += o2w[p * NENDC + lane + i * 32] * h[i];
#pragma unroll
        for (int off = 16; off; off >>= 1) acc += __shfl_down_sync(0xffffffffu, acc, off);
        if (lane == 0) out[(size_t)(b * NPREDC + p) * NNODE + n] = acc + o2b[p];
    }
}

// ---------------- host launcher ----------------
extern "C" void kernel_launch(void* const* d_in, const int* in_sizes, int n_in,
                              void* d_out, int out_size) {
    const float* inputs = (const float*)d_in[0];
    const float* factor = (const float*)d_in[1];
    const float* map_w  = (const float*)d_in[2];
    const float* map_b  = (const float*)d_in[3];
    const float* a1w    = (const float*)d_in[4];
    const float* a1b    = (const float*)d_in[5];
    const float* a2w    = (const float*)d_in[6];
    const float* a2b    = (const float*)d_in[7];
    const float* a3w    = (const float*)d_in[8];
    const float* a3b    = (const float*)d_in[9];
    const float* enter_w = (const float*)d_in[10];
    const float* enter_b = (const float*)d_in[11];
    const float* filt_w = (const float*)d_in[12];
    const float* filt_b = (const float*)d_in[13];
    const float* gate_w = (const float*)d_in[14];
    const float* gate_b = (const float*)d_in[15];
    const float* skp_w  = (const float*)d_in[16];
    const float* skp_b  = (const float*)d_in[17];
    const float* gc_w   = (const float*)d_in[18];
    const float* gc_b   = (const float*)d_in[19];
    const float* bn_g   = (const float*)d_in[20];
    const float* bn_b   = (const float*)d_in[21];
    const float* o1w    = (const float*)d_in[22];
    const float* o1b    = (const float*)d_in[23];
    const float* o2w    = (const float*)d_in[24];
    const float* o2b    = (const float*)d_in[25];

    cudaFuncSetAttribute(tgemm, cudaFuncAttributeMaxDynamicSharedMemorySize, TG_SMEM);
    cudaFuncSetAttribute(gfgemm, cudaFuncAttributeMaxDynamicSharedMemorySize, GF_SMEM);

    float *pScat, *pY, *pX0, *pX1, *pXG, *pXGcat, *pWcat, *pSkip, *pSrelu, *pO1T, *pStats, *pWgc;
    cudaGetSymbolAddress((void**)&pScat, g_Scat);
    cudaGetSymbolAddress((void**)&pY, g_Y);
    cudaGetSymbolAddress((void**)&pX0, g_X0);
    cudaGetSymbolAddress((void**)&pX1, g_X1);
    cudaGetSymbolAddress((void**)&pXG, g_XG);
    cudaGetSymbolAddress((void**)&pXGcat, g_XGcat);
    cudaGetSymbolAddress((void**)&pWcat, g_Wcat);
    cudaGetSymbolAddress((void**)&pSkip, g_skip);
    cudaGetSymbolAddress((void**)&pSrelu, g_Srelu);
    cudaGetSymbolAddress((void**)&pO1T, g_o1wT);
    cudaGetSymbolAddress((void**)&pStats, g_stats2);
    cudaGetSymbolAddress((void**)&pWgc, g_Wgc);

    float* out = (float*)d_out;
    const int ySize = BB * NPREDC * NNODE;
    const int supSize = 2 * NNODE * NNODE;
    int writeSup = (out_size >= ySize + supSize) ? 1 : 0;
    float* outSup = out + ySize;

    static const int Tin[LL] = {13, 12, 10, 9, 7, 6, 4, 3};
    static const int Dd[LL]  = {1, 2, 1, 2, 1, 2, 1, 2};
    static const int To[LL]  = {12, 10, 9, 7, 6, 4, 3, 1};

    k_tmp<<<dim3(TT, BB), 256>>>(inputs, factor);
    k_enter<<<dim3(4, RFh, BB), 128>>>(inputs, factor, enter_w, enter_b, pX0);
    k_prep<<<512, 256>>>(skp_w, o1w, gc_w);
    gfgemm<<<dim3((To[0] * NNODE + 127) / 128, BB), 256, GF_SMEM>>>(
        pX0, pXG, pXGcat, filt_w, filt_b, gate_w, gate_b,
        nullptr, 1.f, bn_g, bn_b, Tin[0], To[0], Dd[0], 0);
    k_pq<<<NNODE, 64>>>(factor, map_w, map_b, a1w, a1b);
    k_adjmlp<<<NNODE, 128>>>(a2w, a2b, a3w, a3b);
    k_softmax<<<2 * NNODE, 256>>>(outSup, writeSup);
    tgemm<<<dim3(4, 4, 2), 256, TG_SMEM>>>(pScat, pScat, pScat + 500, 500, 500, 500,
                                           2000, 2000, 2000, 1000, 1000, 1000, 1);

    float* Xc = pX0;
    float* Xn = pX1;
    for (int i = 0; i < LL - 1; i++) {
        int M = BB * 32 * To[i];
        tgemm<<<dim3(16, M / 128), 256, TG_SMEM>>>(pXG, pScat, pY, M, 2000, 500,
                                                   500, 2000, 2000, 0, 0, 0, 1);
        const float* stP = (i == 0) ? nullptr : (pStats + (i - 1) * 64);
        float cntP = (i == 0) ? 1.f : (float)(BB * To[i - 1] * NNODE);
        gc2gemm<<<dim3(4, To[i], BB), 256>>>(pY, pXG, Xc, Xn,
            pWgc + i * 5120, gc_b + i * 32,
            stP, cntP, bn_g + ((i > 0) ? (i - 1) : 0) * 32, bn_b + ((i > 0) ? (i - 1) : 0) * 32,
            pStats + i * 64, Tin[i], To[i], Dd[i]);
        int j = i + 1;
        gfgemm<<<dim3((To[j] * NNODE + 127) / 128, BB), 256, GF_SMEM>>>(
            Xn, pXG, pXGcat,
            filt_w + j * 2048, filt_b + j * 32, gate_w + j * 2048, gate_b + j * 32,
            pStats + i * 64, (float)(BB * To[i] * NNODE), bn_g + i * 32, bn_b + i * 32,
            Tin[j], To[j], Dd[j], j);
        float* t = Xc; Xc = Xn; Xn = t;
    }
    // skip = Wcat @ XGcat  (batched over b)
    tgemm<<<dim3(4, 2, BB), 256, TG_SMEM>>>(pWcat, pXGcat, pSkip, 256, NNODE, 256,
                                            256, NNODE, NNODE, 0, 256 * NNODE, 256 * NNODE, 0);
    // output head
    k_transpose_skip<<<dim3(16, 8, BB), dim3(32, 32)>>>(pSkip, skp_b, pSrelu);
    tgemm<<<dim3(4, 125), 256, TG_SMEM>>>(pSrelu, pO1T, pY, BB * NNODE, NENDC, NSKIPC,
                                          NSKIPC, NENDC, NENDC, 0, 0, 0, 0);
    k_headfinal<<<(BB * NNODE + 3) / 4, 128>>>(pY, o1b, o2w, o2b, out);
}